// round 13
// baseline (speedup 1.0000x reference)
#include <cuda_runtime.h>
#include <cuda_bf16.h>
#include <cuda_fp16.h>
#include <math.h>
#include <stdint.h>

#define B_   8
#define N_   1024
#define C_   768
#define H_   12
#define HD_  64
#define BH_  (B_*H_)
#define TWO_C_ (2*C_)
#define M_ROWS (B_*N_)

static const size_t KV_ELEMS   = (size_t)BH_ * N_ * HD_;
static const size_t OUT_ELEMS  = (size_t)B_ * N_ * C_;
static const size_t ATTN_ELEMS = (size_t)BH_ * N_ * N_;

#define LAMBD_ 4.0f
// logits carried in log2 domain: S2 = (k2*QSC)·(k2*QSC)^T where QSC^2 = 0.125*log2(e)
#define QSC_ 0.42466089f

// ---------------- device scratch ----------------
__device__ float g_k [6291456];
__device__ float g_y [6291456];
__device__ float g_s [6291456];
__device__ __nv_bfloat16 g_k2h_a[6291456];
__device__ __nv_bfloat16 g_k2l_a[6291456];
__device__ __nv_bfloat16 g_k2h_b[6291456];
__device__ __nv_bfloat16 g_k2l_b[6291456];
__device__ __half g_vh [6291456];
__device__ __half g_vl [6291456];
__device__ __nv_bfloat16 g_xh [6291456];
__device__ __nv_bfloat16 g_xl [6291456];
__device__ __nv_bfloat16 g_wqh[1179648];
__device__ __nv_bfloat16 g_wql[1179648];
__device__ __nv_bfloat16 g_wph[589824];
__device__ __nv_bfloat16 g_wpl[589824];
__device__ __nv_bfloat16 g_och[6291456];
__device__ __nv_bfloat16 g_ocl[6291456];
__device__ float g_mu[96];
__device__ float g_mu_part[768];
__device__ float g_attn_fallback[100663296];

// ---------------- helpers ----------------
__device__ __forceinline__ uint32_t smem_u32(const void* p) {
    uint32_t a;
    asm("{ .reg .u64 t; cvta.to.shared.u64 t, %1; cvt.u32.u64 %0, t; }" : "=r"(a) : "l"(p));
    return a;
}
__device__ __forceinline__ void ldsm4(uint32_t r[4], uint32_t addr) {
    asm volatile("ldmatrix.sync.aligned.m8n8.x4.shared.b16 {%0,%1,%2,%3}, [%4];"
        : "=r"(r[0]), "=r"(r[1]), "=r"(r[2]), "=r"(r[3]) : "r"(addr));
}
__device__ __forceinline__ void ldsm4t(uint32_t r[4], uint32_t addr) {
    asm volatile("ldmatrix.sync.aligned.m8n8.x4.trans.shared.b16 {%0,%1,%2,%3}, [%4];"
        : "=r"(r[0]), "=r"(r[1]), "=r"(r[2]), "=r"(r[3]) : "r"(addr));
}
__device__ __forceinline__ void mma_bf16(float c[4], const uint32_t a[4], const uint32_t* b) {
    asm volatile("mma.sync.aligned.m16n8k16.row.col.f32.bf16.bf16.f32 "
        "{%0,%1,%2,%3}, {%4,%5,%6,%7}, {%8,%9}, {%0,%1,%2,%3};"
        : "+f"(c[0]), "+f"(c[1]), "+f"(c[2]), "+f"(c[3])
        : "r"(a[0]), "r"(a[1]), "r"(a[2]), "r"(a[3]), "r"(b[0]), "r"(b[1]));
}
__device__ __forceinline__ void mma_f16(float c[4], const uint32_t a[4], const uint32_t* b) {
    asm volatile("mma.sync.aligned.m16n8k16.row.col.f32.f16.f16.f32 "
        "{%0,%1,%2,%3}, {%4,%5,%6,%7}, {%8,%9}, {%0,%1,%2,%3};"
        : "+f"(c[0]), "+f"(c[1]), "+f"(c[2]), "+f"(c[3])
        : "r"(a[0]), "r"(a[1]), "r"(a[2]), "r"(a[3]), "r"(b[0]), "r"(b[1]));
}
__device__ __forceinline__ void split2(float x, float y, uint32_t& hi, uint32_t& lo) {
    __nv_bfloat16 hx = __float2bfloat16(x), hy = __float2bfloat16(y);
    __nv_bfloat162 h2; h2.x = hx; h2.y = hy;
    __nv_bfloat162 l2;
    l2.x = __float2bfloat16(x - __bfloat162float(hx));
    l2.y = __float2bfloat16(y - __bfloat162float(hy));
    hi = *reinterpret_cast<uint32_t*>(&h2);
    lo = *reinterpret_cast<uint32_t*>(&l2);
}
__device__ __forceinline__ void split2h(float x, float y, uint32_t& hi, uint32_t& lo) {
    __half2 h = __floats2half2_rn(x, y);
    __half2 l = __floats2half2_rn(x - __half2float(h.x), y - __half2float(h.y));
    hi = *reinterpret_cast<uint32_t*>(&h);
    lo = *reinterpret_cast<uint32_t*>(&l);
}
__device__ __forceinline__ uint32_t pack_h2(float x, float y) {
    __half2 h = __floats2half2_rn(x, y);
    return *reinterpret_cast<uint32_t*>(&h);
}
__device__ __forceinline__ float ex2f(float x) {
    float y; asm("ex2.approx.f32 %0, %1;" : "=f"(y) : "f"(x)); return y;
}
__device__ __forceinline__ void cp16(uint32_t dst, const void* src) {
    asm volatile("cp.async.cg.shared.global [%0], [%1], 16;" :: "r"(dst), "l"(src));
}
#define CP_COMMIT() asm volatile("cp.async.commit_group;" ::: "memory")
#define CP_WAIT0()  asm volatile("cp.async.wait_group 0;" ::: "memory")

// ---------------- elementwise ----------------
__global__ void split_kernel(const float* __restrict__ src, __nv_bfloat16* __restrict__ h,
                             __nv_bfloat16* __restrict__ l, int n2) {
    int i = blockIdx.x * 256 + threadIdx.x;
    if (i >= n2) return;
    float2 v = ((const float2*)src)[i];
    uint32_t hh, ll;
    split2(v.x, v.y, hh, ll);
    ((uint32_t*)h)[i] = hh;
    ((uint32_t*)l)[i] = ll;
}

__global__ void k2_init_kernel() {
    size_t i2 = (size_t)blockIdx.x * 256 + threadIdx.x;
    if (i2 >= KV_ELEMS / 2) return;
    size_t i = i2 * 2;
    int bh = (int)(i / ((size_t)N_ * HD_));
    float mu = g_mu[bh];
    float lm = LAMBD_ * mu;
    float2 kk = *(const float2*)&g_k[i];
    float s0 = (kk.x >= lm) ? (kk.x - lm) : ((kk.x <= -lm) ? (kk.x + lm) : 0.f);
    float s1 = (kk.y >= lm) ? (kk.y - lm) : ((kk.y <= -lm) ? (kk.y + lm) : 0.f);
    *(float2*)&g_s[i] = make_float2(s0, s1);
    *(float2*)&g_y[i] = make_float2(0.f, 0.f);
    uint32_t hh, ll;
    split2((kk.x - s0) * QSC_, (kk.y - s1) * QSC_, hh, ll);
    *(uint32_t*)&g_k2h_a[i] = hh;
    *(uint32_t*)&g_k2l_a[i] = ll;
}

__global__ void mu_part_kernel() {
    __shared__ float red[256];
    int bh = blockIdx.x >> 3;
    int sl = blockIdx.x & 7;
    const float* p = g_k + (size_t)bh * N_ * HD_ + sl * 8192;
    float s = 0.f;
    #pragma unroll
    for (int i = 0; i < 32; i++) s += fabsf(p[threadIdx.x + i * 256]);
    red[threadIdx.x] = s;
    __syncthreads();
    for (int st = 128; st > 0; st >>= 1) {
        if (threadIdx.x < st) red[threadIdx.x] += red[threadIdx.x + st];
        __syncthreads();
    }
    if (threadIdx.x == 0) g_mu_part[blockIdx.x] = red[0];
}
__global__ void mu_fin_kernel() {
    int bh = threadIdx.x;
    if (bh >= BH_) return;
    float s = 0.f;
    #pragma unroll
    for (int i = 0; i < 8; i++) s += g_mu_part[bh * 8 + i];
    g_mu[bh] = ((float)N_ * (float)C_ / 4.0f) / s;
}

// =================== flash iteration (iters 0..4), M=256 rows, 512 threads ===================
// A tiles: 2 x 256 x 72; stage {Bh,Bl,Vh} x 64 x 72; 2 stages. smem 129,024 B -> occ 1, 16 warps.
#define FSPAD 72
#define FA_H  0
#define FA_L  18432
#define FSTG0 36864
#define FSTGS_I 13824
#define FSTGS_F 18432
#define FS_BH 0
#define FS_BL 4608
#define FS_VH 9216
#define FS_VL 13824
#define FA_BL 9216       // final pass A (128-row B tiles): Bl offset within stage

__global__ void __launch_bounds__(512, 1) flash_iter_kernel(
    const __nv_bfloat16* __restrict__ k2h_src, const __nv_bfloat16* __restrict__ k2l_src,
    __nv_bfloat16* __restrict__ k2h_dst, __nv_bfloat16* __restrict__ k2l_dst)
{
    extern __shared__ __nv_bfloat16 fsm[];
    const int bh = blockIdx.y;
    const int i0 = blockIdx.x * 256;
    const int tid = threadIdx.x, wid = tid >> 5, lane = tid & 31;

    const size_t hbase = (size_t)bh * N_ * HD_;
    const __nv_bfloat16* Gh = k2h_src + hbase;
    const __nv_bfloat16* Gl = k2l_src + hbase;
    const __half* Vh = g_vh + hbase;
    const float mu = g_mu[bh];

    // A tiles: 2 arrays x 256 rows x 8 chunks = 4096 / 512
    #pragma unroll
    for (int i = 0; i < 8; i++) {
        int idx = tid + i * 512;
        int arr = idx >> 11, rem = idx & 2047, row = rem >> 3, c = rem & 7;
        const __nv_bfloat16* src = (arr ? Gl : Gh) + (size_t)(i0 + row) * HD_ + c * 8;
        *(uint4*)(fsm + (arr ? FA_L : FA_H) + row * FSPAD + c * 8) = *(const uint4*)src;
    }

    auto cp_tile = [&](int stage, int j) {
        int sbase = FSTG0 + stage * FSTGS_I;
        #pragma unroll
        for (int i = 0; i < 3; i++) {
            int idx = tid + i * 512;           // 0..1535: 3 arrays x 64 rows x 8 chunks
            int arr = idx >> 9, rem = idx & 511, row = rem >> 3, c = rem & 7;
            const void* src;
            int off;
            if      (arr == 0) { src = Gh + (size_t)(j * 64 + row) * HD_ + c * 8; off = FS_BH; }
            else if (arr == 1) { src = Gl + (size_t)(j * 64 + row) * HD_ + c * 8; off = FS_BL; }
            else               { src = Vh + (size_t)(j * 64 + row) * HD_ + c * 8; off = FS_VH; }
            cp16(smem_u32(fsm + sbase + off + row * FSPAD + c * 8), src);
        }
    };

    cp_tile(0, 0);
    CP_COMMIT(); CP_WAIT0();
    __syncthreads();

    float m0 = -1e30f, m1 = -1e30f, l0 = 0.f, l1 = 0.f;
    float acco[8][4] = {};

    for (int j = 0; j < 16; j++) {
        if (j < 15) { cp_tile((j + 1) & 1, j + 1); CP_COMMIT(); }
        const __nv_bfloat16* sb = fsm + FSTG0 + (j & 1) * FSTGS_I;

        float accs[8][4] = {};
        #pragma unroll
        for (int ks = 0; ks < 4; ks++) {
            uint32_t aH[4], aL[4];
            {
                int ar = wid * 16 + (lane & 15);
                int ac = ks * 16 + ((lane >> 4) << 3);
                ldsm4(aH, smem_u32(fsm + FA_H + ar * FSPAD + ac));
                ldsm4(aL, smem_u32(fsm + FA_L + ar * FSPAD + ac));
            }
            #pragma unroll
            for (int ng = 0; ng < 2; ng++) {
                uint32_t bh2[2][4], bl2[2][4];
                #pragma unroll
                for (int p = 0; p < 2; p++) {
                    int nr = ng * 32 + p * 16 + (lane & 7) + ((lane >> 4) << 3);
                    int kc = ks * 16 + (((lane >> 3) & 1) << 3);
                    ldsm4(bh2[p], smem_u32(sb + FS_BH + nr * FSPAD + kc));
                    ldsm4(bl2[p], smem_u32(sb + FS_BL + nr * FSPAD + kc));
                }
                #pragma unroll
                for (int t = 0; t < 4; t++) {
                    float* c = accs[ng * 4 + t];
                    const uint32_t* bhf = &bh2[t >> 1][(t & 1) * 2];
                    const uint32_t* blf = &bl2[t >> 1][(t & 1) * 2];
                    mma_bf16(c, aH, bhf);
                    mma_bf16(c, aH, blf);
                    mma_bf16(c, aL, bhf);
                }
            }
        }

        float tm0 = -1e30f, tm1 = -1e30f;
        #pragma unroll
        for (int t = 0; t < 8; t++) {
            tm0 = fmaxf(tm0, fmaxf(accs[t][0], accs[t][1]));
            tm1 = fmaxf(tm1, fmaxf(accs[t][2], accs[t][3]));
        }
        tm0 = fmaxf(tm0, __shfl_xor_sync(0xFFFFFFFF, tm0, 1));
        tm0 = fmaxf(tm0, __shfl_xor_sync(0xFFFFFFFF, tm0, 2));
        tm1 = fmaxf(tm1, __shfl_xor_sync(0xFFFFFFFF, tm1, 1));
        tm1 = fmaxf(tm1, __shfl_xor_sync(0xFFFFFFFF, tm1, 2));
        float mn0 = fmaxf(m0, tm0), mn1 = fmaxf(m1, tm1);
        float sc0 = ex2f(m0 - mn0), sc1 = ex2f(m1 - mn1);
        m0 = mn0; m1 = mn1;
        float rs0 = 0.f, rs1 = 0.f;
        #pragma unroll
        for (int t = 0; t < 8; t++) {
            accs[t][0] = ex2f(accs[t][0] - m0);
            accs[t][1] = ex2f(accs[t][1] - m0);
            accs[t][2] = ex2f(accs[t][2] - m1);
            accs[t][3] = ex2f(accs[t][3] - m1);
            rs0 += accs[t][0] + accs[t][1];
            rs1 += accs[t][2] + accs[t][3];
        }
        rs0 += __shfl_xor_sync(0xFFFFFFFF, rs0, 1);
        rs0 += __shfl_xor_sync(0xFFFFFFFF, rs0, 2);
        rs1 += __shfl_xor_sync(0xFFFFFFFF, rs1, 1);
        rs1 += __shfl_xor_sync(0xFFFFFFFF, rs1, 2);
        l0 = l0 * sc0 + rs0;
        l1 = l1 * sc1 + rs1;
        #pragma unroll
        for (int o = 0; o < 8; o++) {
            acco[o][0] *= sc0; acco[o][1] *= sc0;
            acco[o][2] *= sc1; acco[o][3] *= sc1;
        }

        #pragma unroll
        for (int kt = 0; kt < 4; kt++) {
            uint32_t pH[4];
            pH[0] = pack_h2(accs[2*kt][0],   accs[2*kt][1]);
            pH[1] = pack_h2(accs[2*kt][2],   accs[2*kt][3]);
            pH[2] = pack_h2(accs[2*kt+1][0], accs[2*kt+1][1]);
            pH[3] = pack_h2(accs[2*kt+1][2], accs[2*kt+1][3]);
            #pragma unroll
            for (int vg = 0; vg < 2; vg++) {
                uint32_t vh2[2][4];
                #pragma unroll
                for (int q = 0; q < 2; q++) {
                    int vr = kt * 16 + (lane & 15);
                    int vc = vg * 32 + q * 16 + ((lane >> 4) << 3);
                    ldsm4t(vh2[q], smem_u32(sb + FS_VH + vr * FSPAD + vc));
                }
                #pragma unroll
                for (int t = 0; t < 4; t++)
                    mma_f16(acco[vg * 4 + t], pH, &vh2[t >> 1][(t & 1) * 2]);
            }
        }

        if (j < 15) CP_WAIT0();
        __syncthreads();
    }

    float inv0 = 1.f / l0, inv1 = 1.f / l1;
    float imu = 1.f / mu;
    float lm = LAMBD_ * mu;
    int row0 = i0 + wid * 16 + (lane >> 2);
    #pragma unroll
    for (int o = 0; o < 8; o++) {
        int col = o * 8 + (lane & 3) * 2;
        #pragma unroll
        for (int half = 0; half < 2; half++) {
            size_t ia = hbase + (size_t)(row0 + half * 8) * HD_ + col;
            float la = acco[o][half * 2]     * (half ? inv1 : inv0);
            float lb = acco[o][half * 2 + 1] * (half ? inv1 : inv0);
            float2 kv = *(const float2*)&g_k[ia];
            float2 yv = *(const float2*)&g_y[ia];
            float2 sv = *(const float2*)&g_s[ia];
            float yn0 = yv.x + mu * (kv.x - la - sv.x);
            float yn1 = yv.y + mu * (kv.y - lb - sv.y);
            float ym0 = yn0 * imu, ym1 = yn1 * imu;
            float t0 = kv.x - la + ym0, t1 = kv.y - lb + ym1;
            float sn0 = (t0 >= lm) ? (t0 - lm) : ((t0 <= -lm) ? (t0 + lm) : 0.f);
            float sn1 = (t1 >= lm) ? (t1 - lm) : ((t1 <= -lm) ? (t1 + lm) : 0.f);
            *(float2*)&g_y[ia] = make_float2(yn0, yn1);
            *(float2*)&g_s[ia] = make_float2(sn0, sn1);
            float k20 = (kv.x - sn0 - ym0) * QSC_;
            float k21 = (kv.y - sn1 - ym1) * QSC_;
            uint32_t h2, l2;
            split2(k20, k21, h2, l2);
            *(uint32_t*)&k2h_dst[ia] = h2;
            *(uint32_t*)&k2l_dst[ia] = l2;
        }
    }
}

// =================== final iteration: 2-pass flash, M=256, 512 threads ===================
__global__ void __launch_bounds__(512, 1) final_flash_kernel(
    float* __restrict__ attn,
    const __nv_bfloat16* __restrict__ k2h_src, const __nv_bfloat16* __restrict__ k2l_src)
{
    extern __shared__ __nv_bfloat16 fsm[];
    const int bh = blockIdx.y;
    const int i0 = blockIdx.x * 256;
    const int tid = threadIdx.x, wid = tid >> 5, lane = tid & 31;

    const size_t hbase = (size_t)bh * N_ * HD_;
    const __nv_bfloat16* Gh = k2h_src + hbase;
    const __nv_bfloat16* Gl = k2l_src + hbase;
    const __half* Vh = g_vh + hbase;
    const __half* Vl = g_vl + hbase;

    #pragma unroll
    for (int i = 0; i < 8; i++) {
        int idx = tid + i * 512;
        int arr = idx >> 11, rem = idx & 2047, row = rem >> 3, c = rem & 7;
        const __nv_bfloat16* src = (arr ? Gl : Gh) + (size_t)(i0 + row) * HD_ + c * 8;
        *(uint4*)(fsm + (arr ? FA_L : FA_H) + row * FSPAD + c * 8) = *(const uint4*)src;
    }

    // pass A: 128-row tiles, {Bh, Bl}: 2 x 128 x 8 = 2048 / 512
    auto cp_tileA = [&](int stage, int j) {
        int sbase = FSTG0 + stage * FSTGS_F;
        #pragma unroll
        for (int i = 0; i < 4; i++) {
            int idx = tid + i * 512;
            int arr = idx >> 10, rem = idx & 1023, row = rem >> 3, c = rem & 7;
            const __nv_bfloat16* src = (arr ? Gl : Gh) + (size_t)(j * 128 + row) * HD_ + c * 8;
            cp16(smem_u32(fsm + sbase + (arr ? FA_BL : FS_BH) + row * FSPAD + c * 8), src);
        }
    };
    // pass B: 64-row tiles, {Bh, Bl, Vh, Vl}: 4 x 64 x 8 = 2048 / 512
    auto cp_tileB = [&](int stage, int j) {
        int sbase = FSTG0 + stage * FSTGS_F;
        #pragma unroll
        for (int i = 0; i < 4; i++) {
            int idx = tid + i * 512;
            int arr = idx >> 9, rem = idx & 511, row = rem >> 3, c = rem & 7;
            const void* src;
            int off;
            if      (arr == 0) { src = Gh + (size_t)(j * 64 + row) * HD_ + c * 8; off = FS_BH; }
            else if (arr == 1) { src = Gl + (size_t)(j * 64 + row) * HD_ + c * 8; off = FS_BL; }
            else if (arr == 2) { src = Vh + (size_t)(j * 64 + row) * HD_ + c * 8; off = FS_VH; }
            else               { src = Vl + (size_t)(j * 64 + row) * HD_ + c * 8; off = FS_VL; }
            cp16(smem_u32(fsm + sbase + off + row * FSPAD + c * 8), src);
        }
    };

    // ---------- PASS A ----------
    cp_tileA(0, 0);
    CP_COMMIT(); CP_WAIT0();
    __syncthreads();

    float m0 = -1e30f, m1 = -1e30f, l0 = 0.f, l1 = 0.f;
    for (int j = 0; j < 8; j++) {
        if (j < 7) { cp_tileA((j + 1) & 1, j + 1); CP_COMMIT(); }
        const __nv_bfloat16* sb = fsm + FSTG0 + (j & 1) * FSTGS_F;
        float accs[16][4] = {};
        #pragma unroll
        for (int ks = 0; ks < 4; ks++) {
            uint32_t aH[4], aL[4];
            {
                int ar = wid * 16 + (lane & 15);
                int ac = ks * 16 + ((lane >> 4) << 3);
                ldsm4(aH, smem_u32(fsm + FA_H + ar * FSPAD + ac));
                ldsm4(aL, smem_u32(fsm + FA_L + ar * FSPAD + ac));
            }
            #pragma unroll
            for (int ng = 0; ng < 4; ng++) {
                uint32_t bh2[2][4], bl2[2][4];
                #pragma unroll
                for (int p = 0; p < 2; p++) {
                    int nr = ng * 32 + p * 16 + (lane & 7) + ((lane >> 4) << 3);
                    int kc = ks * 16 + (((lane >> 3) & 1) << 3);
                    ldsm4(bh2[p], smem_u32(sb + FS_BH + nr * FSPAD + kc));
                    ldsm4(bl2[p], smem_u32(sb + FA_BL + nr * FSPAD + kc));
                }
                #pragma unroll
                for (int t = 0; t < 4; t++) {
                    float* c = accs[ng * 4 + t];
                    const uint32_t* bhf = &bh2[t >> 1][(t & 1) * 2];
                    const uint32_t* blf = &bl2[t >> 1][(t & 1) * 2];
                    mma_bf16(c, aH, bhf);
                    mma_bf16(c, aH, blf);
                    mma_bf16(c, aL, bhf);
                }
            }
        }

        float tm0 = -1e30f, tm1 = -1e30f;
        #pragma unroll
        for (int t = 0; t < 16; t++) {
            tm0 = fmaxf(tm0, fmaxf(accs[t][0], accs[t][1]));
            tm1 = fmaxf(tm1, fmaxf(accs[t][2], accs[t][3]));
        }
        tm0 = fmaxf(tm0, __shfl_xor_sync(0xFFFFFFFF, tm0, 1));
        tm0 = fmaxf(tm0, __shfl_xor_sync(0xFFFFFFFF, tm0, 2));
        tm1 = fmaxf(tm1, __shfl_xor_sync(0xFFFFFFFF, tm1, 1));
        tm1 = fmaxf(tm1, __shfl_xor_sync(0xFFFFFFFF, tm1, 2));
        float mn0 = fmaxf(m0, tm0), mn1 = fmaxf(m1, tm1);
        float sc0 = ex2f(m0 - mn0), sc1 = ex2f(m1 - mn1);
        m0 = mn0; m1 = mn1;
        float rs0 = 0.f, rs1 = 0.f;
        #pragma unroll
        for (int t = 0; t < 16; t++) {
            rs0 += ex2f(accs[t][0] - m0) + ex2f(accs[t][1] - m0);
            rs1 += ex2f(accs[t][2] - m1) + ex2f(accs[t][3] - m1);
        }
        rs0 += __shfl_xor_sync(0xFFFFFFFF, rs0, 1);
        rs0 += __shfl_xor_sync(0xFFFFFFFF, rs0, 2);
        rs1 += __shfl_xor_sync(0xFFFFFFFF, rs1, 1);
        rs1 += __shfl_xor_sync(0xFFFFFFFF, rs1, 2);
        l0 = l0 * sc0 + rs0;
        l1 = l1 * sc1 + rs1;
        if (j < 7) CP_WAIT0();
        __syncthreads();
    }
    float inv0 = 1.f / l0, inv1 = 1.f / l1;

    // ---------- PASS B ----------
    cp_tileB(0, 0);
    CP_COMMIT(); CP_WAIT0();
    __syncthreads();

    float* Sp = attn + (size_t)bh * N_ * N_;
    const int prow = i0 + wid * 16 + (lane >> 2);
    float acco[8][4] = {};

    for (int j = 0; j < 16; j++) {
        if (j < 15) { cp_tileB((j + 1) & 1, j + 1); CP_COMMIT(); }
        const __nv_bfloat16* sb = fsm + FSTG0 + (j & 1) * FSTGS_F;
        float accs[8][4] = {};
        #pragma unroll
        for (int ks = 0; ks < 4; ks++) {
            uint32_t aH[4], aL[4];
            {
                int ar = wid * 16 + (lane & 15);
                int ac = ks * 16 + ((lane >> 4) << 3);
                ldsm4(aH, smem_u32(fsm + FA_H + ar * FSPAD + ac));
                ldsm4(aL, smem_u32(fsm + FA_L + ar * FSPAD + ac));
            }
            #pragma unroll
            for (int ng = 0; ng < 2; ng++) {
                uint32_t bh2[2][4], bl2[2][4];
                #pragma unroll
                for (int p = 0; p < 2; p++) {
                    int nr = ng * 32 + p * 16 + (lane & 7) + ((lane >> 4) << 3);
                    int kc = ks * 16 + (((lane >> 3) & 1) << 3);
                    ldsm4(bh2[p], smem_u32(sb + FS_BH + nr * FSPAD + kc));
                    ldsm4(bl2[p], smem_u32(sb + FS_BL + nr * FSPAD + kc));
                }
                #pragma unroll
                for (int t = 0; t < 4; t++) {
                    float* c = accs[ng * 4 + t];
                    const uint32_t* bhf = &bh2[t >> 1][(t & 1) * 2];
                    const uint32_t* blf = &bl2[t >> 1][(t & 1) * 2];
                    mma_bf16(c, aH, bhf);
                    mma_bf16(c, aH, blf);
                    mma_bf16(c, aL, bhf);
                }
            }
        }

        #pragma unroll
        for (int t = 0; t < 8; t++) {
            accs[t][0] = ex2f(accs[t][0] - m0) * inv0;
            accs[t][1] = ex2f(accs[t][1] - m0) * inv0;
            accs[t][2] = ex2f(accs[t][2] - m1) * inv1;
            accs[t][3] = ex2f(accs[t][3] - m1) * inv1;
            int col = j * 64 + (t >> 2) * 32 + (t & 3) * 8 + (lane & 3) * 2;
            *(float2*)&Sp[(size_t)prow * N_ + col]       = make_float2(accs[t][0], accs[t][1]);
            *(float2*)&Sp[(size_t)(prow + 8) * N_ + col] = make_float2(accs[t][2], accs[t][3]);
        }

        #pragma unroll
        for (int kt = 0; kt < 4; kt++) {
            uint32_t pH[4];
            pH[0] = pack_h2(accs[2*kt][0],   accs[2*kt][1]);
            pH[1] = pack_h2(accs[2*kt][2],   accs[2*kt][3]);
            pH[2] = pack_h2(accs[2*kt+1][0], accs[2*kt+1][1]);
            pH[3] = pack_h2(accs[2*kt+1][2], accs[2*kt+1][3]);
            #pragma unroll
            for (int vg = 0; vg < 2; vg++) {
                uint32_t vh2[2][4], vl2[2][4];
                #pragma unroll
                for (int q = 0; q < 2; q++) {
                    int vr = kt * 16 + (lane & 15);
                    int vc = vg * 32 + q * 16 + ((lane >> 4) << 3);
                    ldsm4t(vh2[q], smem_u32(sb + FS_VH + vr * FSPAD + vc));
                    ldsm4t(vl2[q], smem_u32(sb + FS_VL + vr * FSPAD + vc));
                }
                #pragma unroll
                for (int t = 0; t < 4; t++) {
                    float* o = acco[vg * 4 + t];
                    mma_f16(o, pH, &vh2[t >> 1][(t & 1) * 2]);
                    mma_f16(o, pH, &vl2[t >> 1][(t & 1) * 2]);
                }
            }
        }

        if (j < 15) CP_WAIT0();
        __syncthreads();
    }

    int b = bh / H_, h = bh % H_;
    #pragma unroll
    for (int o = 0; o < 8; o++) {
        int col = o * 8 + (lane & 3) * 2;
        uint32_t h0, l0b, h1, l1b;
        split2(acco[o][0], acco[o][1], h0, l0b);
        split2(acco[o][2], acco[o][3], h1, l1b);
        size_t idx0 = ((size_t)(b * N_ + prow)) * C_ + h * HD_ + col;
        size_t idx1 = ((size_t)(b * N_ + prow + 8)) * C_ + h * HD_ + col;
        *(uint32_t*)&g_och[idx0] = h0;
        *(uint32_t*)&g_ocl[idx0] = l0b;
        *(uint32_t*)&g_och[idx1] = h1;
        *(uint32_t*)&g_ocl[idx1] = l1b;
    }
}

// =================== bf16x3 HMMA GEMM: qkv and proj ===================
#define QA_H 0
#define QA_L 9216
#define QB_H 18432
#define QB_L 23040
#define QSTG 27648
#define WPAD 72

template<int NCOLS, int KDIM>
__device__ __forceinline__ void mma_gemm_main(
    const __nv_bfloat16* __restrict__ Ah, const __nv_bfloat16* __restrict__ Al,
    const __nv_bfloat16* __restrict__ Wh, const __nv_bfloat16* __restrict__ Wl,
    __nv_bfloat16* sm, int by, int bx, float acc[2][4][4])
{
    const int tid = threadIdx.x, wid = tid >> 5, lane = tid & 31;
    const int wm = wid & 3, wn = wid >> 2;

    auto cp_stage = [&](int stage, int k0) {
        int sb = stage * QSTG;
        #pragma unroll
        for (int i = 0; i < 8; i++) {
            int idx = tid + i * 256;
            int arr = idx >> 10, rem = idx & 1023, row = rem >> 3, c = rem & 7;
            const __nv_bfloat16* src = (arr ? Al : Ah) + (size_t)(by + row) * KDIM + k0 + c * 8;
            cp16(smem_u32(sm + sb + (arr ? QA_L : QA_H) + row * FSPAD + c * 8), src);
        }
        #pragma unroll
        for (int i = 0; i < 4; i++) {
            int idx = tid + i * 256;
            int arr = idx >> 9, rem = idx & 511, row = rem >> 3, c = rem & 7;
            const __nv_bfloat16* src = (arr ? Wl : Wh) + (size_t)(k0 + row) * NCOLS + bx + c * 8;
            cp16(smem_u32(sm + sb + (arr ? QB_L : QB_H) + row * WPAD + c * 8), src);
        }
    };

    cp_stage(0, 0);
    CP_COMMIT(); CP_WAIT0();
    __syncthreads();

    const int NCHUNK = KDIM / 64;
    for (int ch = 0; ch < NCHUNK; ch++) {
        if (ch < NCHUNK - 1) { cp_stage((ch + 1) & 1, (ch + 1) * 64); CP_COMMIT(); }
        __nv_bfloat16* sb = sm + (ch & 1) * QSTG;
        #pragma unroll
        for (int ks = 0; ks < 4; ks++) {
            uint32_t aH[2][4], aL[2][4];
            #pragma unroll
            for (int mt = 0; mt < 2; mt++) {
                int ar = wm * 32 + mt * 16 + (lane & 15);
                int ac = ks * 16 + ((lane >> 4) << 3);
                ldsm4(aH[mt], smem_u32(sb + QA_H + ar * FSPAD + ac));
                ldsm4(aL[mt], smem_u32(sb + QA_L + ar * FSPAD + ac));
            }
            uint32_t bh2[2][4], bl2[2][4];
            #pragma unroll
            for (int q = 0; q < 2; q++) {
                int vr = ks * 16 + (lane & 15);
                int vc = wn * 32 + q * 16 + ((lane >> 4) << 3);
                ldsm4t(bh2[q], smem_u32(sb + QB_H + vr * WPAD + vc));
                ldsm4t(bl2[q], smem_u32(sb + QB_L + vr * WPAD + vc));
            }
            #pragma unroll
            for (int mt = 0; mt < 2; mt++)
                #pragma unroll
                for (int nt = 0; nt < 4; nt++) {
                    const uint32_t* bhf = &bh2[nt >> 1][(nt & 1) * 2];
                    const uint32_t* blf = &bl2[nt >> 1][(nt & 1) * 2];
                    mma_bf16(acc[mt][nt], aH[mt], bhf);
                    mma_bf16(acc[mt][nt], aH[mt], blf);
                    mma_bf16(acc[mt][nt], aL[mt], bhf);
                }
        }
        if (ch < NCHUNK - 1) CP_WAIT0();
        __syncthreads();
    }
}

__global__ void __launch_bounds__(256, 2) qkv_mma_kernel(const float* __restrict__ bias) {
    extern __shared__ __nv_bfloat16 qsm[];
    const int bx = blockIdx.x * 64;
    const int by = blockIdx.y * 128;
    const int wid = threadIdx.x >> 5, lane = threadIdx.x & 31;
    const int wm = wid & 3, wn = wid >> 2;

    float acc[2][4][4] = {};
    mma_gemm_main<TWO_C_, C_>(g_xh, g_xl, g_wqh, g_wql, qsm, by, bx, acc);

    #pragma unroll
    for (int mt = 0; mt < 2; mt++) {
        int r0 = by + wm * 32 + mt * 16 + (lane >> 2);
        #pragma unroll
        for (int nt = 0; nt < 4; nt++) {
            int col = bx + wn * 32 + nt * 8 + (lane & 3) * 2;
            float b0 = bias[col], b1 = bias[col + 1];
            #pragma unroll
            for (int half = 0; half < 2; half++) {
                int r = r0 + half * 8;
                float v0 = acc[mt][nt][half * 2]     + b0;
                float v1 = acc[mt][nt][half * 2 + 1] + b1;
                int bb = r >> 10, n = r & 1023;
                int which = col >= C_;
                int cc = col - which * C_;
                int hh = cc / HD_, hd = cc % HD_;
                size_t idx = (((size_t)(bb * H_ + hh)) * N_ + n) * HD_ + hd;
                if (!which) {
                    *(float2*)&g_k[idx] = make_float2(v0, v1);
                } else {
                    uint32_t h2, l2;
                    split2h(v0, v1, h2, l2);
                    *(uint32_t*)&g_vh[idx] = h2;
                    *(uint32_t*)&g_vl[idx] = l2;
                }
            }
        }
    }
}

__global__ void __launch_bounds__(256, 2) proj_mma_kernel(const float* __restrict__ bias,
                                                          float* __restrict__ out) {
    extern __shared__ __nv_bfloat16 qsm[];
    const int bx = blockIdx.x * 64;
    const int by = blockIdx.y * 128;
    const int wid = threadIdx.x >> 5, lane = threadIdx.x & 31;
    const int wm = wid & 3, wn = wid >> 2;

    float acc[2][4][4] = {};
    mma_gemm_main<C_, C_>(g_och, g_ocl, g_wph, g_wpl, qsm, by, bx, acc);

    #pragma unroll
    for (int mt = 0; mt < 2; mt++) {
        int r0 = by + wm * 32 + mt * 16 + (lane >> 2);
        #pragma unroll
        for (int nt = 0; nt < 4; nt++) {
            int col = bx + wn * 32 + nt * 8 + (lane & 3) * 2;
            float b0 = bias[col], b1 = bias[col + 1];
            *(float2*)&out[(size_t)r0 * C_ + col] =
                make_float2(acc[mt][nt][0] + b0, acc[mt][nt][1] + b1);
            *(float2*)&out[(size_t)(r0 + 8) * C_ + col] =
                make_float2(acc[mt][nt][2] + b0, acc[mt][nt][3] + b1);
        }
    }
}

// ---------------- launch ----------------
extern "C" void kernel_launch(void* const* d_in, const int* in_sizes, int n_in,
                              void* d_out, int out_size) {
    const float* x     = (const float*)d_in[0];
    const float* Wqkv  = (const float*)d_in[1];
    const float* bqkv  = (const float*)d_in[2];
    const float* Wproj = (const float*)d_in[3];
    const float* bproj = (const float*)d_in[4];
    float* out = (float*)d_out;

    float* attn;
    if ((size_t)out_size >= OUT_ELEMS + ATTN_ELEMS) {
        attn = out + OUT_ELEMS;
    } else {
        void* p = nullptr;
        cudaGetSymbolAddress(&p, g_attn_fallback);
        attn = (float*)p;
    }

    const int FLASH_SMEM_I = (FSTG0 + 2 * FSTGS_I) * 2;   // 129,024 B
    const int FLASH_SMEM_F = (FSTG0 + 2 * FSTGS_F) * 2;   // 147,456 B
    const int GEMM_SMEM    = 2 * QSTG * 2;                // 110,592 B
    cudaFuncSetAttribute(flash_iter_kernel, cudaFuncAttributeMaxDynamicSharedMemorySize, FLASH_SMEM_I);
    cudaFuncSetAttribute(final_flash_kernel, cudaFuncAttributeMaxDynamicSharedMemorySize, FLASH_SMEM_F);
    cudaFuncSetAttribute(qkv_mma_kernel, cudaFuncAttributeMaxDynamicSharedMemorySize, GEMM_SMEM);
    cudaFuncSetAttribute(proj_mma_kernel, cudaFuncAttributeMaxDynamicSharedMemorySize, GEMM_SMEM);

    __nv_bfloat16 *xh, *xl, *wqh, *wql, *wph, *wpl;
    __nv_bfloat16 *k2h_a, *k2l_a, *k2h_b, *k2l_b;
    { void* p; cudaGetSymbolAddress(&p, g_xh);  xh  = (__nv_bfloat16*)p; }
    { void* p; cudaGetSymbolAddress(&p, g_xl);  xl  = (__nv_bfloat16*)p; }
    { void* p; cudaGetSymbolAddress(&p, g_wqh); wqh = (__nv_bfloat16*)p; }
    { void* p; cudaGetSymbolAddress(&p, g_wql); wql = (__nv_bfloat16*)p; }
    { void* p; cudaGetSymbolAddress(&p, g_wph); wph = (__nv_bfloat16*)p; }
    { void* p; cudaGetSymbolAddress(&p, g_wpl); wpl = (__nv_bfloat16*)p; }
    { void* p; cudaGetSymbolAddress(&p, g_k2h_a); k2h_a = (__nv_bfloat16*)p; }
    { void* p; cudaGetSymbolAddress(&p, g_k2l_a); k2l_a = (__nv_bfloat16*)p; }
    { void* p; cudaGetSymbolAddress(&p, g_k2h_b); k2h_b = (__nv_bfloat16*)p; }
    { void* p; cudaGetSymbolAddress(&p, g_k2l_b); k2l_b = (__nv_bfloat16*)p; }

    split_kernel<<<(3145728 + 255) / 256, 256>>>(x, xh, xl, 3145728);
    split_kernel<<<(589824 + 255) / 256, 256>>>(Wqkv, wqh, wql, 589824);
    split_kernel<<<(294912 + 255) / 256, 256>>>(Wproj, wph, wpl, 294912);

    qkv_mma_kernel<<<dim3(TWO_C_ / 64, M_ROWS / 128), 256, GEMM_SMEM>>>(bqkv);
    mu_part_kernel<<<BH_ * 8, 256>>>();
    mu_fin_kernel<<<1, 128>>>();
    k2_init_kernel<<<(int)((KV_ELEMS / 2 + 255) / 256), 256>>>();

    __nv_bfloat16* bufs_h[2] = {k2h_a, k2h_b};
    __nv_bfloat16* bufs_l[2] = {k2l_a, k2l_b};
    for (int it = 0; it < 5; ++it) {
        int s = it & 1, d = (it + 1) & 1;
        flash_iter_kernel<<<dim3(N_ / 256, BH_), 512, FLASH_SMEM_I>>>(
            bufs_h[s], bufs_l[s], bufs_h[d], bufs_l[d]);
    }
    final_flash_kernel<<<dim3(N_ / 256, BH_), 512, FLASH_SMEM_F>>>(attn, bufs_h[1], bufs_l[1]);

    proj_mma_kernel<<<dim3(C_ / 64, M_ROWS / 128), 256, GEMM_SMEM>>>(bproj, out);
}

// round 14
// speedup vs baseline: 1.0165x; 1.0165x over previous
#include <cuda_runtime.h>
#include <cuda_bf16.h>
#include <cuda_fp16.h>
#include <math.h>
#include <stdint.h>

#define B_   8
#define N_   1024
#define C_   768
#define H_   12
#define HD_  64
#define BH_  (B_*H_)
#define TWO_C_ (2*C_)
#define M_ROWS (B_*N_)

static const size_t KV_ELEMS   = (size_t)BH_ * N_ * HD_;
static const size_t OUT_ELEMS  = (size_t)B_ * N_ * C_;
static const size_t ATTN_ELEMS = (size_t)BH_ * N_ * N_;

#define LAMBD_ 4.0f
// logits carried in log2 domain: S2 = (k2*QSC)·(k2*QSC)^T where QSC^2 = 0.125*log2(e)
#define QSC_ 0.42466089f

// ---------------- device scratch ----------------
__device__ float g_k [6291456];
__device__ float g_y [6291456];
__device__ float g_s [6291456];
__device__ __nv_bfloat16 g_k2h_a[6291456];
__device__ __nv_bfloat16 g_k2l_a[6291456];
__device__ __nv_bfloat16 g_k2h_b[6291456];
__device__ __nv_bfloat16 g_k2l_b[6291456];
__device__ __half g_vh [6291456];
__device__ __half g_vl [6291456];
__device__ __nv_bfloat16 g_xh [6291456];
__device__ __nv_bfloat16 g_xl [6291456];
__device__ __nv_bfloat16 g_wqh[1179648];
__device__ __nv_bfloat16 g_wql[1179648];
__device__ __nv_bfloat16 g_wph[589824];
__device__ __nv_bfloat16 g_wpl[589824];
__device__ __nv_bfloat16 g_och[6291456];
__device__ __nv_bfloat16 g_ocl[6291456];
__device__ float g_mu[96];
__device__ float g_mu_part[768];
__device__ float g_attn_fallback[100663296];

// ---------------- helpers ----------------
__device__ __forceinline__ uint32_t smem_u32(const void* p) {
    uint32_t a;
    asm("{ .reg .u64 t; cvta.to.shared.u64 t, %1; cvt.u32.u64 %0, t; }" : "=r"(a) : "l"(p));
    return a;
}
__device__ __forceinline__ void ldsm4(uint32_t r[4], uint32_t addr) {
    asm volatile("ldmatrix.sync.aligned.m8n8.x4.shared.b16 {%0,%1,%2,%3}, [%4];"
        : "=r"(r[0]), "=r"(r[1]), "=r"(r[2]), "=r"(r[3]) : "r"(addr));
}
__device__ __forceinline__ void ldsm4t(uint32_t r[4], uint32_t addr) {
    asm volatile("ldmatrix.sync.aligned.m8n8.x4.trans.shared.b16 {%0,%1,%2,%3}, [%4];"
        : "=r"(r[0]), "=r"(r[1]), "=r"(r[2]), "=r"(r[3]) : "r"(addr));
}
__device__ __forceinline__ void mma_bf16(float c[4], const uint32_t a[4], const uint32_t* b) {
    asm volatile("mma.sync.aligned.m16n8k16.row.col.f32.bf16.bf16.f32 "
        "{%0,%1,%2,%3}, {%4,%5,%6,%7}, {%8,%9}, {%0,%1,%2,%3};"
        : "+f"(c[0]), "+f"(c[1]), "+f"(c[2]), "+f"(c[3])
        : "r"(a[0]), "r"(a[1]), "r"(a[2]), "r"(a[3]), "r"(b[0]), "r"(b[1]));
}
__device__ __forceinline__ void mma_f16(float c[4], const uint32_t a[4], const uint32_t* b) {
    asm volatile("mma.sync.aligned.m16n8k16.row.col.f32.f16.f16.f32 "
        "{%0,%1,%2,%3}, {%4,%5,%6,%7}, {%8,%9}, {%0,%1,%2,%3};"
        : "+f"(c[0]), "+f"(c[1]), "+f"(c[2]), "+f"(c[3])
        : "r"(a[0]), "r"(a[1]), "r"(a[2]), "r"(a[3]), "r"(b[0]), "r"(b[1]));
}
__device__ __forceinline__ void split2(float x, float y, uint32_t& hi, uint32_t& lo) {
    __nv_bfloat16 hx = __float2bfloat16(x), hy = __float2bfloat16(y);
    __nv_bfloat162 h2; h2.x = hx; h2.y = hy;
    __nv_bfloat162 l2;
    l2.x = __float2bfloat16(x - __bfloat162float(hx));
    l2.y = __float2bfloat16(y - __bfloat162float(hy));
    hi = *reinterpret_cast<uint32_t*>(&h2);
    lo = *reinterpret_cast<uint32_t*>(&l2);
}
__device__ __forceinline__ void split2h(float x, float y, uint32_t& hi, uint32_t& lo) {
    __half2 h = __floats2half2_rn(x, y);
    __half2 l = __floats2half2_rn(x - __half2float(h.x), y - __half2float(h.y));
    hi = *reinterpret_cast<uint32_t*>(&h);
    lo = *reinterpret_cast<uint32_t*>(&l);
}
__device__ __forceinline__ uint32_t pack_h2(float x, float y) {
    __half2 h = __floats2half2_rn(x, y);
    return *reinterpret_cast<uint32_t*>(&h);
}
__device__ __forceinline__ float ex2f(float x) {
    float y; asm("ex2.approx.f32 %0, %1;" : "=f"(y) : "f"(x)); return y;
}
__device__ __forceinline__ void cp16(uint32_t dst, const void* src) {
    asm volatile("cp.async.cg.shared.global [%0], [%1], 16;" :: "r"(dst), "l"(src));
}
#define CP_COMMIT() asm volatile("cp.async.commit_group;" ::: "memory")
#define CP_WAIT0()  asm volatile("cp.async.wait_group 0;" ::: "memory")

// ---------------- elementwise ----------------
// fused hi/lo split of x, W_qkv, W_proj in ONE launch (2 elems per thread)
#define XS_PAIRS 3145728
#define WQ_PAIRS 589824
#define WP_PAIRS 294912
__global__ void split_all_kernel(const float* __restrict__ x,
                                 const float* __restrict__ Wq,
                                 const float* __restrict__ Wp) {
    int i = blockIdx.x * 256 + threadIdx.x;
    const float* src;
    __nv_bfloat16 *h, *l;
    int off;
    if (i < XS_PAIRS) {
        src = x; h = g_xh; l = g_xl; off = i;
    } else if (i < XS_PAIRS + WQ_PAIRS) {
        src = Wq; h = g_wqh; l = g_wql; off = i - XS_PAIRS;
    } else if (i < XS_PAIRS + WQ_PAIRS + WP_PAIRS) {
        src = Wp; h = g_wph; l = g_wpl; off = i - XS_PAIRS - WQ_PAIRS;
    } else return;
    float2 v = ((const float2*)src)[off];
    uint32_t hh, ll;
    split2(v.x, v.y, hh, ll);
    ((uint32_t*)h)[off] = hh;
    ((uint32_t*)l)[off] = ll;
}

__global__ void k2_init_kernel() {
    size_t i2 = (size_t)blockIdx.x * 256 + threadIdx.x;
    if (i2 >= KV_ELEMS / 2) return;
    size_t i = i2 * 2;
    int bh = (int)(i / ((size_t)N_ * HD_));
    float mu = g_mu[bh];
    float lm = LAMBD_ * mu;
    float2 kk = *(const float2*)&g_k[i];
    float s0 = (kk.x >= lm) ? (kk.x - lm) : ((kk.x <= -lm) ? (kk.x + lm) : 0.f);
    float s1 = (kk.y >= lm) ? (kk.y - lm) : ((kk.y <= -lm) ? (kk.y + lm) : 0.f);
    *(float2*)&g_s[i] = make_float2(s0, s1);
    *(float2*)&g_y[i] = make_float2(0.f, 0.f);
    uint32_t hh, ll;
    split2((kk.x - s0) * QSC_, (kk.y - s1) * QSC_, hh, ll);
    *(uint32_t*)&g_k2h_a[i] = hh;
    *(uint32_t*)&g_k2l_a[i] = ll;
}

__global__ void mu_part_kernel() {
    __shared__ float red[256];
    int bh = blockIdx.x >> 3;
    int sl = blockIdx.x & 7;
    const float* p = g_k + (size_t)bh * N_ * HD_ + sl * 8192;
    float s = 0.f;
    #pragma unroll
    for (int i = 0; i < 32; i++) s += fabsf(p[threadIdx.x + i * 256]);
    red[threadIdx.x] = s;
    __syncthreads();
    for (int st = 128; st > 0; st >>= 1) {
        if (threadIdx.x < st) red[threadIdx.x] += red[threadIdx.x + st];
        __syncthreads();
    }
    if (threadIdx.x == 0) g_mu_part[blockIdx.x] = red[0];
}
__global__ void mu_fin_kernel() {
    int bh = threadIdx.x;
    if (bh >= BH_) return;
    float s = 0.f;
    #pragma unroll
    for (int i = 0; i < 8; i++) s += g_mu_part[bh * 8 + i];
    g_mu[bh] = ((float)N_ * (float)C_ / 4.0f) / s;
}

// =================== flash iteration (iters 0..4) + fused y/s/k2 update ===================
// KV tiles of 64 rows, stage = {Bh, Bl, Vh} -> smem 92.2KB -> 2 CTAs/SM.
#define FSPAD 72
#define FA_H  0
#define FA_L  9216
#define FSTG0 18432
#define FSTGS_I 13824
#define FSTGS_F 18432
#define FS_BH 0
#define FS_BL 4608
#define FS_VH 9216
#define FS_VL 13824
#define FA_BL 9216       // final pass A (128-row B tiles): Bl offset

__global__ void __launch_bounds__(256, 2) flash_iter_kernel(
    const __nv_bfloat16* __restrict__ k2h_src, const __nv_bfloat16* __restrict__ k2l_src,
    __nv_bfloat16* __restrict__ k2h_dst, __nv_bfloat16* __restrict__ k2l_dst)
{
    extern __shared__ __nv_bfloat16 fsm[];
    const int bh = blockIdx.y;
    const int i0 = blockIdx.x * 128;
    const int tid = threadIdx.x, wid = tid >> 5, lane = tid & 31;

    const size_t hbase = (size_t)bh * N_ * HD_;
    const __nv_bfloat16* Gh = k2h_src + hbase;
    const __nv_bfloat16* Gl = k2l_src + hbase;
    const __half* Vh = g_vh + hbase;
    const float mu = g_mu[bh];

    #pragma unroll
    for (int i = 0; i < 8; i++) {
        int idx = tid + i * 256;
        int arr = idx >> 10, rem = idx & 1023, row = rem >> 3, c = rem & 7;
        const __nv_bfloat16* src = (arr ? Gl : Gh) + (size_t)(i0 + row) * HD_ + c * 8;
        *(uint4*)(fsm + (arr ? FA_L : FA_H) + row * FSPAD + c * 8) = *(const uint4*)src;
    }

    auto cp_tile = [&](int stage, int j) {
        int sbase = FSTG0 + stage * FSTGS_I;
        #pragma unroll
        for (int i = 0; i < 6; i++) {
            int idx = tid + i * 256;
            int arr = idx >> 9, rem = idx & 511, row = rem >> 3, c = rem & 7;
            const void* src;
            int off;
            if      (arr == 0) { src = Gh + (size_t)(j * 64 + row) * HD_ + c * 8; off = FS_BH; }
            else if (arr == 1) { src = Gl + (size_t)(j * 64 + row) * HD_ + c * 8; off = FS_BL; }
            else               { src = Vh + (size_t)(j * 64 + row) * HD_ + c * 8; off = FS_VH; }
            cp16(smem_u32(fsm + sbase + off + row * FSPAD + c * 8), src);
        }
    };

    cp_tile(0, 0);
    CP_COMMIT(); CP_WAIT0();
    __syncthreads();

    float m0 = -1e30f, m1 = -1e30f, l0 = 0.f, l1 = 0.f;
    float acco[8][4] = {};

    for (int j = 0; j < 16; j++) {
        if (j < 15) { cp_tile((j + 1) & 1, j + 1); CP_COMMIT(); }
        const __nv_bfloat16* sb = fsm + FSTG0 + (j & 1) * FSTGS_I;

        float accs[8][4] = {};
        #pragma unroll
        for (int ks = 0; ks < 4; ks++) {
            uint32_t aH[4], aL[4];
            {
                int ar = wid * 16 + (lane & 15);
                int ac = ks * 16 + ((lane >> 4) << 3);
                ldsm4(aH, smem_u32(fsm + FA_H + ar * FSPAD + ac));
                ldsm4(aL, smem_u32(fsm + FA_L + ar * FSPAD + ac));
            }
            #pragma unroll
            for (int ng = 0; ng < 2; ng++) {
                uint32_t bh2[2][4], bl2[2][4];
                #pragma unroll
                for (int p = 0; p < 2; p++) {
                    int nr = ng * 32 + p * 16 + (lane & 7) + ((lane >> 4) << 3);
                    int kc = ks * 16 + (((lane >> 3) & 1) << 3);
                    ldsm4(bh2[p], smem_u32(sb + FS_BH + nr * FSPAD + kc));
                    ldsm4(bl2[p], smem_u32(sb + FS_BL + nr * FSPAD + kc));
                }
                #pragma unroll
                for (int t = 0; t < 4; t++) {
                    float* c = accs[ng * 4 + t];
                    const uint32_t* bhf = &bh2[t >> 1][(t & 1) * 2];
                    const uint32_t* blf = &bl2[t >> 1][(t & 1) * 2];
                    mma_bf16(c, aH, bhf);
                    mma_bf16(c, aH, blf);
                    mma_bf16(c, aL, bhf);
                }
            }
        }

        float tm0 = -1e30f, tm1 = -1e30f;
        #pragma unroll
        for (int t = 0; t < 8; t++) {
            tm0 = fmaxf(tm0, fmaxf(accs[t][0], accs[t][1]));
            tm1 = fmaxf(tm1, fmaxf(accs[t][2], accs[t][3]));
        }
        tm0 = fmaxf(tm0, __shfl_xor_sync(0xFFFFFFFF, tm0, 1));
        tm0 = fmaxf(tm0, __shfl_xor_sync(0xFFFFFFFF, tm0, 2));
        tm1 = fmaxf(tm1, __shfl_xor_sync(0xFFFFFFFF, tm1, 1));
        tm1 = fmaxf(tm1, __shfl_xor_sync(0xFFFFFFFF, tm1, 2));
        float mn0 = fmaxf(m0, tm0), mn1 = fmaxf(m1, tm1);
        float sc0 = ex2f(m0 - mn0), sc1 = ex2f(m1 - mn1);
        m0 = mn0; m1 = mn1;
        float rs0 = 0.f, rs1 = 0.f;
        #pragma unroll
        for (int t = 0; t < 8; t++) {
            accs[t][0] = ex2f(accs[t][0] - m0);
            accs[t][1] = ex2f(accs[t][1] - m0);
            accs[t][2] = ex2f(accs[t][2] - m1);
            accs[t][3] = ex2f(accs[t][3] - m1);
            rs0 += accs[t][0] + accs[t][1];
            rs1 += accs[t][2] + accs[t][3];
        }
        rs0 += __shfl_xor_sync(0xFFFFFFFF, rs0, 1);
        rs0 += __shfl_xor_sync(0xFFFFFFFF, rs0, 2);
        rs1 += __shfl_xor_sync(0xFFFFFFFF, rs1, 1);
        rs1 += __shfl_xor_sync(0xFFFFFFFF, rs1, 2);
        l0 = l0 * sc0 + rs0;
        l1 = l1 * sc1 + rs1;
        #pragma unroll
        for (int o = 0; o < 8; o++) {
            acco[o][0] *= sc0; acco[o][1] *= sc0;
            acco[o][2] *= sc1; acco[o][3] *= sc1;
        }

        // PV: P fp16 x Vh (single product)
        #pragma unroll
        for (int kt = 0; kt < 4; kt++) {
            uint32_t pH[4];
            pH[0] = pack_h2(accs[2*kt][0],   accs[2*kt][1]);
            pH[1] = pack_h2(accs[2*kt][2],   accs[2*kt][3]);
            pH[2] = pack_h2(accs[2*kt+1][0], accs[2*kt+1][1]);
            pH[3] = pack_h2(accs[2*kt+1][2], accs[2*kt+1][3]);
            #pragma unroll
            for (int vg = 0; vg < 2; vg++) {
                uint32_t vh2[2][4];
                #pragma unroll
                for (int q = 0; q < 2; q++) {
                    int vr = kt * 16 + (lane & 15);
                    int vc = vg * 32 + q * 16 + ((lane >> 4) << 3);
                    ldsm4t(vh2[q], smem_u32(sb + FS_VH + vr * FSPAD + vc));
                }
                #pragma unroll
                for (int t = 0; t < 4; t++)
                    mma_f16(acco[vg * 4 + t], pH, &vh2[t >> 1][(t & 1) * 2]);
            }
        }

        if (j < 15) CP_WAIT0();
        __syncthreads();
    }

    float inv0 = 1.f / l0, inv1 = 1.f / l1;
    float imu = 1.f / mu;
    float lm = LAMBD_ * mu;
    int row0 = i0 + wid * 16 + (lane >> 2);
    #pragma unroll
    for (int o = 0; o < 8; o++) {
        int col = o * 8 + (lane & 3) * 2;
        #pragma unroll
        for (int half = 0; half < 2; half++) {
            size_t ia = hbase + (size_t)(row0 + half * 8) * HD_ + col;
            float la = acco[o][half * 2]     * (half ? inv1 : inv0);
            float lb = acco[o][half * 2 + 1] * (half ? inv1 : inv0);
            float2 kv = *(const float2*)&g_k[ia];
            float2 yv = *(const float2*)&g_y[ia];
            float2 sv = *(const float2*)&g_s[ia];
            float yn0 = yv.x + mu * (kv.x - la - sv.x);
            float yn1 = yv.y + mu * (kv.y - lb - sv.y);
            float ym0 = yn0 * imu, ym1 = yn1 * imu;
            float t0 = kv.x - la + ym0, t1 = kv.y - lb + ym1;
            float sn0 = (t0 >= lm) ? (t0 - lm) : ((t0 <= -lm) ? (t0 + lm) : 0.f);
            float sn1 = (t1 >= lm) ? (t1 - lm) : ((t1 <= -lm) ? (t1 + lm) : 0.f);
            *(float2*)&g_y[ia] = make_float2(yn0, yn1);
            *(float2*)&g_s[ia] = make_float2(sn0, sn1);
            float k20 = (kv.x - sn0 - ym0) * QSC_;
            float k21 = (kv.y - sn1 - ym1) * QSC_;
            uint32_t h2, l2;
            split2(k20, k21, h2, l2);
            *(uint32_t*)&k2h_dst[ia] = h2;
            *(uint32_t*)&k2l_dst[ia] = l2;
        }
    }
}

// =================== final iteration: 2-pass flash, materializes attn + obnc ===================
__global__ void __launch_bounds__(256, 2) final_flash_kernel(
    float* __restrict__ attn,
    const __nv_bfloat16* __restrict__ k2h_src, const __nv_bfloat16* __restrict__ k2l_src)
{
    extern __shared__ __nv_bfloat16 fsm[];
    const int bh = blockIdx.y;
    const int i0 = blockIdx.x * 128;
    const int tid = threadIdx.x, wid = tid >> 5, lane = tid & 31;

    const size_t hbase = (size_t)bh * N_ * HD_;
    const __nv_bfloat16* Gh = k2h_src + hbase;
    const __nv_bfloat16* Gl = k2l_src + hbase;
    const __half* Vh = g_vh + hbase;
    const __half* Vl = g_vl + hbase;

    #pragma unroll
    for (int i = 0; i < 8; i++) {
        int idx = tid + i * 256;
        int arr = idx >> 10, rem = idx & 1023, row = rem >> 3, c = rem & 7;
        const __nv_bfloat16* src = (arr ? Gl : Gh) + (size_t)(i0 + row) * HD_ + c * 8;
        *(uint4*)(fsm + (arr ? FA_L : FA_H) + row * FSPAD + c * 8) = *(const uint4*)src;
    }

    auto cp_tileA = [&](int stage, int j) {
        int sbase = FSTG0 + stage * FSTGS_F;
        #pragma unroll
        for (int i = 0; i < 8; i++) {
            int idx = tid + i * 256;
            int arr = idx >> 10, rem = idx & 1023, row = rem >> 3, c = rem & 7;
            const __nv_bfloat16* src = (arr ? Gl : Gh) + (size_t)(j * 128 + row) * HD_ + c * 8;
            cp16(smem_u32(fsm + sbase + (arr ? FA_BL : FS_BH) + row * FSPAD + c * 8), src);
        }
    };
    auto cp_tileB = [&](int stage, int j) {
        int sbase = FSTG0 + stage * FSTGS_F;
        #pragma unroll
        for (int i = 0; i < 8; i++) {
            int idx = tid + i * 256;
            int arr = idx >> 9, rem = idx & 511, row = rem >> 3, c = rem & 7;
            const void* src;
            int off;
            if      (arr == 0) { src = Gh + (size_t)(j * 64 + row) * HD_ + c * 8; off = FS_BH; }
            else if (arr == 1) { src = Gl + (size_t)(j * 64 + row) * HD_ + c * 8; off = FS_BL; }
            else if (arr == 2) { src = Vh + (size_t)(j * 64 + row) * HD_ + c * 8; off = FS_VH; }
            else               { src = Vl + (size_t)(j * 64 + row) * HD_ + c * 8; off = FS_VL; }
            cp16(smem_u32(fsm + sbase + off + row * FSPAD + c * 8), src);
        }
    };

    // ---------- PASS A: row stats over 128-wide tiles ----------
    cp_tileA(0, 0);
    CP_COMMIT(); CP_WAIT0();
    __syncthreads();

    float m0 = -1e30f, m1 = -1e30f, l0 = 0.f, l1 = 0.f;
    for (int j = 0; j < 8; j++) {
        if (j < 7) { cp_tileA((j + 1) & 1, j + 1); CP_COMMIT(); }
        const __nv_bfloat16* sb = fsm + FSTG0 + (j & 1) * FSTGS_F;
        float accs[16][4] = {};
        #pragma unroll
        for (int ks = 0; ks < 4; ks++) {
            uint32_t aH[4], aL[4];
            {
                int ar = wid * 16 + (lane & 15);
                int ac = ks * 16 + ((lane >> 4) << 3);
                ldsm4(aH, smem_u32(fsm + FA_H + ar * FSPAD + ac));
                ldsm4(aL, smem_u32(fsm + FA_L + ar * FSPAD + ac));
            }
            #pragma unroll
            for (int ng = 0; ng < 4; ng++) {
                uint32_t bh2[2][4], bl2[2][4];
                #pragma unroll
                for (int p = 0; p < 2; p++) {
                    int nr = ng * 32 + p * 16 + (lane & 7) + ((lane >> 4) << 3);
                    int kc = ks * 16 + (((lane >> 3) & 1) << 3);
                    ldsm4(bh2[p], smem_u32(sb + FS_BH + nr * FSPAD + kc));
                    ldsm4(bl2[p], smem_u32(sb + FA_BL + nr * FSPAD + kc));
                }
                #pragma unroll
                for (int t = 0; t < 4; t++) {
                    float* c = accs[ng * 4 + t];
                    const uint32_t* bhf = &bh2[t >> 1][(t & 1) * 2];
                    const uint32_t* blf = &bl2[t >> 1][(t & 1) * 2];
                    mma_bf16(c, aH, bhf);
                    mma_bf16(c, aH, blf);
                    mma_bf16(c, aL, bhf);
                }
            }
        }

        float tm0 = -1e30f, tm1 = -1e30f;
        #pragma unroll
        for (int t = 0; t < 16; t++) {
            tm0 = fmaxf(tm0, fmaxf(accs[t][0], accs[t][1]));
            tm1 = fmaxf(tm1, fmaxf(accs[t][2], accs[t][3]));
        }
        tm0 = fmaxf(tm0, __shfl_xor_sync(0xFFFFFFFF, tm0, 1));
        tm0 = fmaxf(tm0, __shfl_xor_sync(0xFFFFFFFF, tm0, 2));
        tm1 = fmaxf(tm1, __shfl_xor_sync(0xFFFFFFFF, tm1, 1));
        tm1 = fmaxf(tm1, __shfl_xor_sync(0xFFFFFFFF, tm1, 2));
        float mn0 = fmaxf(m0, tm0), mn1 = fmaxf(m1, tm1);
        float sc0 = ex2f(m0 - mn0), sc1 = ex2f(m1 - mn1);
        m0 = mn0; m1 = mn1;
        float rs0 = 0.f, rs1 = 0.f;
        #pragma unroll
        for (int t = 0; t < 16; t++) {
            rs0 += ex2f(accs[t][0] - m0) + ex2f(accs[t][1] - m0);
            rs1 += ex2f(accs[t][2] - m1) + ex2f(accs[t][3] - m1);
        }
        rs0 += __shfl_xor_sync(0xFFFFFFFF, rs0, 1);
        rs0 += __shfl_xor_sync(0xFFFFFFFF, rs0, 2);
        rs1 += __shfl_xor_sync(0xFFFFFFFF, rs1, 1);
        rs1 += __shfl_xor_sync(0xFFFFFFFF, rs1, 2);
        l0 = l0 * sc0 + rs0;
        l1 = l1 * sc1 + rs1;
        if (j < 7) CP_WAIT0();
        __syncthreads();
    }
    float inv0 = 1.f / l0, inv1 = 1.f / l1;

    // ---------- PASS B: normalized P -> attn, PV (64-wide tiles) ----------
    cp_tileB(0, 0);
    CP_COMMIT(); CP_WAIT0();
    __syncthreads();

    float* Sp = attn + (size_t)bh * N_ * N_;
    const int prow = i0 + wid * 16 + (lane >> 2);
    float acco[8][4] = {};

    for (int j = 0; j < 16; j++) {
        if (j < 15) { cp_tileB((j + 1) & 1, j + 1); CP_COMMIT(); }
        const __nv_bfloat16* sb = fsm + FSTG0 + (j & 1) * FSTGS_F;
        float accs[8][4] = {};
        #pragma unroll
        for (int ks = 0; ks < 4; ks++) {
            uint32_t aH[4], aL[4];
            {
                int ar = wid * 16 + (lane & 15);
                int ac = ks * 16 + ((lane >> 4) << 3);
                ldsm4(aH, smem_u32(fsm + FA_H + ar * FSPAD + ac));
                ldsm4(aL, smem_u32(fsm + FA_L + ar * FSPAD + ac));
            }
            #pragma unroll
            for (int ng = 0; ng < 2; ng++) {
                uint32_t bh2[2][4], bl2[2][4];
                #pragma unroll
                for (int p = 0; p < 2; p++) {
                    int nr = ng * 32 + p * 16 + (lane & 7) + ((lane >> 4) << 3);
                    int kc = ks * 16 + (((lane >> 3) & 1) << 3);
                    ldsm4(bh2[p], smem_u32(sb + FS_BH + nr * FSPAD + kc));
                    ldsm4(bl2[p], smem_u32(sb + FS_BL + nr * FSPAD + kc));
                }
                #pragma unroll
                for (int t = 0; t < 4; t++) {
                    float* c = accs[ng * 4 + t];
                    const uint32_t* bhf = &bh2[t >> 1][(t & 1) * 2];
                    const uint32_t* blf = &bl2[t >> 1][(t & 1) * 2];
                    mma_bf16(c, aH, bhf);
                    mma_bf16(c, aH, blf);
                    mma_bf16(c, aL, bhf);
                }
            }
        }

        #pragma unroll
        for (int t = 0; t < 8; t++) {
            accs[t][0] = ex2f(accs[t][0] - m0) * inv0;
            accs[t][1] = ex2f(accs[t][1] - m0) * inv0;
            accs[t][2] = ex2f(accs[t][2] - m1) * inv1;
            accs[t][3] = ex2f(accs[t][3] - m1) * inv1;
            int col = j * 64 + (t >> 2) * 32 + (t & 3) * 8 + (lane & 3) * 2;
            *(float2*)&Sp[(size_t)prow * N_ + col]       = make_float2(accs[t][0], accs[t][1]);
            *(float2*)&Sp[(size_t)(prow + 8) * N_ + col] = make_float2(accs[t][2], accs[t][3]);
        }

        #pragma unroll
        for (int kt = 0; kt < 4; kt++) {
            uint32_t pH[4];
            pH[0] = pack_h2(accs[2*kt][0],   accs[2*kt][1]);
            pH[1] = pack_h2(accs[2*kt][2],   accs[2*kt][3]);
            pH[2] = pack_h2(accs[2*kt+1][0], accs[2*kt+1][1]);
            pH[3] = pack_h2(accs[2*kt+1][2], accs[2*kt+1][3]);
            #pragma unroll
            for (int vg = 0; vg < 2; vg++) {
                uint32_t vh2[2][4], vl2[2][4];
                #pragma unroll
                for (int q = 0; q < 2; q++) {
                    int vr = kt * 16 + (lane & 15);
                    int vc = vg * 32 + q * 16 + ((lane >> 4) << 3);
                    ldsm4t(vh2[q], smem_u32(sb + FS_VH + vr * FSPAD + vc));
                    ldsm4t(vl2[q], smem_u32(sb + FS_VL + vr * FSPAD + vc));
                }
                #pragma unroll
                for (int t = 0; t < 4; t++) {
                    float* o = acco[vg * 4 + t];
                    mma_f16(o, pH, &vh2[t >> 1][(t & 1) * 2]);
                    mma_f16(o, pH, &vl2[t >> 1][(t & 1) * 2]);
                }
            }
        }

        if (j < 15) CP_WAIT0();
        __syncthreads();
    }

    int b = bh / H_, h = bh % H_;
    #pragma unroll
    for (int o = 0; o < 8; o++) {
        int col = o * 8 + (lane & 3) * 2;
        uint32_t h0, l0b, h1, l1b;
        split2(acco[o][0], acco[o][1], h0, l0b);
        split2(acco[o][2], acco[o][3], h1, l1b);
        size_t idx0 = ((size_t)(b * N_ + prow)) * C_ + h * HD_ + col;
        size_t idx1 = ((size_t)(b * N_ + prow + 8)) * C_ + h * HD_ + col;
        *(uint32_t*)&g_och[idx0] = h0;
        *(uint32_t*)&g_ocl[idx0] = l0b;
        *(uint32_t*)&g_och[idx1] = h1;
        *(uint32_t*)&g_ocl[idx1] = l1b;
    }
}

// =================== bf16x3 HMMA GEMM: qkv and proj ===================
#define QA_H 0
#define QA_L 9216
#define QB_H 18432
#define QB_L 23040
#define QSTG 27648
#define WPAD 72

template<int NCOLS, int KDIM>
__device__ __forceinline__ void mma_gemm_main(
    const __nv_bfloat16* __restrict__ Ah, const __nv_bfloat16* __restrict__ Al,
    const __nv_bfloat16* __restrict__ Wh, const __nv_bfloat16* __restrict__ Wl,
    __nv_bfloat16* sm, int by, int bx, float acc[2][4][4])
{
    const int tid = threadIdx.x, wid = tid >> 5, lane = tid & 31;
    const int wm = wid & 3, wn = wid >> 2;

    auto cp_stage = [&](int stage, int k0) {
        int sb = stage * QSTG;
        #pragma unroll
        for (int i = 0; i < 8; i++) {
            int idx = tid + i * 256;
            int arr = idx >> 10, rem = idx & 1023, row = rem >> 3, c = rem & 7;
            const __nv_bfloat16* src = (arr ? Al : Ah) + (size_t)(by + row) * KDIM + k0 + c * 8;
            cp16(smem_u32(sm + sb + (arr ? QA_L : QA_H) + row * FSPAD + c * 8), src);
        }
        #pragma unroll
        for (int i = 0; i < 4; i++) {
            int idx = tid + i * 256;
            int arr = idx >> 9, rem = idx & 511, row = rem >> 3, c = rem & 7;
            const __nv_bfloat16* src = (arr ? Wl : Wh) + (size_t)(k0 + row) * NCOLS + bx + c * 8;
            cp16(smem_u32(sm + sb + (arr ? QB_L : QB_H) + row * WPAD + c * 8), src);
        }
    };

    cp_stage(0, 0);
    CP_COMMIT(); CP_WAIT0();
    __syncthreads();

    const int NCHUNK = KDIM / 64;
    for (int ch = 0; ch < NCHUNK; ch++) {
        if (ch < NCHUNK - 1) { cp_stage((ch + 1) & 1, (ch + 1) * 64); CP_COMMIT(); }
        __nv_bfloat16* sb = sm + (ch & 1) * QSTG;
        #pragma unroll
        for (int ks = 0; ks < 4; ks++) {
            uint32_t aH[2][4], aL[2][4];
            #pragma unroll
            for (int mt = 0; mt < 2; mt++) {
                int ar = wm * 32 + mt * 16 + (lane & 15);
                int ac = ks * 16 + ((lane >> 4) << 3);
                ldsm4(aH[mt], smem_u32(sb + QA_H + ar * FSPAD + ac));
                ldsm4(aL[mt], smem_u32(sb + QA_L + ar * FSPAD + ac));
            }
            uint32_t bh2[2][4], bl2[2][4];
            #pragma unroll
            for (int q = 0; q < 2; q++) {
                int vr = ks * 16 + (lane & 15);
                int vc = wn * 32 + q * 16 + ((lane >> 4) << 3);
                ldsm4t(bh2[q], smem_u32(sb + QB_H + vr * WPAD + vc));
                ldsm4t(bl2[q], smem_u32(sb + QB_L + vr * WPAD + vc));
            }
            #pragma unroll
            for (int mt = 0; mt < 2; mt++)
                #pragma unroll
                for (int nt = 0; nt < 4; nt++) {
                    const uint32_t* bhf = &bh2[nt >> 1][(nt & 1) * 2];
                    const uint32_t* blf = &bl2[nt >> 1][(nt & 1) * 2];
                    mma_bf16(acc[mt][nt], aH[mt], bhf);
                    mma_bf16(acc[mt][nt], aH[mt], blf);
                    mma_bf16(acc[mt][nt], aL[mt], bhf);
                }
        }
        if (ch < NCHUNK - 1) CP_WAIT0();
        __syncthreads();
    }
}

__global__ void __launch_bounds__(256, 2) qkv_mma_kernel(const float* __restrict__ bias) {
    extern __shared__ __nv_bfloat16 qsm[];
    const int bx = blockIdx.x * 64;
    const int by = blockIdx.y * 128;
    const int wid = threadIdx.x >> 5, lane = threadIdx.x & 31;
    const int wm = wid & 3, wn = wid >> 2;

    float acc[2][4][4] = {};
    mma_gemm_main<TWO_C_, C_>(g_xh, g_xl, g_wqh, g_wql, qsm, by, bx, acc);

    #pragma unroll
    for (int mt = 0; mt < 2; mt++) {
        int r0 = by + wm * 32 + mt * 16 + (lane >> 2);
        #pragma unroll
        for (int nt = 0; nt < 4; nt++) {
            int col = bx + wn * 32 + nt * 8 + (lane & 3) * 2;
            float b0 = bias[col], b1 = bias[col + 1];
            #pragma unroll
            for (int half = 0; half < 2; half++) {
                int r = r0 + half * 8;
                float v0 = acc[mt][nt][half * 2]     + b0;
                float v1 = acc[mt][nt][half * 2 + 1] + b1;
                int bb = r >> 10, n = r & 1023;
                int which = col >= C_;
                int cc = col - which * C_;
                int hh = cc / HD_, hd = cc % HD_;
                size_t idx = (((size_t)(bb * H_ + hh)) * N_ + n) * HD_ + hd;
                if (!which) {
                    *(float2*)&g_k[idx] = make_float2(v0, v1);
                } else {
                    uint32_t h2, l2;
                    split2h(v0, v1, h2, l2);
                    *(uint32_t*)&g_vh[idx] = h2;
                    *(uint32_t*)&g_vl[idx] = l2;
                }
            }
        }
    }
}

__global__ void __launch_bounds__(256, 2) proj_mma_kernel(const float* __restrict__ bias,
                                                          float* __restrict__ out) {
    extern __shared__ __nv_bfloat16 qsm[];
    const int bx = blockIdx.x * 64;
    const int by = blockIdx.y * 128;
    const int wid = threadIdx.x >> 5, lane = threadIdx.x & 31;
    const int wm = wid & 3, wn = wid >> 2;

    float acc[2][4][4] = {};
    mma_gemm_main<C_, C_>(g_och, g_ocl, g_wph, g_wpl, qsm, by, bx, acc);

    #pragma unroll
    for (int mt = 0; mt < 2; mt++) {
        int r0 = by + wm * 32 + mt * 16 + (lane >> 2);
        #pragma unroll
        for (int nt = 0; nt < 4; nt++) {
            int col = bx + wn * 32 + nt * 8 + (lane & 3) * 2;
            float b0 = bias[col], b1 = bias[col + 1];
            *(float2*)&out[(size_t)r0 * C_ + col] =
                make_float2(acc[mt][nt][0] + b0, acc[mt][nt][1] + b1);
            *(float2*)&out[(size_t)(r0 + 8) * C_ + col] =
                make_float2(acc[mt][nt][2] + b0, acc[mt][nt][3] + b1);
        }
    }
}

// ---------------- launch ----------------
extern "C" void kernel_launch(void* const* d_in, const int* in_sizes, int n_in,
                              void* d_out, int out_size) {
    const float* x     = (const float*)d_in[0];
    const float* Wqkv  = (const float*)d_in[1];
    const float* bqkv  = (const float*)d_in[2];
    const float* Wproj = (const float*)d_in[3];
    const float* bproj = (const float*)d_in[4];
    float* out = (float*)d_out;

    float* attn;
    if ((size_t)out_size >= OUT_ELEMS + ATTN_ELEMS) {
        attn = out + OUT_ELEMS;
    } else {
        void* p = nullptr;
        cudaGetSymbolAddress(&p, g_attn_fallback);
        attn = (float*)p;
    }

    const int FLASH_SMEM_I = (FSTG0 + 2 * FSTGS_I) * 2;   // 92,160 B
    const int FLASH_SMEM_F = (FSTG0 + 2 * FSTGS_F) * 2;   // 110,592 B
    const int GEMM_SMEM    = 2 * QSTG * 2;                // 110,592 B
    cudaFuncSetAttribute(flash_iter_kernel, cudaFuncAttributeMaxDynamicSharedMemorySize, FLASH_SMEM_I);
    cudaFuncSetAttribute(final_flash_kernel, cudaFuncAttributeMaxDynamicSharedMemorySize, FLASH_SMEM_F);
    cudaFuncSetAttribute(qkv_mma_kernel, cudaFuncAttributeMaxDynamicSharedMemorySize, GEMM_SMEM);
    cudaFuncSetAttribute(proj_mma_kernel, cudaFuncAttributeMaxDynamicSharedMemorySize, GEMM_SMEM);

    __nv_bfloat16 *k2h_a, *k2l_a, *k2h_b, *k2l_b;
    { void* p; cudaGetSymbolAddress(&p, g_k2h_a); k2h_a = (__nv_bfloat16*)p; }
    { void* p; cudaGetSymbolAddress(&p, g_k2l_a); k2l_a = (__nv_bfloat16*)p; }
    { void* p; cudaGetSymbolAddress(&p, g_k2h_b); k2h_b = (__nv_bfloat16*)p; }
    { void* p; cudaGetSymbolAddress(&p, g_k2l_b); k2l_b = (__nv_bfloat16*)p; }

    const int TOTAL_PAIRS = XS_PAIRS + WQ_PAIRS + WP_PAIRS;
    split_all_kernel<<<(TOTAL_PAIRS + 255) / 256, 256>>>(x, Wqkv, Wproj);

    qkv_mma_kernel<<<dim3(TWO_C_ / 64, M_ROWS / 128), 256, GEMM_SMEM>>>(bqkv);
    mu_part_kernel<<<BH_ * 8, 256>>>();
    mu_fin_kernel<<<1, 128>>>();
    k2_init_kernel<<<(int)((KV_ELEMS / 2 + 255) / 256), 256>>>();

    __nv_bfloat16* bufs_h[2] = {k2h_a, k2h_b};
    __nv_bfloat16* bufs_l[2] = {k2l_a, k2l_b};
    for (int it = 0; it < 5; ++it) {
        int s = it & 1, d = (it + 1) & 1;
        flash_iter_kernel<<<dim3(N_ / 128, BH_), 256, FLASH_SMEM_I>>>(
            bufs_h[s], bufs_l[s], bufs_h[d], bufs_l[d]);
    }
    final_flash_kernel<<<dim3(N_ / 128, BH_), 256, FLASH_SMEM_F>>>(attn, bufs_h[1], bufs_l[1]);

    proj_mma_kernel<<<dim3(C_ / 64, M_ROWS / 128), 256, GEMM_SMEM>>>(bproj, out);
}

// round 15
// speedup vs baseline: 1.0178x; 1.0012x over previous
#include <cuda_runtime.h>
#include <cuda_bf16.h>
#include <cuda_fp16.h>
#include <math.h>
#include <stdint.h>

#define B_   8
#define N_   1024
#define C_   768
#define H_   12
#define HD_  64
#define BH_  (B_*H_)
#define TWO_C_ (2*C_)
#define M_ROWS (B_*N_)

static const size_t KV_ELEMS   = (size_t)BH_ * N_ * HD_;
static const size_t OUT_ELEMS  = (size_t)B_ * N_ * C_;
static const size_t ATTN_ELEMS = (size_t)BH_ * N_ * N_;

#define LAMBD_ 4.0f
// logits carried in log2 domain: S2 = (k2*QSC)·(k2*QSC)^T where QSC^2 = 0.125*log2(e)
#define QSC_ 0.42466089f

// ---------------- device scratch ----------------
__device__ float g_k [6291456];
__device__ float g_y [6291456];
__device__ float g_s [6291456];
__device__ __nv_bfloat16 g_k2h_a[6291456];
__device__ __nv_bfloat16 g_k2l_a[6291456];
__device__ __nv_bfloat16 g_k2h_b[6291456];
__device__ __nv_bfloat16 g_k2l_b[6291456];
__device__ __half g_vh [6291456];
__device__ __half g_vl [6291456];
__device__ __nv_bfloat16 g_xh [6291456];
__device__ __nv_bfloat16 g_xl [6291456];
__device__ __nv_bfloat16 g_wqh[1179648];
__device__ __nv_bfloat16 g_wql[1179648];
__device__ __nv_bfloat16 g_wph[589824];
__device__ __nv_bfloat16 g_wpl[589824];
__device__ __nv_bfloat16 g_och[6291456];
__device__ __nv_bfloat16 g_ocl[6291456];
__device__ float g_mu[96];
__device__ float g_mu_part[768];
__device__ float g_attn_fallback[100663296];

// ---------------- helpers ----------------
__device__ __forceinline__ uint32_t smem_u32(const void* p) {
    uint32_t a;
    asm("{ .reg .u64 t; cvta.to.shared.u64 t, %1; cvt.u32.u64 %0, t; }" : "=r"(a) : "l"(p));
    return a;
}
__device__ __forceinline__ void ldsm4(uint32_t r[4], uint32_t addr) {
    asm volatile("ldmatrix.sync.aligned.m8n8.x4.shared.b16 {%0,%1,%2,%3}, [%4];"
        : "=r"(r[0]), "=r"(r[1]), "=r"(r[2]), "=r"(r[3]) : "r"(addr));
}
__device__ __forceinline__ void ldsm4t(uint32_t r[4], uint32_t addr) {
    asm volatile("ldmatrix.sync.aligned.m8n8.x4.trans.shared.b16 {%0,%1,%2,%3}, [%4];"
        : "=r"(r[0]), "=r"(r[1]), "=r"(r[2]), "=r"(r[3]) : "r"(addr));
}
__device__ __forceinline__ void mma_bf16(float c[4], const uint32_t a[4], const uint32_t* b) {
    asm volatile("mma.sync.aligned.m16n8k16.row.col.f32.bf16.bf16.f32 "
        "{%0,%1,%2,%3}, {%4,%5,%6,%7}, {%8,%9}, {%0,%1,%2,%3};"
        : "+f"(c[0]), "+f"(c[1]), "+f"(c[2]), "+f"(c[3])
        : "r"(a[0]), "r"(a[1]), "r"(a[2]), "r"(a[3]), "r"(b[0]), "r"(b[1]));
}
__device__ __forceinline__ void mma_f16(float c[4], const uint32_t a[4], const uint32_t* b) {
    asm volatile("mma.sync.aligned.m16n8k16.row.col.f32.f16.f16.f32 "
        "{%0,%1,%2,%3}, {%4,%5,%6,%7}, {%8,%9}, {%0,%1,%2,%3};"
        : "+f"(c[0]), "+f"(c[1]), "+f"(c[2]), "+f"(c[3])
        : "r"(a[0]), "r"(a[1]), "r"(a[2]), "r"(a[3]), "r"(b[0]), "r"(b[1]));
}
__device__ __forceinline__ void split2(float x, float y, uint32_t& hi, uint32_t& lo) {
    __nv_bfloat16 hx = __float2bfloat16(x), hy = __float2bfloat16(y);
    __nv_bfloat162 h2; h2.x = hx; h2.y = hy;
    __nv_bfloat162 l2;
    l2.x = __float2bfloat16(x - __bfloat162float(hx));
    l2.y = __float2bfloat16(y - __bfloat162float(hy));
    hi = *reinterpret_cast<uint32_t*>(&h2);
    lo = *reinterpret_cast<uint32_t*>(&l2);
}
__device__ __forceinline__ void split2h(float x, float y, uint32_t& hi, uint32_t& lo) {
    __half2 h = __floats2half2_rn(x, y);
    __half2 l = __floats2half2_rn(x - __half2float(h.x), y - __half2float(h.y));
    hi = *reinterpret_cast<uint32_t*>(&h);
    lo = *reinterpret_cast<uint32_t*>(&l);
}
__device__ __forceinline__ uint32_t pack_h2(float x, float y) {
    __half2 h = __floats2half2_rn(x, y);
    return *reinterpret_cast<uint32_t*>(&h);
}
__device__ __forceinline__ float ex2f(float x) {
    float y; asm("ex2.approx.f32 %0, %1;" : "=f"(y) : "f"(x)); return y;
}
__device__ __forceinline__ void cp16(uint32_t dst, const void* src) {
    asm volatile("cp.async.cg.shared.global [%0], [%1], 16;" :: "r"(dst), "l"(src));
}
#define CP_COMMIT() asm volatile("cp.async.commit_group;" ::: "memory")
#define CP_WAIT0()  asm volatile("cp.async.wait_group 0;" ::: "memory")

// ---------------- elementwise ----------------
// fused hi/lo split of x, W_qkv, W_proj in ONE launch (2 elems per thread)
#define XS_PAIRS 3145728
#define WQ_PAIRS 589824
#define WP_PAIRS 294912
__global__ void split_all_kernel(const float* __restrict__ x,
                                 const float* __restrict__ Wq,
                                 const float* __restrict__ Wp) {
    int i = blockIdx.x * 256 + threadIdx.x;
    const float* src;
    __nv_bfloat16 *h, *l;
    int off;
    if (i < XS_PAIRS) {
        src = x; h = g_xh; l = g_xl; off = i;
    } else if (i < XS_PAIRS + WQ_PAIRS) {
        src = Wq; h = g_wqh; l = g_wql; off = i - XS_PAIRS;
    } else if (i < XS_PAIRS + WQ_PAIRS + WP_PAIRS) {
        src = Wp; h = g_wph; l = g_wpl; off = i - XS_PAIRS - WQ_PAIRS;
    } else return;
    float2 v = ((const float2*)src)[off];
    uint32_t hh, ll;
    split2(v.x, v.y, hh, ll);
    ((uint32_t*)h)[off] = hh;
    ((uint32_t*)l)[off] = ll;
}

// k2 init with mu computed inline from partials (same fixed 8-term order as the
// old mu_fin kernel -> identical value). One thread per head also publishes g_mu.
__global__ void k2_init_kernel() {
    size_t i2 = (size_t)blockIdx.x * 256 + threadIdx.x;
    if (i2 >= KV_ELEMS / 2) return;
    size_t i = i2 * 2;
    int bh = (int)(i / ((size_t)N_ * HD_));
    float psum = 0.f;
    #pragma unroll
    for (int q = 0; q < 8; q++) psum += g_mu_part[bh * 8 + q];
    float mu = ((float)N_ * (float)C_ / 4.0f) / psum;
    if ((i % ((size_t)N_ * HD_)) == 0) g_mu[bh] = mu;
    float lm = LAMBD_ * mu;
    float2 kk = *(const float2*)&g_k[i];
    float s0 = (kk.x >= lm) ? (kk.x - lm) : ((kk.x <= -lm) ? (kk.x + lm) : 0.f);
    float s1 = (kk.y >= lm) ? (kk.y - lm) : ((kk.y <= -lm) ? (kk.y + lm) : 0.f);
    *(float2*)&g_s[i] = make_float2(s0, s1);
    *(float2*)&g_y[i] = make_float2(0.f, 0.f);
    uint32_t hh, ll;
    split2((kk.x - s0) * QSC_, (kk.y - s1) * QSC_, hh, ll);
    *(uint32_t*)&g_k2h_a[i] = hh;
    *(uint32_t*)&g_k2l_a[i] = ll;
}

__global__ void mu_part_kernel() {
    __shared__ float red[256];
    int bh = blockIdx.x >> 3;
    int sl = blockIdx.x & 7;
    const float* p = g_k + (size_t)bh * N_ * HD_ + sl * 8192;
    float s = 0.f;
    #pragma unroll
    for (int i = 0; i < 32; i++) s += fabsf(p[threadIdx.x + i * 256]);
    red[threadIdx.x] = s;
    __syncthreads();
    for (int st = 128; st > 0; st >>= 1) {
        if (threadIdx.x < st) red[threadIdx.x] += red[threadIdx.x + st];
        __syncthreads();
    }
    if (threadIdx.x == 0) g_mu_part[blockIdx.x] = red[0];
}

// =================== flash iteration (iters 0..4) + fused y/s/k2 update ===================
// KV tiles of 64 rows, stage = {Bh, Bl, Vh} -> smem 92.2KB -> 2 CTAs/SM.
#define FSPAD 72
#define FA_H  0
#define FA_L  9216
#define FSTG0 18432
#define FSTGS_I 13824
#define FSTGS_F 18432
#define FS_BH 0
#define FS_BL 4608
#define FS_VH 9216
#define FS_VL 13824
#define FA_BL 9216       // final pass A (128-row B tiles): Bl offset

__global__ void __launch_bounds__(256, 2) flash_iter_kernel(
    const __nv_bfloat16* __restrict__ k2h_src, const __nv_bfloat16* __restrict__ k2l_src,
    __nv_bfloat16* __restrict__ k2h_dst, __nv_bfloat16* __restrict__ k2l_dst)
{
    extern __shared__ __nv_bfloat16 fsm[];
    const int bh = blockIdx.y;
    const int i0 = blockIdx.x * 128;
    const int tid = threadIdx.x, wid = tid >> 5, lane = tid & 31;

    const size_t hbase = (size_t)bh * N_ * HD_;
    const __nv_bfloat16* Gh = k2h_src + hbase;
    const __nv_bfloat16* Gl = k2l_src + hbase;
    const __half* Vh = g_vh + hbase;
    const float mu = g_mu[bh];

    #pragma unroll
    for (int i = 0; i < 8; i++) {
        int idx = tid + i * 256;
        int arr = idx >> 10, rem = idx & 1023, row = rem >> 3, c = rem & 7;
        const __nv_bfloat16* src = (arr ? Gl : Gh) + (size_t)(i0 + row) * HD_ + c * 8;
        *(uint4*)(fsm + (arr ? FA_L : FA_H) + row * FSPAD + c * 8) = *(const uint4*)src;
    }

    auto cp_tile = [&](int stage, int j) {
        int sbase = FSTG0 + stage * FSTGS_I;
        #pragma unroll
        for (int i = 0; i < 6; i++) {
            int idx = tid + i * 256;
            int arr = idx >> 9, rem = idx & 511, row = rem >> 3, c = rem & 7;
            const void* src;
            int off;
            if      (arr == 0) { src = Gh + (size_t)(j * 64 + row) * HD_ + c * 8; off = FS_BH; }
            else if (arr == 1) { src = Gl + (size_t)(j * 64 + row) * HD_ + c * 8; off = FS_BL; }
            else               { src = Vh + (size_t)(j * 64 + row) * HD_ + c * 8; off = FS_VH; }
            cp16(smem_u32(fsm + sbase + off + row * FSPAD + c * 8), src);
        }
    };

    cp_tile(0, 0);
    CP_COMMIT(); CP_WAIT0();
    __syncthreads();

    float m0 = -1e30f, m1 = -1e30f, l0 = 0.f, l1 = 0.f;
    float acco[8][4] = {};

    for (int j = 0; j < 16; j++) {
        if (j < 15) { cp_tile((j + 1) & 1, j + 1); CP_COMMIT(); }
        const __nv_bfloat16* sb = fsm + FSTG0 + (j & 1) * FSTGS_I;

        float accs[8][4] = {};
        #pragma unroll
        for (int ks = 0; ks < 4; ks++) {
            uint32_t aH[4], aL[4];
            {
                int ar = wid * 16 + (lane & 15);
                int ac = ks * 16 + ((lane >> 4) << 3);
                ldsm4(aH, smem_u32(fsm + FA_H + ar * FSPAD + ac));
                ldsm4(aL, smem_u32(fsm + FA_L + ar * FSPAD + ac));
            }
            #pragma unroll
            for (int ng = 0; ng < 2; ng++) {
                uint32_t bh2[2][4], bl2[2][4];
                #pragma unroll
                for (int p = 0; p < 2; p++) {
                    int nr = ng * 32 + p * 16 + (lane & 7) + ((lane >> 4) << 3);
                    int kc = ks * 16 + (((lane >> 3) & 1) << 3);
                    ldsm4(bh2[p], smem_u32(sb + FS_BH + nr * FSPAD + kc));
                    ldsm4(bl2[p], smem_u32(sb + FS_BL + nr * FSPAD + kc));
                }
                #pragma unroll
                for (int t = 0; t < 4; t++) {
                    float* c = accs[ng * 4 + t];
                    const uint32_t* bhf = &bh2[t >> 1][(t & 1) * 2];
                    const uint32_t* blf = &bl2[t >> 1][(t & 1) * 2];
                    mma_bf16(c, aH, bhf);
                    mma_bf16(c, aH, blf);
                    mma_bf16(c, aL, bhf);
                }
            }
        }

        float tm0 = -1e30f, tm1 = -1e30f;
        #pragma unroll
        for (int t = 0; t < 8; t++) {
            tm0 = fmaxf(tm0, fmaxf(accs[t][0], accs[t][1]));
            tm1 = fmaxf(tm1, fmaxf(accs[t][2], accs[t][3]));
        }
        tm0 = fmaxf(tm0, __shfl_xor_sync(0xFFFFFFFF, tm0, 1));
        tm0 = fmaxf(tm0, __shfl_xor_sync(0xFFFFFFFF, tm0, 2));
        tm1 = fmaxf(tm1, __shfl_xor_sync(0xFFFFFFFF, tm1, 1));
        tm1 = fmaxf(tm1, __shfl_xor_sync(0xFFFFFFFF, tm1, 2));
        float mn0 = fmaxf(m0, tm0), mn1 = fmaxf(m1, tm1);
        float sc0 = ex2f(m0 - mn0), sc1 = ex2f(m1 - mn1);
        m0 = mn0; m1 = mn1;
        float rs0 = 0.f, rs1 = 0.f;
        #pragma unroll
        for (int t = 0; t < 8; t++) {
            accs[t][0] = ex2f(accs[t][0] - m0);
            accs[t][1] = ex2f(accs[t][1] - m0);
            accs[t][2] = ex2f(accs[t][2] - m1);
            accs[t][3] = ex2f(accs[t][3] - m1);
            rs0 += accs[t][0] + accs[t][1];
            rs1 += accs[t][2] + accs[t][3];
        }
        rs0 += __shfl_xor_sync(0xFFFFFFFF, rs0, 1);
        rs0 += __shfl_xor_sync(0xFFFFFFFF, rs0, 2);
        rs1 += __shfl_xor_sync(0xFFFFFFFF, rs1, 1);
        rs1 += __shfl_xor_sync(0xFFFFFFFF, rs1, 2);
        l0 = l0 * sc0 + rs0;
        l1 = l1 * sc1 + rs1;
        #pragma unroll
        for (int o = 0; o < 8; o++) {
            acco[o][0] *= sc0; acco[o][1] *= sc0;
            acco[o][2] *= sc1; acco[o][3] *= sc1;
        }

        // PV: P fp16 x Vh (single product)
        #pragma unroll
        for (int kt = 0; kt < 4; kt++) {
            uint32_t pH[4];
            pH[0] = pack_h2(accs[2*kt][0],   accs[2*kt][1]);
            pH[1] = pack_h2(accs[2*kt][2],   accs[2*kt][3]);
            pH[2] = pack_h2(accs[2*kt+1][0], accs[2*kt+1][1]);
            pH[3] = pack_h2(accs[2*kt+1][2], accs[2*kt+1][3]);
            #pragma unroll
            for (int vg = 0; vg < 2; vg++) {
                uint32_t vh2[2][4];
                #pragma unroll
                for (int q = 0; q < 2; q++) {
                    int vr = kt * 16 + (lane & 15);
                    int vc = vg * 32 + q * 16 + ((lane >> 4) << 3);
                    ldsm4t(vh2[q], smem_u32(sb + FS_VH + vr * FSPAD + vc));
                }
                #pragma unroll
                for (int t = 0; t < 4; t++)
                    mma_f16(acco[vg * 4 + t], pH, &vh2[t >> 1][(t & 1) * 2]);
            }
        }

        if (j < 15) CP_WAIT0();
        __syncthreads();
    }

    float inv0 = 1.f / l0, inv1 = 1.f / l1;
    float imu = 1.f / mu;
    float lm = LAMBD_ * mu;
    int row0 = i0 + wid * 16 + (lane >> 2);
    #pragma unroll
    for (int o = 0; o < 8; o++) {
        int col = o * 8 + (lane & 3) * 2;
        #pragma unroll
        for (int half = 0; half < 2; half++) {
            size_t ia = hbase + (size_t)(row0 + half * 8) * HD_ + col;
            float la = acco[o][half * 2]     * (half ? inv1 : inv0);
            float lb = acco[o][half * 2 + 1] * (half ? inv1 : inv0);
            float2 kv = *(const float2*)&g_k[ia];
            float2 yv = *(const float2*)&g_y[ia];
            float2 sv = *(const float2*)&g_s[ia];
            float yn0 = yv.x + mu * (kv.x - la - sv.x);
            float yn1 = yv.y + mu * (kv.y - lb - sv.y);
            float ym0 = yn0 * imu, ym1 = yn1 * imu;
            float t0 = kv.x - la + ym0, t1 = kv.y - lb + ym1;
            float sn0 = (t0 >= lm) ? (t0 - lm) : ((t0 <= -lm) ? (t0 + lm) : 0.f);
            float sn1 = (t1 >= lm) ? (t1 - lm) : ((t1 <= -lm) ? (t1 + lm) : 0.f);
            *(float2*)&g_y[ia] = make_float2(yn0, yn1);
            *(float2*)&g_s[ia] = make_float2(sn0, sn1);
            float k20 = (kv.x - sn0 - ym0) * QSC_;
            float k21 = (kv.y - sn1 - ym1) * QSC_;
            uint32_t h2, l2;
            split2(k20, k21, h2, l2);
            *(uint32_t*)&k2h_dst[ia] = h2;
            *(uint32_t*)&k2l_dst[ia] = l2;
        }
    }
}

// =================== final iteration: 2-pass flash, materializes attn + obnc ===================
__global__ void __launch_bounds__(256, 2) final_flash_kernel(
    float* __restrict__ attn,
    const __nv_bfloat16* __restrict__ k2h_src, const __nv_bfloat16* __restrict__ k2l_src)
{
    extern __shared__ __nv_bfloat16 fsm[];
    const int bh = blockIdx.y;
    const int i0 = blockIdx.x * 128;
    const int tid = threadIdx.x, wid = tid >> 5, lane = tid & 31;

    const size_t hbase = (size_t)bh * N_ * HD_;
    const __nv_bfloat16* Gh = k2h_src + hbase;
    const __nv_bfloat16* Gl = k2l_src + hbase;
    const __half* Vh = g_vh + hbase;
    const __half* Vl = g_vl + hbase;

    #pragma unroll
    for (int i = 0; i < 8; i++) {
        int idx = tid + i * 256;
        int arr = idx >> 10, rem = idx & 1023, row = rem >> 3, c = rem & 7;
        const __nv_bfloat16* src = (arr ? Gl : Gh) + (size_t)(i0 + row) * HD_ + c * 8;
        *(uint4*)(fsm + (arr ? FA_L : FA_H) + row * FSPAD + c * 8) = *(const uint4*)src;
    }

    auto cp_tileA = [&](int stage, int j) {
        int sbase = FSTG0 + stage * FSTGS_F;
        #pragma unroll
        for (int i = 0; i < 8; i++) {
            int idx = tid + i * 256;
            int arr = idx >> 10, rem = idx & 1023, row = rem >> 3, c = rem & 7;
            const __nv_bfloat16* src = (arr ? Gl : Gh) + (size_t)(j * 128 + row) * HD_ + c * 8;
            cp16(smem_u32(fsm + sbase + (arr ? FA_BL : FS_BH) + row * FSPAD + c * 8), src);
        }
    };
    auto cp_tileB = [&](int stage, int j) {
        int sbase = FSTG0 + stage * FSTGS_F;
        #pragma unroll
        for (int i = 0; i < 8; i++) {
            int idx = tid + i * 256;
            int arr = idx >> 9, rem = idx & 511, row = rem >> 3, c = rem & 7;
            const void* src;
            int off;
            if      (arr == 0) { src = Gh + (size_t)(j * 64 + row) * HD_ + c * 8; off = FS_BH; }
            else if (arr == 1) { src = Gl + (size_t)(j * 64 + row) * HD_ + c * 8; off = FS_BL; }
            else if (arr == 2) { src = Vh + (size_t)(j * 64 + row) * HD_ + c * 8; off = FS_VH; }
            else               { src = Vl + (size_t)(j * 64 + row) * HD_ + c * 8; off = FS_VL; }
            cp16(smem_u32(fsm + sbase + off + row * FSPAD + c * 8), src);
        }
    };

    // ---------- PASS A: row stats over 128-wide tiles ----------
    cp_tileA(0, 0);
    CP_COMMIT(); CP_WAIT0();
    __syncthreads();

    float m0 = -1e30f, m1 = -1e30f, l0 = 0.f, l1 = 0.f;
    for (int j = 0; j < 8; j++) {
        if (j < 7) { cp_tileA((j + 1) & 1, j + 1); CP_COMMIT(); }
        const __nv_bfloat16* sb = fsm + FSTG0 + (j & 1) * FSTGS_F;
        float accs[16][4] = {};
        #pragma unroll
        for (int ks = 0; ks < 4; ks++) {
            uint32_t aH[4], aL[4];
            {
                int ar = wid * 16 + (lane & 15);
                int ac = ks * 16 + ((lane >> 4) << 3);
                ldsm4(aH, smem_u32(fsm + FA_H + ar * FSPAD + ac));
                ldsm4(aL, smem_u32(fsm + FA_L + ar * FSPAD + ac));
            }
            #pragma unroll
            for (int ng = 0; ng < 4; ng++) {
                uint32_t bh2[2][4], bl2[2][4];
                #pragma unroll
                for (int p = 0; p < 2; p++) {
                    int nr = ng * 32 + p * 16 + (lane & 7) + ((lane >> 4) << 3);
                    int kc = ks * 16 + (((lane >> 3) & 1) << 3);
                    ldsm4(bh2[p], smem_u32(sb + FS_BH + nr * FSPAD + kc));
                    ldsm4(bl2[p], smem_u32(sb + FA_BL + nr * FSPAD + kc));
                }
                #pragma unroll
                for (int t = 0; t < 4; t++) {
                    float* c = accs[ng * 4 + t];
                    const uint32_t* bhf = &bh2[t >> 1][(t & 1) * 2];
                    const uint32_t* blf = &bl2[t >> 1][(t & 1) * 2];
                    mma_bf16(c, aH, bhf);
                    mma_bf16(c, aH, blf);
                    mma_bf16(c, aL, bhf);
                }
            }
        }

        float tm0 = -1e30f, tm1 = -1e30f;
        #pragma unroll
        for (int t = 0; t < 16; t++) {
            tm0 = fmaxf(tm0, fmaxf(accs[t][0], accs[t][1]));
            tm1 = fmaxf(tm1, fmaxf(accs[t][2], accs[t][3]));
        }
        tm0 = fmaxf(tm0, __shfl_xor_sync(0xFFFFFFFF, tm0, 1));
        tm0 = fmaxf(tm0, __shfl_xor_sync(0xFFFFFFFF, tm0, 2));
        tm1 = fmaxf(tm1, __shfl_xor_sync(0xFFFFFFFF, tm1, 1));
        tm1 = fmaxf(tm1, __shfl_xor_sync(0xFFFFFFFF, tm1, 2));
        float mn0 = fmaxf(m0, tm0), mn1 = fmaxf(m1, tm1);
        float sc0 = ex2f(m0 - mn0), sc1 = ex2f(m1 - mn1);
        m0 = mn0; m1 = mn1;
        float rs0 = 0.f, rs1 = 0.f;
        #pragma unroll
        for (int t = 0; t < 16; t++) {
            rs0 += ex2f(accs[t][0] - m0) + ex2f(accs[t][1] - m0);
            rs1 += ex2f(accs[t][2] - m1) + ex2f(accs[t][3] - m1);
        }
        rs0 += __shfl_xor_sync(0xFFFFFFFF, rs0, 1);
        rs0 += __shfl_xor_sync(0xFFFFFFFF, rs0, 2);
        rs1 += __shfl_xor_sync(0xFFFFFFFF, rs1, 1);
        rs1 += __shfl_xor_sync(0xFFFFFFFF, rs1, 2);
        l0 = l0 * sc0 + rs0;
        l1 = l1 * sc1 + rs1;
        if (j < 7) CP_WAIT0();
        __syncthreads();
    }
    float inv0 = 1.f / l0, inv1 = 1.f / l1;

    // ---------- PASS B: normalized P -> attn, PV (64-wide tiles) ----------
    cp_tileB(0, 0);
    CP_COMMIT(); CP_WAIT0();
    __syncthreads();

    float* Sp = attn + (size_t)bh * N_ * N_;
    const int prow = i0 + wid * 16 + (lane >> 2);
    float acco[8][4] = {};

    for (int j = 0; j < 16; j++) {
        if (j < 15) { cp_tileB((j + 1) & 1, j + 1); CP_COMMIT(); }
        const __nv_bfloat16* sb = fsm + FSTG0 + (j & 1) * FSTGS_F;
        float accs[8][4] = {};
        #pragma unroll
        for (int ks = 0; ks < 4; ks++) {
            uint32_t aH[4], aL[4];
            {
                int ar = wid * 16 + (lane & 15);
                int ac = ks * 16 + ((lane >> 4) << 3);
                ldsm4(aH, smem_u32(fsm + FA_H + ar * FSPAD + ac));
                ldsm4(aL, smem_u32(fsm + FA_L + ar * FSPAD + ac));
            }
            #pragma unroll
            for (int ng = 0; ng < 2; ng++) {
                uint32_t bh2[2][4], bl2[2][4];
                #pragma unroll
                for (int p = 0; p < 2; p++) {
                    int nr = ng * 32 + p * 16 + (lane & 7) + ((lane >> 4) << 3);
                    int kc = ks * 16 + (((lane >> 3) & 1) << 3);
                    ldsm4(bh2[p], smem_u32(sb + FS_BH + nr * FSPAD + kc));
                    ldsm4(bl2[p], smem_u32(sb + FS_BL + nr * FSPAD + kc));
                }
                #pragma unroll
                for (int t = 0; t < 4; t++) {
                    float* c = accs[ng * 4 + t];
                    const uint32_t* bhf = &bh2[t >> 1][(t & 1) * 2];
                    const uint32_t* blf = &bl2[t >> 1][(t & 1) * 2];
                    mma_bf16(c, aH, bhf);
                    mma_bf16(c, aH, blf);
                    mma_bf16(c, aL, bhf);
                }
            }
        }

        #pragma unroll
        for (int t = 0; t < 8; t++) {
            accs[t][0] = ex2f(accs[t][0] - m0) * inv0;
            accs[t][1] = ex2f(accs[t][1] - m0) * inv0;
            accs[t][2] = ex2f(accs[t][2] - m1) * inv1;
            accs[t][3] = ex2f(accs[t][3] - m1) * inv1;
            int col = j * 64 + (t >> 2) * 32 + (t & 3) * 8 + (lane & 3) * 2;
            *(float2*)&Sp[(size_t)prow * N_ + col]       = make_float2(accs[t][0], accs[t][1]);
            *(float2*)&Sp[(size_t)(prow + 8) * N_ + col] = make_float2(accs[t][2], accs[t][3]);
        }

        #pragma unroll
        for (int kt = 0; kt < 4; kt++) {
            uint32_t pH[4];
            pH[0] = pack_h2(accs[2*kt][0],   accs[2*kt][1]);
            pH[1] = pack_h2(accs[2*kt][2],   accs[2*kt][3]);
            pH[2] = pack_h2(accs[2*kt+1][0], accs[2*kt+1][1]);
            pH[3] = pack_h2(accs[2*kt+1][2], accs[2*kt+1][3]);
            #pragma unroll
            for (int vg = 0; vg < 2; vg++) {
                uint32_t vh2[2][4], vl2[2][4];
                #pragma unroll
                for (int q = 0; q < 2; q++) {
                    int vr = kt * 16 + (lane & 15);
                    int vc = vg * 32 + q * 16 + ((lane >> 4) << 3);
                    ldsm4t(vh2[q], smem_u32(sb + FS_VH + vr * FSPAD + vc));
                    ldsm4t(vl2[q], smem_u32(sb + FS_VL + vr * FSPAD + vc));
                }
                #pragma unroll
                for (int t = 0; t < 4; t++) {
                    float* o = acco[vg * 4 + t];
                    mma_f16(o, pH, &vh2[t >> 1][(t & 1) * 2]);
                    mma_f16(o, pH, &vl2[t >> 1][(t & 1) * 2]);
                }
            }
        }

        if (j < 15) CP_WAIT0();
        __syncthreads();
    }

    int b = bh / H_, h = bh % H_;
    #pragma unroll
    for (int o = 0; o < 8; o++) {
        int col = o * 8 + (lane & 3) * 2;
        uint32_t h0, l0b, h1, l1b;
        split2(acco[o][0], acco[o][1], h0, l0b);
        split2(acco[o][2], acco[o][3], h1, l1b);
        size_t idx0 = ((size_t)(b * N_ + prow)) * C_ + h * HD_ + col;
        size_t idx1 = ((size_t)(b * N_ + prow + 8)) * C_ + h * HD_ + col;
        *(uint32_t*)&g_och[idx0] = h0;
        *(uint32_t*)&g_ocl[idx0] = l0b;
        *(uint32_t*)&g_och[idx1] = h1;
        *(uint32_t*)&g_ocl[idx1] = l1b;
    }
}

// =================== bf16x3 HMMA GEMM: qkv and proj ===================
#define QA_H 0
#define QA_L 9216
#define QB_H 18432
#define QB_L 23040
#define QSTG 27648
#define WPAD 72

template<int NCOLS, int KDIM>
__device__ __forceinline__ void mma_gemm_main(
    const __nv_bfloat16* __restrict__ Ah, const __nv_bfloat16* __restrict__ Al,
    const __nv_bfloat16* __restrict__ Wh, const __nv_bfloat16* __restrict__ Wl,
    __nv_bfloat16* sm, int by, int bx, float acc[2][4][4])
{
    const int tid = threadIdx.x, wid = tid >> 5, lane = tid & 31;
    const int wm = wid & 3, wn = wid >> 2;

    auto cp_stage = [&](int stage, int k0) {
        int sb = stage * QSTG;
        #pragma unroll
        for (int i = 0; i < 8; i++) {
            int idx = tid + i * 256;
            int arr = idx >> 10, rem = idx & 1023, row = rem >> 3, c = rem & 7;
            const __nv_bfloat16* src = (arr ? Al : Ah) + (size_t)(by + row) * KDIM + k0 + c * 8;
            cp16(smem_u32(sm + sb + (arr ? QA_L : QA_H) + row * FSPAD + c * 8), src);
        }
        #pragma unroll
        for (int i = 0; i < 4; i++) {
            int idx = tid + i * 256;
            int arr = idx >> 9, rem = idx & 511, row = rem >> 3, c = rem & 7;
            const __nv_bfloat16* src = (arr ? Wl : Wh) + (size_t)(k0 + row) * NCOLS + bx + c * 8;
            cp16(smem_u32(sm + sb + (arr ? QB_L : QB_H) + row * WPAD + c * 8), src);
        }
    };

    cp_stage(0, 0);
    CP_COMMIT(); CP_WAIT0();
    __syncthreads();

    const int NCHUNK = KDIM / 64;
    for (int ch = 0; ch < NCHUNK; ch++) {
        if (ch < NCHUNK - 1) { cp_stage((ch + 1) & 1, (ch + 1) * 64); CP_COMMIT(); }
        __nv_bfloat16* sb = sm + (ch & 1) * QSTG;
        #pragma unroll
        for (int ks = 0; ks < 4; ks++) {
            uint32_t aH[2][4], aL[2][4];
            #pragma unroll
            for (int mt = 0; mt < 2; mt++) {
                int ar = wm * 32 + mt * 16 + (lane & 15);
                int ac = ks * 16 + ((lane >> 4) << 3);
                ldsm4(aH[mt], smem_u32(sb + QA_H + ar * FSPAD + ac));
                ldsm4(aL[mt], smem_u32(sb + QA_L + ar * FSPAD + ac));
            }
            uint32_t bh2[2][4], bl2[2][4];
            #pragma unroll
            for (int q = 0; q < 2; q++) {
                int vr = ks * 16 + (lane & 15);
                int vc = wn * 32 + q * 16 + ((lane >> 4) << 3);
                ldsm4t(bh2[q], smem_u32(sb + QB_H + vr * WPAD + vc));
                ldsm4t(bl2[q], smem_u32(sb + QB_L + vr * WPAD + vc));
            }
            #pragma unroll
            for (int mt = 0; mt < 2; mt++)
                #pragma unroll
                for (int nt = 0; nt < 4; nt++) {
                    const uint32_t* bhf = &bh2[nt >> 1][(nt & 1) * 2];
                    const uint32_t* blf = &bl2[nt >> 1][(nt & 1) * 2];
                    mma_bf16(acc[mt][nt], aH[mt], bhf);
                    mma_bf16(acc[mt][nt], aH[mt], blf);
                    mma_bf16(acc[mt][nt], aL[mt], bhf);
                }
        }
        if (ch < NCHUNK - 1) CP_WAIT0();
        __syncthreads();
    }
}

__global__ void __launch_bounds__(256, 2) qkv_mma_kernel(const float* __restrict__ bias) {
    extern __shared__ __nv_bfloat16 qsm[];
    const int bx = blockIdx.x * 64;
    const int by = blockIdx.y * 128;
    const int wid = threadIdx.x >> 5, lane = threadIdx.x & 31;
    const int wm = wid & 3, wn = wid >> 2;

    float acc[2][4][4] = {};
    mma_gemm_main<TWO_C_, C_>(g_xh, g_xl, g_wqh, g_wql, qsm, by, bx, acc);

    #pragma unroll
    for (int mt = 0; mt < 2; mt++) {
        int r0 = by + wm * 32 + mt * 16 + (lane >> 2);
        #pragma unroll
        for (int nt = 0; nt < 4; nt++) {
            int col = bx + wn * 32 + nt * 8 + (lane & 3) * 2;
            float b0 = bias[col], b1 = bias[col + 1];
            #pragma unroll
            for (int half = 0; half < 2; half++) {
                int r = r0 + half * 8;
                float v0 = acc[mt][nt][half * 2]     + b0;
                float v1 = acc[mt][nt][half * 2 + 1] + b1;
                int bb = r >> 10, n = r & 1023;
                int which = col >= C_;
                int cc = col - which * C_;
                int hh = cc / HD_, hd = cc % HD_;
                size_t idx = (((size_t)(bb * H_ + hh)) * N_ + n) * HD_ + hd;
                if (!which) {
                    *(float2*)&g_k[idx] = make_float2(v0, v1);
                } else {
                    uint32_t h2, l2;
                    split2h(v0, v1, h2, l2);
                    *(uint32_t*)&g_vh[idx] = h2;
                    *(uint32_t*)&g_vl[idx] = l2;
                }
            }
        }
    }
}

__global__ void __launch_bounds__(256, 2) proj_mma_kernel(const float* __restrict__ bias,
                                                          float* __restrict__ out) {
    extern __shared__ __nv_bfloat16 qsm[];
    const int bx = blockIdx.x * 64;
    const int by = blockIdx.y * 128;
    const int wid = threadIdx.x >> 5, lane = threadIdx.x & 31;
    const int wm = wid & 3, wn = wid >> 2;

    float acc[2][4][4] = {};
    mma_gemm_main<C_, C_>(g_och, g_ocl, g_wph, g_wpl, qsm, by, bx, acc);

    #pragma unroll
    for (int mt = 0; mt < 2; mt++) {
        int r0 = by + wm * 32 + mt * 16 + (lane >> 2);
        #pragma unroll
        for (int nt = 0; nt < 4; nt++) {
            int col = bx + wn * 32 + nt * 8 + (lane & 3) * 2;
            float b0 = bias[col], b1 = bias[col + 1];
            *(float2*)&out[(size_t)r0 * C_ + col] =
                make_float2(acc[mt][nt][0] + b0, acc[mt][nt][1] + b1);
            *(float2*)&out[(size_t)(r0 + 8) * C_ + col] =
                make_float2(acc[mt][nt][2] + b0, acc[mt][nt][3] + b1);
        }
    }
}

// ---------------- launch ----------------
extern "C" void kernel_launch(void* const* d_in, const int* in_sizes, int n_in,
                              void* d_out, int out_size) {
    const float* x     = (const float*)d_in[0];
    const float* Wqkv  = (const float*)d_in[1];
    const float* bqkv  = (const float*)d_in[2];
    const float* Wproj = (const float*)d_in[3];
    const float* bproj = (const float*)d_in[4];
    float* out = (float*)d_out;

    float* attn;
    if ((size_t)out_size >= OUT_ELEMS + ATTN_ELEMS) {
        attn = out + OUT_ELEMS;
    } else {
        void* p = nullptr;
        cudaGetSymbolAddress(&p, g_attn_fallback);
        attn = (float*)p;
    }

    const int FLASH_SMEM_I = (FSTG0 + 2 * FSTGS_I) * 2;   // 92,160 B
    const int FLASH_SMEM_F = (FSTG0 + 2 * FSTGS_F) * 2;   // 110,592 B
    const int GEMM_SMEM    = 2 * QSTG * 2;                // 110,592 B
    cudaFuncSetAttribute(flash_iter_kernel, cudaFuncAttributeMaxDynamicSharedMemorySize, FLASH_SMEM_I);
    cudaFuncSetAttribute(final_flash_kernel, cudaFuncAttributeMaxDynamicSharedMemorySize, FLASH_SMEM_F);
    cudaFuncSetAttribute(qkv_mma_kernel, cudaFuncAttributeMaxDynamicSharedMemorySize, GEMM_SMEM);
    cudaFuncSetAttribute(proj_mma_kernel, cudaFuncAttributeMaxDynamicSharedMemorySize, GEMM_SMEM);

    __nv_bfloat16 *k2h_a, *k2l_a, *k2h_b, *k2l_b;
    { void* p; cudaGetSymbolAddress(&p, g_k2h_a); k2h_a = (__nv_bfloat16*)p; }
    { void* p; cudaGetSymbolAddress(&p, g_k2l_a); k2l_a = (__nv_bfloat16*)p; }
    { void* p; cudaGetSymbolAddress(&p, g_k2h_b); k2h_b = (__nv_bfloat16*)p; }
    { void* p; cudaGetSymbolAddress(&p, g_k2l_b); k2l_b = (__nv_bfloat16*)p; }

    const int TOTAL_PAIRS = XS_PAIRS + WQ_PAIRS + WP_PAIRS;
    split_all_kernel<<<(TOTAL_PAIRS + 255) / 256, 256>>>(x, Wqkv, Wproj);

    qkv_mma_kernel<<<dim3(TWO_C_ / 64, M_ROWS / 128), 256, GEMM_SMEM>>>(bqkv);
    mu_part_kernel<<<BH_ * 8, 256>>>();
    k2_init_kernel<<<(int)((KV_ELEMS / 2 + 255) / 256), 256>>>();   // computes mu inline, writes g_mu + buffer A

    __nv_bfloat16* bufs_h[2] = {k2h_a, k2h_b};
    __nv_bfloat16* bufs_l[2] = {k2l_a, k2l_b};
    for (int it = 0; it < 5; ++it) {
        int s = it & 1, d = (it + 1) & 1;
        flash_iter_kernel<<<dim3(N_ / 128, BH_), 256, FLASH_SMEM_I>>>(
            bufs_h[s], bufs_l[s], bufs_h[d], bufs_l[d]);
    }
    final_flash_kernel<<<dim3(N_ / 128, BH_), 256, FLASH_SMEM_F>>>(attn, bufs_h[1], bufs_l[1]);

    proj_mma_kernel<<<dim3(C_ / 64, M_ROWS / 128), 256, GEMM_SMEM>>>(bproj, out);
}

// round 16
// speedup vs baseline: 1.0206x; 1.0028x over previous
#include <cuda_runtime.h>
#include <cuda_bf16.h>
#include <cuda_fp16.h>
#include <math.h>
#include <stdint.h>

#define B_   8
#define N_   1024
#define C_   768
#define H_   12
#define HD_  64
#define BH_  (B_*H_)
#define TWO_C_ (2*C_)
#define M_ROWS (B_*N_)

static const size_t KV_ELEMS   = (size_t)BH_ * N_ * HD_;
static const size_t OUT_ELEMS  = (size_t)B_ * N_ * C_;
static const size_t ATTN_ELEMS = (size_t)BH_ * N_ * N_;

#define LAMBD_ 4.0f
// logits carried in log2 domain: S2 = (k2*QSC)·(k2*QSC)^T where QSC^2 = 0.125*log2(e)
#define QSC_ 0.42466089f

// ---------------- device scratch ----------------
__device__ float g_k [6291456];
__device__ float g_y [6291456];
__device__ float g_s [6291456];
__device__ __nv_bfloat16 g_k2h_a[6291456];
__device__ __nv_bfloat16 g_k2l_a[6291456];
__device__ __nv_bfloat16 g_k2h_b[6291456];
__device__ __nv_bfloat16 g_k2l_b[6291456];
__device__ __half g_vh [6291456];
__device__ __half g_vl [6291456];
__device__ __nv_bfloat16 g_xh [6291456];
__device__ __nv_bfloat16 g_xl [6291456];
__device__ __nv_bfloat16 g_wqh[1179648];
__device__ __nv_bfloat16 g_wql[1179648];
__device__ __nv_bfloat16 g_wph[589824];
__device__ __nv_bfloat16 g_wpl[589824];
__device__ __nv_bfloat16 g_och[6291456];
__device__ __nv_bfloat16 g_ocl[6291456];
__device__ float g_mu[96];
__device__ float g_mu_part[768];
__device__ float g_attn_fallback[100663296];

// ---------------- helpers ----------------
__device__ __forceinline__ uint32_t smem_u32(const void* p) {
    uint32_t a;
    asm("{ .reg .u64 t; cvta.to.shared.u64 t, %1; cvt.u32.u64 %0, t; }" : "=r"(a) : "l"(p));
    return a;
}
__device__ __forceinline__ void ldsm4(uint32_t r[4], uint32_t addr) {
    asm volatile("ldmatrix.sync.aligned.m8n8.x4.shared.b16 {%0,%1,%2,%3}, [%4];"
        : "=r"(r[0]), "=r"(r[1]), "=r"(r[2]), "=r"(r[3]) : "r"(addr));
}
__device__ __forceinline__ void ldsm4t(uint32_t r[4], uint32_t addr) {
    asm volatile("ldmatrix.sync.aligned.m8n8.x4.trans.shared.b16 {%0,%1,%2,%3}, [%4];"
        : "=r"(r[0]), "=r"(r[1]), "=r"(r[2]), "=r"(r[3]) : "r"(addr));
}
__device__ __forceinline__ void mma_bf16(float c[4], const uint32_t a[4], const uint32_t* b) {
    asm volatile("mma.sync.aligned.m16n8k16.row.col.f32.bf16.bf16.f32 "
        "{%0,%1,%2,%3}, {%4,%5,%6,%7}, {%8,%9}, {%0,%1,%2,%3};"
        : "+f"(c[0]), "+f"(c[1]), "+f"(c[2]), "+f"(c[3])
        : "r"(a[0]), "r"(a[1]), "r"(a[2]), "r"(a[3]), "r"(b[0]), "r"(b[1]));
}
__device__ __forceinline__ void mma_f16(float c[4], const uint32_t a[4], const uint32_t* b) {
    asm volatile("mma.sync.aligned.m16n8k16.row.col.f32.f16.f16.f32 "
        "{%0,%1,%2,%3}, {%4,%5,%6,%7}, {%8,%9}, {%0,%1,%2,%3};"
        : "+f"(c[0]), "+f"(c[1]), "+f"(c[2]), "+f"(c[3])
        : "r"(a[0]), "r"(a[1]), "r"(a[2]), "r"(a[3]), "r"(b[0]), "r"(b[1]));
}
__device__ __forceinline__ void split2(float x, float y, uint32_t& hi, uint32_t& lo) {
    __nv_bfloat16 hx = __float2bfloat16(x), hy = __float2bfloat16(y);
    __nv_bfloat162 h2; h2.x = hx; h2.y = hy;
    __nv_bfloat162 l2;
    l2.x = __float2bfloat16(x - __bfloat162float(hx));
    l2.y = __float2bfloat16(y - __bfloat162float(hy));
    hi = *reinterpret_cast<uint32_t*>(&h2);
    lo = *reinterpret_cast<uint32_t*>(&l2);
}
__device__ __forceinline__ void split2h(float x, float y, uint32_t& hi, uint32_t& lo) {
    __half2 h = __floats2half2_rn(x, y);
    __half2 l = __floats2half2_rn(x - __half2float(h.x), y - __half2float(h.y));
    hi = *reinterpret_cast<uint32_t*>(&h);
    lo = *reinterpret_cast<uint32_t*>(&l);
}
__device__ __forceinline__ uint32_t pack_h2(float x, float y) {
    __half2 h = __floats2half2_rn(x, y);
    return *reinterpret_cast<uint32_t*>(&h);
}
__device__ __forceinline__ float ex2f(float x) {
    float y; asm("ex2.approx.f32 %0, %1;" : "=f"(y) : "f"(x)); return y;
}
__device__ __forceinline__ void cp16(uint32_t dst, const void* src) {
    asm volatile("cp.async.cg.shared.global [%0], [%1], 16;" :: "r"(dst), "l"(src));
}
// streaming (evict-first) store of a float2 — output-only data, keep out of L2
__device__ __forceinline__ void st_cs_f2(float* p, float a, float b) {
    asm volatile("st.global.cs.v2.f32 [%0], {%1, %2};" :: "l"(p), "f"(a), "f"(b) : "memory");
}
#define CP_COMMIT() asm volatile("cp.async.commit_group;" ::: "memory")
#define CP_WAIT0()  asm volatile("cp.async.wait_group 0;" ::: "memory")

// ---------------- elementwise ----------------
// fused hi/lo split of x, W_qkv, W_proj in ONE launch (2 elems per thread)
#define XS_PAIRS 3145728
#define WQ_PAIRS 589824
#define WP_PAIRS 294912
__global__ void split_all_kernel(const float* __restrict__ x,
                                 const float* __restrict__ Wq,
                                 const float* __restrict__ Wp) {
    int i = blockIdx.x * 256 + threadIdx.x;
    const float* src;
    __nv_bfloat16 *h, *l;
    int off;
    if (i < XS_PAIRS) {
        src = x; h = g_xh; l = g_xl; off = i;
    } else if (i < XS_PAIRS + WQ_PAIRS) {
        src = Wq; h = g_wqh; l = g_wql; off = i - XS_PAIRS;
    } else if (i < XS_PAIRS + WQ_PAIRS + WP_PAIRS) {
        src = Wp; h = g_wph; l = g_wpl; off = i - XS_PAIRS - WQ_PAIRS;
    } else return;
    float2 v = ((const float2*)src)[off];
    uint32_t hh, ll;
    split2(v.x, v.y, hh, ll);
    ((uint32_t*)h)[off] = hh;
    ((uint32_t*)l)[off] = ll;
}

// k2 init with mu computed inline from partials (same fixed 8-term order) ->
// identical value. One thread per head also publishes g_mu.
__global__ void k2_init_kernel() {
    size_t i2 = (size_t)blockIdx.x * 256 + threadIdx.x;
    if (i2 >= KV_ELEMS / 2) return;
    size_t i = i2 * 2;
    int bh = (int)(i / ((size_t)N_ * HD_));
    float psum = 0.f;
    #pragma unroll
    for (int q = 0; q < 8; q++) psum += g_mu_part[bh * 8 + q];
    float mu = ((float)N_ * (float)C_ / 4.0f) / psum;
    if ((i % ((size_t)N_ * HD_)) == 0) g_mu[bh] = mu;
    float lm = LAMBD_ * mu;
    float2 kk = *(const float2*)&g_k[i];
    float s0 = (kk.x >= lm) ? (kk.x - lm) : ((kk.x <= -lm) ? (kk.x + lm) : 0.f);
    float s1 = (kk.y >= lm) ? (kk.y - lm) : ((kk.y <= -lm) ? (kk.y + lm) : 0.f);
    *(float2*)&g_s[i] = make_float2(s0, s1);
    *(float2*)&g_y[i] = make_float2(0.f, 0.f);
    uint32_t hh, ll;
    split2((kk.x - s0) * QSC_, (kk.y - s1) * QSC_, hh, ll);
    *(uint32_t*)&g_k2h_a[i] = hh;
    *(uint32_t*)&g_k2l_a[i] = ll;
}

__global__ void mu_part_kernel() {
    __shared__ float red[256];
    int bh = blockIdx.x >> 3;
    int sl = blockIdx.x & 7;
    const float* p = g_k + (size_t)bh * N_ * HD_ + sl * 8192;
    float s = 0.f;
    #pragma unroll
    for (int i = 0; i < 32; i++) s += fabsf(p[threadIdx.x + i * 256]);
    red[threadIdx.x] = s;
    __syncthreads();
    for (int st = 128; st > 0; st >>= 1) {
        if (threadIdx.x < st) red[threadIdx.x] += red[threadIdx.x + st];
        __syncthreads();
    }
    if (threadIdx.x == 0) g_mu_part[blockIdx.x] = red[0];
}

// =================== flash iteration (iters 0..4) + fused y/s/k2 update ===================
// KV tiles of 64 rows, stage = {Bh, Bl, Vh} -> smem 92.2KB -> 2 CTAs/SM.
#define FSPAD 72
#define FA_H  0
#define FA_L  9216
#define FSTG0 18432
#define FSTGS_I 13824
#define FSTGS_F 18432
#define FS_BH 0
#define FS_BL 4608
#define FS_VH 9216
#define FS_VL 13824
#define FA_BL 9216       // final pass A (128-row B tiles): Bl offset

__global__ void __launch_bounds__(256, 2) flash_iter_kernel(
    const __nv_bfloat16* __restrict__ k2h_src, const __nv_bfloat16* __restrict__ k2l_src,
    __nv_bfloat16* __restrict__ k2h_dst, __nv_bfloat16* __restrict__ k2l_dst)
{
    extern __shared__ __nv_bfloat16 fsm[];
    const int bh = blockIdx.y;
    const int i0 = blockIdx.x * 128;
    const int tid = threadIdx.x, wid = tid >> 5, lane = tid & 31;

    const size_t hbase = (size_t)bh * N_ * HD_;
    const __nv_bfloat16* Gh = k2h_src + hbase;
    const __nv_bfloat16* Gl = k2l_src + hbase;
    const __half* Vh = g_vh + hbase;
    const float mu = g_mu[bh];

    #pragma unroll
    for (int i = 0; i < 8; i++) {
        int idx = tid + i * 256;
        int arr = idx >> 10, rem = idx & 1023, row = rem >> 3, c = rem & 7;
        const __nv_bfloat16* src = (arr ? Gl : Gh) + (size_t)(i0 + row) * HD_ + c * 8;
        *(uint4*)(fsm + (arr ? FA_L : FA_H) + row * FSPAD + c * 8) = *(const uint4*)src;
    }

    auto cp_tile = [&](int stage, int j) {
        int sbase = FSTG0 + stage * FSTGS_I;
        #pragma unroll
        for (int i = 0; i < 6; i++) {
            int idx = tid + i * 256;
            int arr = idx >> 9, rem = idx & 511, row = rem >> 3, c = rem & 7;
            const void* src;
            int off;
            if      (arr == 0) { src = Gh + (size_t)(j * 64 + row) * HD_ + c * 8; off = FS_BH; }
            else if (arr == 1) { src = Gl + (size_t)(j * 64 + row) * HD_ + c * 8; off = FS_BL; }
            else               { src = Vh + (size_t)(j * 64 + row) * HD_ + c * 8; off = FS_VH; }
            cp16(smem_u32(fsm + sbase + off + row * FSPAD + c * 8), src);
        }
    };

    cp_tile(0, 0);
    CP_COMMIT(); CP_WAIT0();
    __syncthreads();

    float m0 = -1e30f, m1 = -1e30f, l0 = 0.f, l1 = 0.f;
    float acco[8][4] = {};

    for (int j = 0; j < 16; j++) {
        if (j < 15) { cp_tile((j + 1) & 1, j + 1); CP_COMMIT(); }
        const __nv_bfloat16* sb = fsm + FSTG0 + (j & 1) * FSTGS_I;

        float accs[8][4] = {};
        #pragma unroll
        for (int ks = 0; ks < 4; ks++) {
            uint32_t aH[4], aL[4];
            {
                int ar = wid * 16 + (lane & 15);
                int ac = ks * 16 + ((lane >> 4) << 3);
                ldsm4(aH, smem_u32(fsm + FA_H + ar * FSPAD + ac));
                ldsm4(aL, smem_u32(fsm + FA_L + ar * FSPAD + ac));
            }
            #pragma unroll
            for (int ng = 0; ng < 2; ng++) {
                uint32_t bh2[2][4], bl2[2][4];
                #pragma unroll
                for (int p = 0; p < 2; p++) {
                    int nr = ng * 32 + p * 16 + (lane & 7) + ((lane >> 4) << 3);
                    int kc = ks * 16 + (((lane >> 3) & 1) << 3);
                    ldsm4(bh2[p], smem_u32(sb + FS_BH + nr * FSPAD + kc));
                    ldsm4(bl2[p], smem_u32(sb + FS_BL + nr * FSPAD + kc));
                }
                #pragma unroll
                for (int t = 0; t < 4; t++) {
                    float* c = accs[ng * 4 + t];
                    const uint32_t* bhf = &bh2[t >> 1][(t & 1) * 2];
                    const uint32_t* blf = &bl2[t >> 1][(t & 1) * 2];
                    mma_bf16(c, aH, bhf);
                    mma_bf16(c, aH, blf);
                    mma_bf16(c, aL, bhf);
                }
            }
        }

        float tm0 = -1e30f, tm1 = -1e30f;
        #pragma unroll
        for (int t = 0; t < 8; t++) {
            tm0 = fmaxf(tm0, fmaxf(accs[t][0], accs[t][1]));
            tm1 = fmaxf(tm1, fmaxf(accs[t][2], accs[t][3]));
        }
        tm0 = fmaxf(tm0, __shfl_xor_sync(0xFFFFFFFF, tm0, 1));
        tm0 = fmaxf(tm0, __shfl_xor_sync(0xFFFFFFFF, tm0, 2));
        tm1 = fmaxf(tm1, __shfl_xor_sync(0xFFFFFFFF, tm1, 1));
        tm1 = fmaxf(tm1, __shfl_xor_sync(0xFFFFFFFF, tm1, 2));
        float mn0 = fmaxf(m0, tm0), mn1 = fmaxf(m1, tm1);
        float sc0 = ex2f(m0 - mn0), sc1 = ex2f(m1 - mn1);
        m0 = mn0; m1 = mn1;
        float rs0 = 0.f, rs1 = 0.f;
        #pragma unroll
        for (int t = 0; t < 8; t++) {
            accs[t][0] = ex2f(accs[t][0] - m0);
            accs[t][1] = ex2f(accs[t][1] - m0);
            accs[t][2] = ex2f(accs[t][2] - m1);
            accs[t][3] = ex2f(accs[t][3] - m1);
            rs0 += accs[t][0] + accs[t][1];
            rs1 += accs[t][2] + accs[t][3];
        }
        rs0 += __shfl_xor_sync(0xFFFFFFFF, rs0, 1);
        rs0 += __shfl_xor_sync(0xFFFFFFFF, rs0, 2);
        rs1 += __shfl_xor_sync(0xFFFFFFFF, rs1, 1);
        rs1 += __shfl_xor_sync(0xFFFFFFFF, rs1, 2);
        l0 = l0 * sc0 + rs0;
        l1 = l1 * sc1 + rs1;
        #pragma unroll
        for (int o = 0; o < 8; o++) {
            acco[o][0] *= sc0; acco[o][1] *= sc0;
            acco[o][2] *= sc1; acco[o][3] *= sc1;
        }

        // PV: P fp16 x Vh (single product)
        #pragma unroll
        for (int kt = 0; kt < 4; kt++) {
            uint32_t pH[4];
            pH[0] = pack_h2(accs[2*kt][0],   accs[2*kt][1]);
            pH[1] = pack_h2(accs[2*kt][2],   accs[2*kt][3]);
            pH[2] = pack_h2(accs[2*kt+1][0], accs[2*kt+1][1]);
            pH[3] = pack_h2(accs[2*kt+1][2], accs[2*kt+1][3]);
            #pragma unroll
            for (int vg = 0; vg < 2; vg++) {
                uint32_t vh2[2][4];
                #pragma unroll
                for (int q = 0; q < 2; q++) {
                    int vr = kt * 16 + (lane & 15);
                    int vc = vg * 32 + q * 16 + ((lane >> 4) << 3);
                    ldsm4t(vh2[q], smem_u32(sb + FS_VH + vr * FSPAD + vc));
                }
                #pragma unroll
                for (int t = 0; t < 4; t++)
                    mma_f16(acco[vg * 4 + t], pH, &vh2[t >> 1][(t & 1) * 2]);
            }
        }

        if (j < 15) CP_WAIT0();
        __syncthreads();
    }

    float inv0 = 1.f / l0, inv1 = 1.f / l1;
    float imu = 1.f / mu;
    float lm = LAMBD_ * mu;
    int row0 = i0 + wid * 16 + (lane >> 2);
    #pragma unroll
    for (int o = 0; o < 8; o++) {
        int col = o * 8 + (lane & 3) * 2;
        #pragma unroll
        for (int half = 0; half < 2; half++) {
            size_t ia = hbase + (size_t)(row0 + half * 8) * HD_ + col;
            float la = acco[o][half * 2]     * (half ? inv1 : inv0);
            float lb = acco[o][half * 2 + 1] * (half ? inv1 : inv0);
            float2 kv = *(const float2*)&g_k[ia];
            float2 yv = *(const float2*)&g_y[ia];
            float2 sv = *(const float2*)&g_s[ia];
            float yn0 = yv.x + mu * (kv.x - la - sv.x);
            float yn1 = yv.y + mu * (kv.y - lb - sv.y);
            float ym0 = yn0 * imu, ym1 = yn1 * imu;
            float t0 = kv.x - la + ym0, t1 = kv.y - lb + ym1;
            float sn0 = (t0 >= lm) ? (t0 - lm) : ((t0 <= -lm) ? (t0 + lm) : 0.f);
            float sn1 = (t1 >= lm) ? (t1 - lm) : ((t1 <= -lm) ? (t1 + lm) : 0.f);
            *(float2*)&g_y[ia] = make_float2(yn0, yn1);
            *(float2*)&g_s[ia] = make_float2(sn0, sn1);
            float k20 = (kv.x - sn0 - ym0) * QSC_;
            float k21 = (kv.y - sn1 - ym1) * QSC_;
            uint32_t h2, l2;
            split2(k20, k21, h2, l2);
            *(uint32_t*)&k2h_dst[ia] = h2;
            *(uint32_t*)&k2l_dst[ia] = l2;
        }
    }
}

// =================== final iteration: 2-pass flash, materializes attn + obnc ===================
__global__ void __launch_bounds__(256, 2) final_flash_kernel(
    float* __restrict__ attn,
    const __nv_bfloat16* __restrict__ k2h_src, const __nv_bfloat16* __restrict__ k2l_src)
{
    extern __shared__ __nv_bfloat16 fsm[];
    const int bh = blockIdx.y;
    const int i0 = blockIdx.x * 128;
    const int tid = threadIdx.x, wid = tid >> 5, lane = tid & 31;

    const size_t hbase = (size_t)bh * N_ * HD_;
    const __nv_bfloat16* Gh = k2h_src + hbase;
    const __nv_bfloat16* Gl = k2l_src + hbase;
    const __half* Vh = g_vh + hbase;
    const __half* Vl = g_vl + hbase;

    #pragma unroll
    for (int i = 0; i < 8; i++) {
        int idx = tid + i * 256;
        int arr = idx >> 10, rem = idx & 1023, row = rem >> 3, c = rem & 7;
        const __nv_bfloat16* src = (arr ? Gl : Gh) + (size_t)(i0 + row) * HD_ + c * 8;
        *(uint4*)(fsm + (arr ? FA_L : FA_H) + row * FSPAD + c * 8) = *(const uint4*)src;
    }

    auto cp_tileA = [&](int stage, int j) {
        int sbase = FSTG0 + stage * FSTGS_F;
        #pragma unroll
        for (int i = 0; i < 8; i++) {
            int idx = tid + i * 256;
            int arr = idx >> 10, rem = idx & 1023, row = rem >> 3, c = rem & 7;
            const __nv_bfloat16* src = (arr ? Gl : Gh) + (size_t)(j * 128 + row) * HD_ + c * 8;
            cp16(smem_u32(fsm + sbase + (arr ? FA_BL : FS_BH) + row * FSPAD + c * 8), src);
        }
    };
    auto cp_tileB = [&](int stage, int j) {
        int sbase = FSTG0 + stage * FSTGS_F;
        #pragma unroll
        for (int i = 0; i < 8; i++) {
            int idx = tid + i * 256;
            int arr = idx >> 9, rem = idx & 511, row = rem >> 3, c = rem & 7;
            const void* src;
            int off;
            if      (arr == 0) { src = Gh + (size_t)(j * 64 + row) * HD_ + c * 8; off = FS_BH; }
            else if (arr == 1) { src = Gl + (size_t)(j * 64 + row) * HD_ + c * 8; off = FS_BL; }
            else if (arr == 2) { src = Vh + (size_t)(j * 64 + row) * HD_ + c * 8; off = FS_VH; }
            else               { src = Vl + (size_t)(j * 64 + row) * HD_ + c * 8; off = FS_VL; }
            cp16(smem_u32(fsm + sbase + off + row * FSPAD + c * 8), src);
        }
    };

    // ---------- PASS A: row stats over 128-wide tiles ----------
    cp_tileA(0, 0);
    CP_COMMIT(); CP_WAIT0();
    __syncthreads();

    float m0 = -1e30f, m1 = -1e30f, l0 = 0.f, l1 = 0.f;
    for (int j = 0; j < 8; j++) {
        if (j < 7) { cp_tileA((j + 1) & 1, j + 1); CP_COMMIT(); }
        const __nv_bfloat16* sb = fsm + FSTG0 + (j & 1) * FSTGS_F;
        float accs[16][4] = {};
        #pragma unroll
        for (int ks = 0; ks < 4; ks++) {
            uint32_t aH[4], aL[4];
            {
                int ar = wid * 16 + (lane & 15);
                int ac = ks * 16 + ((lane >> 4) << 3);
                ldsm4(aH, smem_u32(fsm + FA_H + ar * FSPAD + ac));
                ldsm4(aL, smem_u32(fsm + FA_L + ar * FSPAD + ac));
            }
            #pragma unroll
            for (int ng = 0; ng < 4; ng++) {
                uint32_t bh2[2][4], bl2[2][4];
                #pragma unroll
                for (int p = 0; p < 2; p++) {
                    int nr = ng * 32 + p * 16 + (lane & 7) + ((lane >> 4) << 3);
                    int kc = ks * 16 + (((lane >> 3) & 1) << 3);
                    ldsm4(bh2[p], smem_u32(sb + FS_BH + nr * FSPAD + kc));
                    ldsm4(bl2[p], smem_u32(sb + FA_BL + nr * FSPAD + kc));
                }
                #pragma unroll
                for (int t = 0; t < 4; t++) {
                    float* c = accs[ng * 4 + t];
                    const uint32_t* bhf = &bh2[t >> 1][(t & 1) * 2];
                    const uint32_t* blf = &bl2[t >> 1][(t & 1) * 2];
                    mma_bf16(c, aH, bhf);
                    mma_bf16(c, aH, blf);
                    mma_bf16(c, aL, bhf);
                }
            }
        }

        float tm0 = -1e30f, tm1 = -1e30f;
        #pragma unroll
        for (int t = 0; t < 16; t++) {
            tm0 = fmaxf(tm0, fmaxf(accs[t][0], accs[t][1]));
            tm1 = fmaxf(tm1, fmaxf(accs[t][2], accs[t][3]));
        }
        tm0 = fmaxf(tm0, __shfl_xor_sync(0xFFFFFFFF, tm0, 1));
        tm0 = fmaxf(tm0, __shfl_xor_sync(0xFFFFFFFF, tm0, 2));
        tm1 = fmaxf(tm1, __shfl_xor_sync(0xFFFFFFFF, tm1, 1));
        tm1 = fmaxf(tm1, __shfl_xor_sync(0xFFFFFFFF, tm1, 2));
        float mn0 = fmaxf(m0, tm0), mn1 = fmaxf(m1, tm1);
        float sc0 = ex2f(m0 - mn0), sc1 = ex2f(m1 - mn1);
        m0 = mn0; m1 = mn1;
        float rs0 = 0.f, rs1 = 0.f;
        #pragma unroll
        for (int t = 0; t < 16; t++) {
            rs0 += ex2f(accs[t][0] - m0) + ex2f(accs[t][1] - m0);
            rs1 += ex2f(accs[t][2] - m1) + ex2f(accs[t][3] - m1);
        }
        rs0 += __shfl_xor_sync(0xFFFFFFFF, rs0, 1);
        rs0 += __shfl_xor_sync(0xFFFFFFFF, rs0, 2);
        rs1 += __shfl_xor_sync(0xFFFFFFFF, rs1, 1);
        rs1 += __shfl_xor_sync(0xFFFFFFFF, rs1, 2);
        l0 = l0 * sc0 + rs0;
        l1 = l1 * sc1 + rs1;
        if (j < 7) CP_WAIT0();
        __syncthreads();
    }
    float inv0 = 1.f / l0, inv1 = 1.f / l1;

    // ---------- PASS B: normalized P -> attn (streaming stores), PV ----------
    cp_tileB(0, 0);
    CP_COMMIT(); CP_WAIT0();
    __syncthreads();

    float* Sp = attn + (size_t)bh * N_ * N_;
    const int prow = i0 + wid * 16 + (lane >> 2);
    float acco[8][4] = {};

    for (int j = 0; j < 16; j++) {
        if (j < 15) { cp_tileB((j + 1) & 1, j + 1); CP_COMMIT(); }
        const __nv_bfloat16* sb = fsm + FSTG0 + (j & 1) * FSTGS_F;
        float accs[8][4] = {};
        #pragma unroll
        for (int ks = 0; ks < 4; ks++) {
            uint32_t aH[4], aL[4];
            {
                int ar = wid * 16 + (lane & 15);
                int ac = ks * 16 + ((lane >> 4) << 3);
                ldsm4(aH, smem_u32(fsm + FA_H + ar * FSPAD + ac));
                ldsm4(aL, smem_u32(fsm + FA_L + ar * FSPAD + ac));
            }
            #pragma unroll
            for (int ng = 0; ng < 2; ng++) {
                uint32_t bh2[2][4], bl2[2][4];
                #pragma unroll
                for (int p = 0; p < 2; p++) {
                    int nr = ng * 32 + p * 16 + (lane & 7) + ((lane >> 4) << 3);
                    int kc = ks * 16 + (((lane >> 3) & 1) << 3);
                    ldsm4(bh2[p], smem_u32(sb + FS_BH + nr * FSPAD + kc));
                    ldsm4(bl2[p], smem_u32(sb + FS_BL + nr * FSPAD + kc));
                }
                #pragma unroll
                for (int t = 0; t < 4; t++) {
                    float* c = accs[ng * 4 + t];
                    const uint32_t* bhf = &bh2[t >> 1][(t & 1) * 2];
                    const uint32_t* blf = &bl2[t >> 1][(t & 1) * 2];
                    mma_bf16(c, aH, bhf);
                    mma_bf16(c, aH, blf);
                    mma_bf16(c, aL, bhf);
                }
            }
        }

        #pragma unroll
        for (int t = 0; t < 8; t++) {
            accs[t][0] = ex2f(accs[t][0] - m0) * inv0;
            accs[t][1] = ex2f(accs[t][1] - m0) * inv0;
            accs[t][2] = ex2f(accs[t][2] - m1) * inv1;
            accs[t][3] = ex2f(accs[t][3] - m1) * inv1;
            int col = j * 64 + (t >> 2) * 32 + (t & 3) * 8 + (lane & 3) * 2;
            st_cs_f2(&Sp[(size_t)prow * N_ + col],       accs[t][0], accs[t][1]);
            st_cs_f2(&Sp[(size_t)(prow + 8) * N_ + col], accs[t][2], accs[t][3]);
        }

        #pragma unroll
        for (int kt = 0; kt < 4; kt++) {
            uint32_t pH[4];
            pH[0] = pack_h2(accs[2*kt][0],   accs[2*kt][1]);
            pH[1] = pack_h2(accs[2*kt][2],   accs[2*kt][3]);
            pH[2] = pack_h2(accs[2*kt+1][0], accs[2*kt+1][1]);
            pH[3] = pack_h2(accs[2*kt+1][2], accs[2*kt+1][3]);
            #pragma unroll
            for (int vg = 0; vg < 2; vg++) {
                uint32_t vh2[2][4], vl2[2][4];
                #pragma unroll
                for (int q = 0; q < 2; q++) {
                    int vr = kt * 16 + (lane & 15);
                    int vc = vg * 32 + q * 16 + ((lane >> 4) << 3);
                    ldsm4t(vh2[q], smem_u32(sb + FS_VH + vr * FSPAD + vc));
                    ldsm4t(vl2[q], smem_u32(sb + FS_VL + vr * FSPAD + vc));
                }
                #pragma unroll
                for (int t = 0; t < 4; t++) {
                    float* o = acco[vg * 4 + t];
                    mma_f16(o, pH, &vh2[t >> 1][(t & 1) * 2]);
                    mma_f16(o, pH, &vl2[t >> 1][(t & 1) * 2]);
                }
            }
        }

        if (j < 15) CP_WAIT0();
        __syncthreads();
    }

    int b = bh / H_, h = bh % H_;
    #pragma unroll
    for (int o = 0; o < 8; o++) {
        int col = o * 8 + (lane & 3) * 2;
        uint32_t h0, l0b, h1, l1b;
        split2(acco[o][0], acco[o][1], h0, l0b);
        split2(acco[o][2], acco[o][3], h1, l1b);
        size_t idx0 = ((size_t)(b * N_ + prow)) * C_ + h * HD_ + col;
        size_t idx1 = ((size_t)(b * N_ + prow + 8)) * C_ + h * HD_ + col;
        *(uint32_t*)&g_och[idx0] = h0;
        *(uint32_t*)&g_ocl[idx0] = l0b;
        *(uint32_t*)&g_och[idx1] = h1;
        *(uint32_t*)&g_ocl[idx1] = l1b;
    }
}

// =================== bf16x3 HMMA GEMM: qkv and proj ===================
#define QA_H 0
#define QA_L 9216
#define QB_H 18432
#define QB_L 23040
#define QSTG 27648
#define WPAD 72

template<int NCOLS, int KDIM>
__device__ __forceinline__ void mma_gemm_main(
    const __nv_bfloat16* __restrict__ Ah, const __nv_bfloat16* __restrict__ Al,
    const __nv_bfloat16* __restrict__ Wh, const __nv_bfloat16* __restrict__ Wl,
    __nv_bfloat16* sm, int by, int bx, float acc[2][4][4])
{
    const int tid = threadIdx.x, wid = tid >> 5, lane = tid & 31;
    const int wm = wid & 3, wn = wid >> 2;

    auto cp_stage = [&](int stage, int k0) {
        int sb = stage * QSTG;
        #pragma unroll
        for (int i = 0; i < 8; i++) {
            int idx = tid + i * 256;
            int arr = idx >> 10, rem = idx & 1023, row = rem >> 3, c = rem & 7;
            const __nv_bfloat16* src = (arr ? Al : Ah) + (size_t)(by + row) * KDIM + k0 + c * 8;
            cp16(smem_u32(sm + sb + (arr ? QA_L : QA_H) + row * FSPAD + c * 8), src);
        }
        #pragma unroll
        for (int i = 0; i < 4; i++) {
            int idx = tid + i * 256;
            int arr = idx >> 9, rem = idx & 511, row = rem >> 3, c = rem & 7;
            const __nv_bfloat16* src = (arr ? Wl : Wh) + (size_t)(k0 + row) * NCOLS + bx + c * 8;
            cp16(smem_u32(sm + sb + (arr ? QB_L : QB_H) + row * WPAD + c * 8), src);
        }
    };

    cp_stage(0, 0);
    CP_COMMIT(); CP_WAIT0();
    __syncthreads();

    const int NCHUNK = KDIM / 64;
    for (int ch = 0; ch < NCHUNK; ch++) {
        if (ch < NCHUNK - 1) { cp_stage((ch + 1) & 1, (ch + 1) * 64); CP_COMMIT(); }
        __nv_bfloat16* sb = sm + (ch & 1) * QSTG;
        #pragma unroll
        for (int ks = 0; ks < 4; ks++) {
            uint32_t aH[2][4], aL[2][4];
            #pragma unroll
            for (int mt = 0; mt < 2; mt++) {
                int ar = wm * 32 + mt * 16 + (lane & 15);
                int ac = ks * 16 + ((lane >> 4) << 3);
                ldsm4(aH[mt], smem_u32(sb + QA_H + ar * FSPAD + ac));
                ldsm4(aL[mt], smem_u32(sb + QA_L + ar * FSPAD + ac));
            }
            uint32_t bh2[2][4], bl2[2][4];
            #pragma unroll
            for (int q = 0; q < 2; q++) {
                int vr = ks * 16 + (lane & 15);
                int vc = wn * 32 + q * 16 + ((lane >> 4) << 3);
                ldsm4t(bh2[q], smem_u32(sb + QB_H + vr * WPAD + vc));
                ldsm4t(bl2[q], smem_u32(sb + QB_L + vr * WPAD + vc));
            }
            #pragma unroll
            for (int mt = 0; mt < 2; mt++)
                #pragma unroll
                for (int nt = 0; nt < 4; nt++) {
                    const uint32_t* bhf = &bh2[nt >> 1][(nt & 1) * 2];
                    const uint32_t* blf = &bl2[nt >> 1][(nt & 1) * 2];
                    mma_bf16(acc[mt][nt], aH[mt], bhf);
                    mma_bf16(acc[mt][nt], aH[mt], blf);
                    mma_bf16(acc[mt][nt], aL[mt], bhf);
                }
        }
        if (ch < NCHUNK - 1) CP_WAIT0();
        __syncthreads();
    }
}

__global__ void __launch_bounds__(256, 2) qkv_mma_kernel(const float* __restrict__ bias) {
    extern __shared__ __nv_bfloat16 qsm[];
    const int bx = blockIdx.x * 64;
    const int by = blockIdx.y * 128;
    const int wid = threadIdx.x >> 5, lane = threadIdx.x & 31;
    const int wm = wid & 3, wn = wid >> 2;

    float acc[2][4][4] = {};
    mma_gemm_main<TWO_C_, C_>(g_xh, g_xl, g_wqh, g_wql, qsm, by, bx, acc);

    #pragma unroll
    for (int mt = 0; mt < 2; mt++) {
        int r0 = by + wm * 32 + mt * 16 + (lane >> 2);
        #pragma unroll
        for (int nt = 0; nt < 4; nt++) {
            int col = bx + wn * 32 + nt * 8 + (lane & 3) * 2;
            float b0 = bias[col], b1 = bias[col + 1];
            #pragma unroll
            for (int half = 0; half < 2; half++) {
                int r = r0 + half * 8;
                float v0 = acc[mt][nt][half * 2]     + b0;
                float v1 = acc[mt][nt][half * 2 + 1] + b1;
                int bb = r >> 10, n = r & 1023;
                int which = col >= C_;
                int cc = col - which * C_;
                int hh = cc / HD_, hd = cc % HD_;
                size_t idx = (((size_t)(bb * H_ + hh)) * N_ + n) * HD_ + hd;
                if (!which) {
                    *(float2*)&g_k[idx] = make_float2(v0, v1);
                } else {
                    uint32_t h2, l2;
                    split2h(v0, v1, h2, l2);
                    *(uint32_t*)&g_vh[idx] = h2;
                    *(uint32_t*)&g_vl[idx] = l2;
                }
            }
        }
    }
}

__global__ void __launch_bounds__(256, 2) proj_mma_kernel(const float* __restrict__ bias,
                                                          float* __restrict__ out) {
    extern __shared__ __nv_bfloat16 qsm[];
    const int bx = blockIdx.x * 64;
    const int by = blockIdx.y * 128;
    const int wid = threadIdx.x >> 5, lane = threadIdx.x & 31;
    const int wm = wid & 3, wn = wid >> 2;

    float acc[2][4][4] = {};
    mma_gemm_main<C_, C_>(g_och, g_ocl, g_wph, g_wpl, qsm, by, bx, acc);

    #pragma unroll
    for (int mt = 0; mt < 2; mt++) {
        int r0 = by + wm * 32 + mt * 16 + (lane >> 2);
        #pragma unroll
        for (int nt = 0; nt < 4; nt++) {
            int col = bx + wn * 32 + nt * 8 + (lane & 3) * 2;
            float b0 = bias[col], b1 = bias[col + 1];
            st_cs_f2(&out[(size_t)r0 * C_ + col],
                     acc[mt][nt][0] + b0, acc[mt][nt][1] + b1);
            st_cs_f2(&out[(size_t)(r0 + 8) * C_ + col],
                     acc[mt][nt][2] + b0, acc[mt][nt][3] + b1);
        }
    }
}

// ---------------- launch ----------------
extern "C" void kernel_launch(void* const* d_in, const int* in_sizes, int n_in,
                              void* d_out, int out_size) {
    const float* x     = (const float*)d_in[0];
    const float* Wqkv  = (const float*)d_in[1];
    const float* bqkv  = (const float*)d_in[2];
    const float* Wproj = (const float*)d_in[3];
    const float* bproj = (const float*)d_in[4];
    float* out = (float*)d_out;

    float* attn;
    if ((size_t)out_size >= OUT_ELEMS + ATTN_ELEMS) {
        attn = out + OUT_ELEMS;
    } else {
        void* p = nullptr;
        cudaGetSymbolAddress(&p, g_attn_fallback);
        attn = (float*)p;
    }

    const int FLASH_SMEM_I = (FSTG0 + 2 * FSTGS_I) * 2;   // 92,160 B
    const int FLASH_SMEM_F = (FSTG0 + 2 * FSTGS_F) * 2;   // 110,592 B
    const int GEMM_SMEM    = 2 * QSTG * 2;                // 110,592 B
    cudaFuncSetAttribute(flash_iter_kernel, cudaFuncAttributeMaxDynamicSharedMemorySize, FLASH_SMEM_I);
    cudaFuncSetAttribute(final_flash_kernel, cudaFuncAttributeMaxDynamicSharedMemorySize, FLASH_SMEM_F);
    cudaFuncSetAttribute(qkv_mma_kernel, cudaFuncAttributeMaxDynamicSharedMemorySize, GEMM_SMEM);
    cudaFuncSetAttribute(proj_mma_kernel, cudaFuncAttributeMaxDynamicSharedMemorySize, GEMM_SMEM);

    __nv_bfloat16 *k2h_a, *k2l_a, *k2h_b, *k2l_b;
    { void* p; cudaGetSymbolAddress(&p, g_k2h_a); k2h_a = (__nv_bfloat16*)p; }
    { void* p; cudaGetSymbolAddress(&p, g_k2l_a); k2l_a = (__nv_bfloat16*)p; }
    { void* p; cudaGetSymbolAddress(&p, g_k2h_b); k2h_b = (__nv_bfloat16*)p; }
    { void* p; cudaGetSymbolAddress(&p, g_k2l_b); k2l_b = (__nv_bfloat16*)p; }

    const int TOTAL_PAIRS = XS_PAIRS + WQ_PAIRS + WP_PAIRS;
    split_all_kernel<<<(TOTAL_PAIRS + 255) / 256, 256>>>(x, Wqkv, Wproj);

    qkv_mma_kernel<<<dim3(TWO_C_ / 64, M_ROWS / 128), 256, GEMM_SMEM>>>(bqkv);
    mu_part_kernel<<<BH_ * 8, 256>>>();
    k2_init_kernel<<<(int)((KV_ELEMS / 2 + 255) / 256), 256>>>();   // computes mu inline, writes g_mu + buffer A

    __nv_bfloat16* bufs_h[2] = {k2h_a, k2h_b};
    __nv_bfloat16* bufs_l[2] = {k2l_a, k2l_b};
    for (int it = 0; it < 5; ++it) {
        int s = it & 1, d = (it + 1) & 1;
        flash_iter_kernel<<<dim3(N_ / 128, BH_), 256, FLASH_SMEM_I>>>(
            bufs_h[s], bufs_l[s], bufs_h[d], bufs_l[d]);
    }
    final_flash_kernel<<<dim3(N_ / 128, BH_), 256, FLASH_SMEM_F>>>(attn, bufs_h[1], bufs_l[1]);

    proj_mma_kernel<<<dim3(C_ / 64, M_ROWS / 128), 256, GEMM_SMEM>>>(bproj, out);
}

// round 17
// speedup vs baseline: 1.0238x; 1.0032x over previous
#include <cuda_runtime.h>
#include <cuda_bf16.h>
#include <cuda_fp16.h>
#include <math.h>
#include <stdint.h>

#define B_   8
#define N_   1024
#define C_   768
#define H_   12
#define HD_  64
#define BH_  (B_*H_)
#define TWO_C_ (2*C_)
#define M_ROWS (B_*N_)

static const size_t KV_ELEMS   = (size_t)BH_ * N_ * HD_;
static const size_t OUT_ELEMS  = (size_t)B_ * N_ * C_;
static const size_t ATTN_ELEMS = (size_t)BH_ * N_ * N_;

#define LAMBD_ 4.0f
// logits carried in log2 domain: S2 = (k2*QSC)·(k2*QSC)^T where QSC^2 = 0.125*log2(e)
#define QSC_ 0.42466089f

// ---------------- device scratch ----------------
__device__ float g_k [6291456];
__device__ float g_y [6291456];
__device__ float g_s [6291456];
__device__ __nv_bfloat16 g_k2h_a[6291456];
__device__ __nv_bfloat16 g_k2l_a[6291456];
__device__ __nv_bfloat16 g_k2h_b[6291456];
__device__ __nv_bfloat16 g_k2l_b[6291456];
__device__ __half g_vh [6291456];
__device__ __half g_vl [6291456];
__device__ __nv_bfloat16 g_xh [6291456];
__device__ __nv_bfloat16 g_xl [6291456];
__device__ __nv_bfloat16 g_wqh[1179648];
__device__ __nv_bfloat16 g_wql[1179648];
__device__ __nv_bfloat16 g_wph[589824];
__device__ __nv_bfloat16 g_wpl[589824];
__device__ __nv_bfloat16 g_och[6291456];
__device__ __nv_bfloat16 g_ocl[6291456];
__device__ float g_mu[96];
__device__ float g_mu_part[768];
__device__ float g_attn_fallback[100663296];

// ---------------- helpers ----------------
__device__ __forceinline__ uint32_t smem_u32(const void* p) {
    uint32_t a;
    asm("{ .reg .u64 t; cvta.to.shared.u64 t, %1; cvt.u32.u64 %0, t; }" : "=r"(a) : "l"(p));
    return a;
}
__device__ __forceinline__ void ldsm4(uint32_t r[4], uint32_t addr) {
    asm volatile("ldmatrix.sync.aligned.m8n8.x4.shared.b16 {%0,%1,%2,%3}, [%4];"
        : "=r"(r[0]), "=r"(r[1]), "=r"(r[2]), "=r"(r[3]) : "r"(addr));
}
__device__ __forceinline__ void ldsm4t(uint32_t r[4], uint32_t addr) {
    asm volatile("ldmatrix.sync.aligned.m8n8.x4.trans.shared.b16 {%0,%1,%2,%3}, [%4];"
        : "=r"(r[0]), "=r"(r[1]), "=r"(r[2]), "=r"(r[3]) : "r"(addr));
}
__device__ __forceinline__ void mma_bf16(float c[4], const uint32_t a[4], const uint32_t* b) {
    asm volatile("mma.sync.aligned.m16n8k16.row.col.f32.bf16.bf16.f32 "
        "{%0,%1,%2,%3}, {%4,%5,%6,%7}, {%8,%9}, {%0,%1,%2,%3};"
        : "+f"(c[0]), "+f"(c[1]), "+f"(c[2]), "+f"(c[3])
        : "r"(a[0]), "r"(a[1]), "r"(a[2]), "r"(a[3]), "r"(b[0]), "r"(b[1]));
}
__device__ __forceinline__ void mma_f16(float c[4], const uint32_t a[4], const uint32_t* b) {
    asm volatile("mma.sync.aligned.m16n8k16.row.col.f32.f16.f16.f32 "
        "{%0,%1,%2,%3}, {%4,%5,%6,%7}, {%8,%9}, {%0,%1,%2,%3};"
        : "+f"(c[0]), "+f"(c[1]), "+f"(c[2]), "+f"(c[3])
        : "r"(a[0]), "r"(a[1]), "r"(a[2]), "r"(a[3]), "r"(b[0]), "r"(b[1]));
}
__device__ __forceinline__ void split2(float x, float y, uint32_t& hi, uint32_t& lo) {
    __nv_bfloat16 hx = __float2bfloat16(x), hy = __float2bfloat16(y);
    __nv_bfloat162 h2; h2.x = hx; h2.y = hy;
    __nv_bfloat162 l2;
    l2.x = __float2bfloat16(x - __bfloat162float(hx));
    l2.y = __float2bfloat16(y - __bfloat162float(hy));
    hi = *reinterpret_cast<uint32_t*>(&h2);
    lo = *reinterpret_cast<uint32_t*>(&l2);
}
__device__ __forceinline__ void split2h(float x, float y, uint32_t& hi, uint32_t& lo) {
    __half2 h = __floats2half2_rn(x, y);
    __half2 l = __floats2half2_rn(x - __half2float(h.x), y - __half2float(h.y));
    hi = *reinterpret_cast<uint32_t*>(&h);
    lo = *reinterpret_cast<uint32_t*>(&l);
}
__device__ __forceinline__ uint32_t pack_h2(float x, float y) {
    __half2 h = __floats2half2_rn(x, y);
    return *reinterpret_cast<uint32_t*>(&h);
}
__device__ __forceinline__ float ex2f(float x) {
    float y; asm("ex2.approx.f32 %0, %1;" : "=f"(y) : "f"(x)); return y;
}
__device__ __forceinline__ void cp16(uint32_t dst, const void* src) {
    asm volatile("cp.async.cg.shared.global [%0], [%1], 16;" :: "r"(dst), "l"(src));
}
// streaming (evict-first) store / load of a float2 — single-use data, keep out of L2
__device__ __forceinline__ void st_cs_f2(float* p, float a, float b) {
    asm volatile("st.global.cs.v2.f32 [%0], {%1, %2};" :: "l"(p), "f"(a), "f"(b) : "memory");
}
__device__ __forceinline__ float2 ld_cs_f2(const float* p) {
    float2 v;
    asm volatile("ld.global.cs.v2.f32 {%0, %1}, [%2];" : "=f"(v.x), "=f"(v.y) : "l"(p));
    return v;
}
#define CP_COMMIT() asm volatile("cp.async.commit_group;" ::: "memory")
#define CP_WAIT0()  asm volatile("cp.async.wait_group 0;" ::: "memory")

// ---------------- elementwise ----------------
// fused hi/lo split of x, W_qkv, W_proj in ONE launch (2 elems per thread)
#define XS_PAIRS 3145728
#define WQ_PAIRS 589824
#define WP_PAIRS 294912
__global__ void split_all_kernel(const float* __restrict__ x,
                                 const float* __restrict__ Wq,
                                 const float* __restrict__ Wp) {
    int i = blockIdx.x * 256 + threadIdx.x;
    const float* src;
    __nv_bfloat16 *h, *l;
    int off;
    if (i < XS_PAIRS) {
        src = x; h = g_xh; l = g_xl; off = i;
    } else if (i < XS_PAIRS + WQ_PAIRS) {
        src = Wq; h = g_wqh; l = g_wql; off = i - XS_PAIRS;
    } else if (i < XS_PAIRS + WQ_PAIRS + WP_PAIRS) {
        src = Wp; h = g_wph; l = g_wpl; off = i - XS_PAIRS - WQ_PAIRS;
    } else return;
    float2 v = ((const float2*)src)[off];
    uint32_t hh, ll;
    split2(v.x, v.y, hh, ll);
    ((uint32_t*)h)[off] = hh;
    ((uint32_t*)l)[off] = ll;
}

// k2 init with mu computed inline from partials (same fixed 8-term order) ->
// identical value. One thread per head also publishes g_mu.
__global__ void k2_init_kernel() {
    size_t i2 = (size_t)blockIdx.x * 256 + threadIdx.x;
    if (i2 >= KV_ELEMS / 2) return;
    size_t i = i2 * 2;
    int bh = (int)(i / ((size_t)N_ * HD_));
    float psum = 0.f;
    #pragma unroll
    for (int q = 0; q < 8; q++) psum += g_mu_part[bh * 8 + q];
    float mu = ((float)N_ * (float)C_ / 4.0f) / psum;
    if ((i % ((size_t)N_ * HD_)) == 0) g_mu[bh] = mu;
    float lm = LAMBD_ * mu;
    float2 kk = ld_cs_f2(&g_k[i]);
    float s0 = (kk.x >= lm) ? (kk.x - lm) : ((kk.x <= -lm) ? (kk.x + lm) : 0.f);
    float s1 = (kk.y >= lm) ? (kk.y - lm) : ((kk.y <= -lm) ? (kk.y + lm) : 0.f);
    st_cs_f2(&g_s[i], s0, s1);
    st_cs_f2(&g_y[i], 0.f, 0.f);
    uint32_t hh, ll;
    split2((kk.x - s0) * QSC_, (kk.y - s1) * QSC_, hh, ll);
    *(uint32_t*)&g_k2h_a[i] = hh;
    *(uint32_t*)&g_k2l_a[i] = ll;
}

__global__ void mu_part_kernel() {
    __shared__ float red[256];
    int bh = blockIdx.x >> 3;
    int sl = blockIdx.x & 7;
    const float* p = g_k + (size_t)bh * N_ * HD_ + sl * 8192;
    float s = 0.f;
    #pragma unroll
    for (int i = 0; i < 32; i++) s += fabsf(p[threadIdx.x + i * 256]);
    red[threadIdx.x] = s;
    __syncthreads();
    for (int st = 128; st > 0; st >>= 1) {
        if (threadIdx.x < st) red[threadIdx.x] += red[threadIdx.x + st];
        __syncthreads();
    }
    if (threadIdx.x == 0) g_mu_part[blockIdx.x] = red[0];
}

// =================== flash iteration (iters 0..4) + fused y/s/k2 update ===================
// KV tiles of 64 rows, stage = {Bh, Bl, Vh} -> smem 92.2KB -> 2 CTAs/SM.
#define FSPAD 72
#define FA_H  0
#define FA_L  9216
#define FSTG0 18432
#define FSTGS_I 13824
#define FSTGS_F 18432
#define FS_BH 0
#define FS_BL 4608
#define FS_VH 9216
#define FS_VL 13824
#define FA_BL 9216       // final pass A (128-row B tiles): Bl offset

__global__ void __launch_bounds__(256, 2) flash_iter_kernel(
    const __nv_bfloat16* __restrict__ k2h_src, const __nv_bfloat16* __restrict__ k2l_src,
    __nv_bfloat16* __restrict__ k2h_dst, __nv_bfloat16* __restrict__ k2l_dst)
{
    extern __shared__ __nv_bfloat16 fsm[];
    const int bh = blockIdx.y;
    const int i0 = blockIdx.x * 128;
    const int tid = threadIdx.x, wid = tid >> 5, lane = tid & 31;

    const size_t hbase = (size_t)bh * N_ * HD_;
    const __nv_bfloat16* Gh = k2h_src + hbase;
    const __nv_bfloat16* Gl = k2l_src + hbase;
    const __half* Vh = g_vh + hbase;
    const float mu = g_mu[bh];

    #pragma unroll
    for (int i = 0; i < 8; i++) {
        int idx = tid + i * 256;
        int arr = idx >> 10, rem = idx & 1023, row = rem >> 3, c = rem & 7;
        const __nv_bfloat16* src = (arr ? Gl : Gh) + (size_t)(i0 + row) * HD_ + c * 8;
        *(uint4*)(fsm + (arr ? FA_L : FA_H) + row * FSPAD + c * 8) = *(const uint4*)src;
    }

    auto cp_tile = [&](int stage, int j) {
        int sbase = FSTG0 + stage * FSTGS_I;
        #pragma unroll
        for (int i = 0; i < 6; i++) {
            int idx = tid + i * 256;
            int arr = idx >> 9, rem = idx & 511, row = rem >> 3, c = rem & 7;
            const void* src;
            int off;
            if      (arr == 0) { src = Gh + (size_t)(j * 64 + row) * HD_ + c * 8; off = FS_BH; }
            else if (arr == 1) { src = Gl + (size_t)(j * 64 + row) * HD_ + c * 8; off = FS_BL; }
            else               { src = Vh + (size_t)(j * 64 + row) * HD_ + c * 8; off = FS_VH; }
            cp16(smem_u32(fsm + sbase + off + row * FSPAD + c * 8), src);
        }
    };

    cp_tile(0, 0);
    CP_COMMIT(); CP_WAIT0();
    __syncthreads();

    float m0 = -1e30f, m1 = -1e30f, l0 = 0.f, l1 = 0.f;
    float acco[8][4] = {};

    for (int j = 0; j < 16; j++) {
        if (j < 15) { cp_tile((j + 1) & 1, j + 1); CP_COMMIT(); }
        const __nv_bfloat16* sb = fsm + FSTG0 + (j & 1) * FSTGS_I;

        float accs[8][4] = {};
        #pragma unroll
        for (int ks = 0; ks < 4; ks++) {
            uint32_t aH[4], aL[4];
            {
                int ar = wid * 16 + (lane & 15);
                int ac = ks * 16 + ((lane >> 4) << 3);
                ldsm4(aH, smem_u32(fsm + FA_H + ar * FSPAD + ac));
                ldsm4(aL, smem_u32(fsm + FA_L + ar * FSPAD + ac));
            }
            #pragma unroll
            for (int ng = 0; ng < 2; ng++) {
                uint32_t bh2[2][4], bl2[2][4];
                #pragma unroll
                for (int p = 0; p < 2; p++) {
                    int nr = ng * 32 + p * 16 + (lane & 7) + ((lane >> 4) << 3);
                    int kc = ks * 16 + (((lane >> 3) & 1) << 3);
                    ldsm4(bh2[p], smem_u32(sb + FS_BH + nr * FSPAD + kc));
                    ldsm4(bl2[p], smem_u32(sb + FS_BL + nr * FSPAD + kc));
                }
                #pragma unroll
                for (int t = 0; t < 4; t++) {
                    float* c = accs[ng * 4 + t];
                    const uint32_t* bhf = &bh2[t >> 1][(t & 1) * 2];
                    const uint32_t* blf = &bl2[t >> 1][(t & 1) * 2];
                    mma_bf16(c, aH, bhf);
                    mma_bf16(c, aH, blf);
                    mma_bf16(c, aL, bhf);
                }
            }
        }

        float tm0 = -1e30f, tm1 = -1e30f;
        #pragma unroll
        for (int t = 0; t < 8; t++) {
            tm0 = fmaxf(tm0, fmaxf(accs[t][0], accs[t][1]));
            tm1 = fmaxf(tm1, fmaxf(accs[t][2], accs[t][3]));
        }
        tm0 = fmaxf(tm0, __shfl_xor_sync(0xFFFFFFFF, tm0, 1));
        tm0 = fmaxf(tm0, __shfl_xor_sync(0xFFFFFFFF, tm0, 2));
        tm1 = fmaxf(tm1, __shfl_xor_sync(0xFFFFFFFF, tm1, 1));
        tm1 = fmaxf(tm1, __shfl_xor_sync(0xFFFFFFFF, tm1, 2));
        float mn0 = fmaxf(m0, tm0), mn1 = fmaxf(m1, tm1);
        float sc0 = ex2f(m0 - mn0), sc1 = ex2f(m1 - mn1);
        m0 = mn0; m1 = mn1;
        float rs0 = 0.f, rs1 = 0.f;
        #pragma unroll
        for (int t = 0; t < 8; t++) {
            accs[t][0] = ex2f(accs[t][0] - m0);
            accs[t][1] = ex2f(accs[t][1] - m0);
            accs[t][2] = ex2f(accs[t][2] - m1);
            accs[t][3] = ex2f(accs[t][3] - m1);
            rs0 += accs[t][0] + accs[t][1];
            rs1 += accs[t][2] + accs[t][3];
        }
        rs0 += __shfl_xor_sync(0xFFFFFFFF, rs0, 1);
        rs0 += __shfl_xor_sync(0xFFFFFFFF, rs0, 2);
        rs1 += __shfl_xor_sync(0xFFFFFFFF, rs1, 1);
        rs1 += __shfl_xor_sync(0xFFFFFFFF, rs1, 2);
        l0 = l0 * sc0 + rs0;
        l1 = l1 * sc1 + rs1;
        #pragma unroll
        for (int o = 0; o < 8; o++) {
            acco[o][0] *= sc0; acco[o][1] *= sc0;
            acco[o][2] *= sc1; acco[o][3] *= sc1;
        }

        // PV: P fp16 x Vh (single product)
        #pragma unroll
        for (int kt = 0; kt < 4; kt++) {
            uint32_t pH[4];
            pH[0] = pack_h2(accs[2*kt][0],   accs[2*kt][1]);
            pH[1] = pack_h2(accs[2*kt][2],   accs[2*kt][3]);
            pH[2] = pack_h2(accs[2*kt+1][0], accs[2*kt+1][1]);
            pH[3] = pack_h2(accs[2*kt+1][2], accs[2*kt+1][3]);
            #pragma unroll
            for (int vg = 0; vg < 2; vg++) {
                uint32_t vh2[2][4];
                #pragma unroll
                for (int q = 0; q < 2; q++) {
                    int vr = kt * 16 + (lane & 15);
                    int vc = vg * 32 + q * 16 + ((lane >> 4) << 3);
                    ldsm4t(vh2[q], smem_u32(sb + FS_VH + vr * FSPAD + vc));
                }
                #pragma unroll
                for (int t = 0; t < 4; t++)
                    mma_f16(acco[vg * 4 + t], pH, &vh2[t >> 1][(t & 1) * 2]);
            }
        }

        if (j < 15) CP_WAIT0();
        __syncthreads();
    }

    float inv0 = 1.f / l0, inv1 = 1.f / l1;
    float imu = 1.f / mu;
    float lm = LAMBD_ * mu;
    int row0 = i0 + wid * 16 + (lane >> 2);
    #pragma unroll
    for (int o = 0; o < 8; o++) {
        int col = o * 8 + (lane & 3) * 2;
        #pragma unroll
        for (int half = 0; half < 2; half++) {
            size_t ia = hbase + (size_t)(row0 + half * 8) * HD_ + col;
            float la = acco[o][half * 2]     * (half ? inv1 : inv0);
            float lb = acco[o][half * 2 + 1] * (half ? inv1 : inv0);
            float2 kv = ld_cs_f2(&g_k[ia]);
            float2 yv = ld_cs_f2(&g_y[ia]);
            float2 sv = ld_cs_f2(&g_s[ia]);
            float yn0 = yv.x + mu * (kv.x - la - sv.x);
            float yn1 = yv.y + mu * (kv.y - lb - sv.y);
            float ym0 = yn0 * imu, ym1 = yn1 * imu;
            float t0 = kv.x - la + ym0, t1 = kv.y - lb + ym1;
            float sn0 = (t0 >= lm) ? (t0 - lm) : ((t0 <= -lm) ? (t0 + lm) : 0.f);
            float sn1 = (t1 >= lm) ? (t1 - lm) : ((t1 <= -lm) ? (t1 + lm) : 0.f);
            st_cs_f2(&g_y[ia], yn0, yn1);
            st_cs_f2(&g_s[ia], sn0, sn1);
            float k20 = (kv.x - sn0 - ym0) * QSC_;
            float k21 = (kv.y - sn1 - ym1) * QSC_;
            uint32_t h2, l2;
            split2(k20, k21, h2, l2);
            *(uint32_t*)&k2h_dst[ia] = h2;
            *(uint32_t*)&k2l_dst[ia] = l2;
        }
    }
}

// =================== final iteration: 2-pass flash, materializes attn + obnc ===================
__global__ void __launch_bounds__(256, 2) final_flash_kernel(
    float* __restrict__ attn,
    const __nv_bfloat16* __restrict__ k2h_src, const __nv_bfloat16* __restrict__ k2l_src)
{
    extern __shared__ __nv_bfloat16 fsm[];
    const int bh = blockIdx.y;
    const int i0 = blockIdx.x * 128;
    const int tid = threadIdx.x, wid = tid >> 5, lane = tid & 31;

    const size_t hbase = (size_t)bh * N_ * HD_;
    const __nv_bfloat16* Gh = k2h_src + hbase;
    const __nv_bfloat16* Gl = k2l_src + hbase;
    const __half* Vh = g_vh + hbase;
    const __half* Vl = g_vl + hbase;

    #pragma unroll
    for (int i = 0; i < 8; i++) {
        int idx = tid + i * 256;
        int arr = idx >> 10, rem = idx & 1023, row = rem >> 3, c = rem & 7;
        const __nv_bfloat16* src = (arr ? Gl : Gh) + (size_t)(i0 + row) * HD_ + c * 8;
        *(uint4*)(fsm + (arr ? FA_L : FA_H) + row * FSPAD + c * 8) = *(const uint4*)src;
    }

    auto cp_tileA = [&](int stage, int j) {
        int sbase = FSTG0 + stage * FSTGS_F;
        #pragma unroll
        for (int i = 0; i < 8; i++) {
            int idx = tid + i * 256;
            int arr = idx >> 10, rem = idx & 1023, row = rem >> 3, c = rem & 7;
            const __nv_bfloat16* src = (arr ? Gl : Gh) + (size_t)(j * 128 + row) * HD_ + c * 8;
            cp16(smem_u32(fsm + sbase + (arr ? FA_BL : FS_BH) + row * FSPAD + c * 8), src);
        }
    };
    auto cp_tileB = [&](int stage, int j) {
        int sbase = FSTG0 + stage * FSTGS_F;
        #pragma unroll
        for (int i = 0; i < 8; i++) {
            int idx = tid + i * 256;
            int arr = idx >> 9, rem = idx & 511, row = rem >> 3, c = rem & 7;
            const void* src;
            int off;
            if      (arr == 0) { src = Gh + (size_t)(j * 64 + row) * HD_ + c * 8; off = FS_BH; }
            else if (arr == 1) { src = Gl + (size_t)(j * 64 + row) * HD_ + c * 8; off = FS_BL; }
            else if (arr == 2) { src = Vh + (size_t)(j * 64 + row) * HD_ + c * 8; off = FS_VH; }
            else               { src = Vl + (size_t)(j * 64 + row) * HD_ + c * 8; off = FS_VL; }
            cp16(smem_u32(fsm + sbase + off + row * FSPAD + c * 8), src);
        }
    };

    // ---------- PASS A: row stats over 128-wide tiles ----------
    cp_tileA(0, 0);
    CP_COMMIT(); CP_WAIT0();
    __syncthreads();

    float m0 = -1e30f, m1 = -1e30f, l0 = 0.f, l1 = 0.f;
    for (int j = 0; j < 8; j++) {
        if (j < 7) { cp_tileA((j + 1) & 1, j + 1); CP_COMMIT(); }
        const __nv_bfloat16* sb = fsm + FSTG0 + (j & 1) * FSTGS_F;
        float accs[16][4] = {};
        #pragma unroll
        for (int ks = 0; ks < 4; ks++) {
            uint32_t aH[4], aL[4];
            {
                int ar = wid * 16 + (lane & 15);
                int ac = ks * 16 + ((lane >> 4) << 3);
                ldsm4(aH, smem_u32(fsm + FA_H + ar * FSPAD + ac));
                ldsm4(aL, smem_u32(fsm + FA_L + ar * FSPAD + ac));
            }
            #pragma unroll
            for (int ng = 0; ng < 4; ng++) {
                uint32_t bh2[2][4], bl2[2][4];
                #pragma unroll
                for (int p = 0; p < 2; p++) {
                    int nr = ng * 32 + p * 16 + (lane & 7) + ((lane >> 4) << 3);
                    int kc = ks * 16 + (((lane >> 3) & 1) << 3);
                    ldsm4(bh2[p], smem_u32(sb + FS_BH + nr * FSPAD + kc));
                    ldsm4(bl2[p], smem_u32(sb + FA_BL + nr * FSPAD + kc));
                }
                #pragma unroll
                for (int t = 0; t < 4; t++) {
                    float* c = accs[ng * 4 + t];
                    const uint32_t* bhf = &bh2[t >> 1][(t & 1) * 2];
                    const uint32_t* blf = &bl2[t >> 1][(t & 1) * 2];
                    mma_bf16(c, aH, bhf);
                    mma_bf16(c, aH, blf);
                    mma_bf16(c, aL, bhf);
                }
            }
        }

        float tm0 = -1e30f, tm1 = -1e30f;
        #pragma unroll
        for (int t = 0; t < 16; t++) {
            tm0 = fmaxf(tm0, fmaxf(accs[t][0], accs[t][1]));
            tm1 = fmaxf(tm1, fmaxf(accs[t][2], accs[t][3]));
        }
        tm0 = fmaxf(tm0, __shfl_xor_sync(0xFFFFFFFF, tm0, 1));
        tm0 = fmaxf(tm0, __shfl_xor_sync(0xFFFFFFFF, tm0, 2));
        tm1 = fmaxf(tm1, __shfl_xor_sync(0xFFFFFFFF, tm1, 1));
        tm1 = fmaxf(tm1, __shfl_xor_sync(0xFFFFFFFF, tm1, 2));
        float mn0 = fmaxf(m0, tm0), mn1 = fmaxf(m1, tm1);
        float sc0 = ex2f(m0 - mn0), sc1 = ex2f(m1 - mn1);
        m0 = mn0; m1 = mn1;
        float rs0 = 0.f, rs1 = 0.f;
        #pragma unroll
        for (int t = 0; t < 16; t++) {
            rs0 += ex2f(accs[t][0] - m0) + ex2f(accs[t][1] - m0);
            rs1 += ex2f(accs[t][2] - m1) + ex2f(accs[t][3] - m1);
        }
        rs0 += __shfl_xor_sync(0xFFFFFFFF, rs0, 1);
        rs0 += __shfl_xor_sync(0xFFFFFFFF, rs0, 2);
        rs1 += __shfl_xor_sync(0xFFFFFFFF, rs1, 1);
        rs1 += __shfl_xor_sync(0xFFFFFFFF, rs1, 2);
        l0 = l0 * sc0 + rs0;
        l1 = l1 * sc1 + rs1;
        if (j < 7) CP_WAIT0();
        __syncthreads();
    }
    float inv0 = 1.f / l0, inv1 = 1.f / l1;

    // ---------- PASS B: normalized P -> attn (streaming stores), PV ----------
    cp_tileB(0, 0);
    CP_COMMIT(); CP_WAIT0();
    __syncthreads();

    float* Sp = attn + (size_t)bh * N_ * N_;
    const int prow = i0 + wid * 16 + (lane >> 2);
    float acco[8][4] = {};

    for (int j = 0; j < 16; j++) {
        if (j < 15) { cp_tileB((j + 1) & 1, j + 1); CP_COMMIT(); }
        const __nv_bfloat16* sb = fsm + FSTG0 + (j & 1) * FSTGS_F;
        float accs[8][4] = {};
        #pragma unroll
        for (int ks = 0; ks < 4; ks++) {
            uint32_t aH[4], aL[4];
            {
                int ar = wid * 16 + (lane & 15);
                int ac = ks * 16 + ((lane >> 4) << 3);
                ldsm4(aH, smem_u32(fsm + FA_H + ar * FSPAD + ac));
                ldsm4(aL, smem_u32(fsm + FA_L + ar * FSPAD + ac));
            }
            #pragma unroll
            for (int ng = 0; ng < 2; ng++) {
                uint32_t bh2[2][4], bl2[2][4];
                #pragma unroll
                for (int p = 0; p < 2; p++) {
                    int nr = ng * 32 + p * 16 + (lane & 7) + ((lane >> 4) << 3);
                    int kc = ks * 16 + (((lane >> 3) & 1) << 3);
                    ldsm4(bh2[p], smem_u32(sb + FS_BH + nr * FSPAD + kc));
                    ldsm4(bl2[p], smem_u32(sb + FS_BL + nr * FSPAD + kc));
                }
                #pragma unroll
                for (int t = 0; t < 4; t++) {
                    float* c = accs[ng * 4 + t];
                    const uint32_t* bhf = &bh2[t >> 1][(t & 1) * 2];
                    const uint32_t* blf = &bl2[t >> 1][(t & 1) * 2];
                    mma_bf16(c, aH, bhf);
                    mma_bf16(c, aH, blf);
                    mma_bf16(c, aL, bhf);
                }
            }
        }

        #pragma unroll
        for (int t = 0; t < 8; t++) {
            accs[t][0] = ex2f(accs[t][0] - m0) * inv0;
            accs[t][1] = ex2f(accs[t][1] - m0) * inv0;
            accs[t][2] = ex2f(accs[t][2] - m1) * inv1;
            accs[t][3] = ex2f(accs[t][3] - m1) * inv1;
            int col = j * 64 + (t >> 2) * 32 + (t & 3) * 8 + (lane & 3) * 2;
            st_cs_f2(&Sp[(size_t)prow * N_ + col],       accs[t][0], accs[t][1]);
            st_cs_f2(&Sp[(size_t)(prow + 8) * N_ + col], accs[t][2], accs[t][3]);
        }

        #pragma unroll
        for (int kt = 0; kt < 4; kt++) {
            uint32_t pH[4];
            pH[0] = pack_h2(accs[2*kt][0],   accs[2*kt][1]);
            pH[1] = pack_h2(accs[2*kt][2],   accs[2*kt][3]);
            pH[2] = pack_h2(accs[2*kt+1][0], accs[2*kt+1][1]);
            pH[3] = pack_h2(accs[2*kt+1][2], accs[2*kt+1][3]);
            #pragma unroll
            for (int vg = 0; vg < 2; vg++) {
                uint32_t vh2[2][4], vl2[2][4];
                #pragma unroll
                for (int q = 0; q < 2; q++) {
                    int vr = kt * 16 + (lane & 15);
                    int vc = vg * 32 + q * 16 + ((lane >> 4) << 3);
                    ldsm4t(vh2[q], smem_u32(sb + FS_VH + vr * FSPAD + vc));
                    ldsm4t(vl2[q], smem_u32(sb + FS_VL + vr * FSPAD + vc));
                }
                #pragma unroll
                for (int t = 0; t < 4; t++) {
                    float* o = acco[vg * 4 + t];
                    mma_f16(o, pH, &vh2[t >> 1][(t & 1) * 2]);
                    mma_f16(o, pH, &vl2[t >> 1][(t & 1) * 2]);
                }
            }
        }

        if (j < 15) CP_WAIT0();
        __syncthreads();
    }

    int b = bh / H_, h = bh % H_;
    #pragma unroll
    for (int o = 0; o < 8; o++) {
        int col = o * 8 + (lane & 3) * 2;
        uint32_t h0, l0b, h1, l1b;
        split2(acco[o][0], acco[o][1], h0, l0b);
        split2(acco[o][2], acco[o][3], h1, l1b);
        size_t idx0 = ((size_t)(b * N_ + prow)) * C_ + h * HD_ + col;
        size_t idx1 = ((size_t)(b * N_ + prow + 8)) * C_ + h * HD_ + col;
        *(uint32_t*)&g_och[idx0] = h0;
        *(uint32_t*)&g_ocl[idx0] = l0b;
        *(uint32_t*)&g_och[idx1] = h1;
        *(uint32_t*)&g_ocl[idx1] = l1b;
    }
}

// =================== bf16x3 HMMA GEMM: qkv and proj ===================
#define QA_H 0
#define QA_L 9216
#define QB_H 18432
#define QB_L 23040
#define QSTG 27648
#define WPAD 72

template<int NCOLS, int KDIM>
__device__ __forceinline__ void mma_gemm_main(
    const __nv_bfloat16* __restrict__ Ah, const __nv_bfloat16* __restrict__ Al,
    const __nv_bfloat16* __restrict__ Wh, const __nv_bfloat16* __restrict__ Wl,
    __nv_bfloat16* sm, int by, int bx, float acc[2][4][4])
{
    const int tid = threadIdx.x, wid = tid >> 5, lane = tid & 31;
    const int wm = wid & 3, wn = wid >> 2;

    auto cp_stage = [&](int stage, int k0) {
        int sb = stage * QSTG;
        #pragma unroll
        for (int i = 0; i < 8; i++) {
            int idx = tid + i * 256;
            int arr = idx >> 10, rem = idx & 1023, row = rem >> 3, c = rem & 7;
            const __nv_bfloat16* src = (arr ? Al : Ah) + (size_t)(by + row) * KDIM + k0 + c * 8;
            cp16(smem_u32(sm + sb + (arr ? QA_L : QA_H) + row * FSPAD + c * 8), src);
        }
        #pragma unroll
        for (int i = 0; i < 4; i++) {
            int idx = tid + i * 256;
            int arr = idx >> 9, rem = idx & 511, row = rem >> 3, c = rem & 7;
            const __nv_bfloat16* src = (arr ? Wl : Wh) + (size_t)(k0 + row) * NCOLS + bx + c * 8;
            cp16(smem_u32(sm + sb + (arr ? QB_L : QB_H) + row * WPAD + c * 8), src);
        }
    };

    cp_stage(0, 0);
    CP_COMMIT(); CP_WAIT0();
    __syncthreads();

    const int NCHUNK = KDIM / 64;
    for (int ch = 0; ch < NCHUNK; ch++) {
        if (ch < NCHUNK - 1) { cp_stage((ch + 1) & 1, (ch + 1) * 64); CP_COMMIT(); }
        __nv_bfloat16* sb = sm + (ch & 1) * QSTG;
        #pragma unroll
        for (int ks = 0; ks < 4; ks++) {
            uint32_t aH[2][4], aL[2][4];
            #pragma unroll
            for (int mt = 0; mt < 2; mt++) {
                int ar = wm * 32 + mt * 16 + (lane & 15);
                int ac = ks * 16 + ((lane >> 4) << 3);
                ldsm4(aH[mt], smem_u32(sb + QA_H + ar * FSPAD + ac));
                ldsm4(aL[mt], smem_u32(sb + QA_L + ar * FSPAD + ac));
            }
            uint32_t bh2[2][4], bl2[2][4];
            #pragma unroll
            for (int q = 0; q < 2; q++) {
                int vr = ks * 16 + (lane & 15);
                int vc = wn * 32 + q * 16 + ((lane >> 4) << 3);
                ldsm4t(bh2[q], smem_u32(sb + QB_H + vr * WPAD + vc));
                ldsm4t(bl2[q], smem_u32(sb + QB_L + vr * WPAD + vc));
            }
            #pragma unroll
            for (int mt = 0; mt < 2; mt++)
                #pragma unroll
                for (int nt = 0; nt < 4; nt++) {
                    const uint32_t* bhf = &bh2[nt >> 1][(nt & 1) * 2];
                    const uint32_t* blf = &bl2[nt >> 1][(nt & 1) * 2];
                    mma_bf16(acc[mt][nt], aH[mt], bhf);
                    mma_bf16(acc[mt][nt], aH[mt], blf);
                    mma_bf16(acc[mt][nt], aL[mt], bhf);
                }
        }
        if (ch < NCHUNK - 1) CP_WAIT0();
        __syncthreads();
    }
}

__global__ void __launch_bounds__(256, 2) qkv_mma_kernel(const float* __restrict__ bias) {
    extern __shared__ __nv_bfloat16 qsm[];
    const int bx = blockIdx.x * 64;
    const int by = blockIdx.y * 128;
    const int wid = threadIdx.x >> 5, lane = threadIdx.x & 31;
    const int wm = wid & 3, wn = wid >> 2;

    float acc[2][4][4] = {};
    mma_gemm_main<TWO_C_, C_>(g_xh, g_xl, g_wqh, g_wql, qsm, by, bx, acc);

    #pragma unroll
    for (int mt = 0; mt < 2; mt++) {
        int r0 = by + wm * 32 + mt * 16 + (lane >> 2);
        #pragma unroll
        for (int nt = 0; nt < 4; nt++) {
            int col = bx + wn * 32 + nt * 8 + (lane & 3) * 2;
            float b0 = bias[col], b1 = bias[col + 1];
            #pragma unroll
            for (int half = 0; half < 2; half++) {
                int r = r0 + half * 8;
                float v0 = acc[mt][nt][half * 2]     + b0;
                float v1 = acc[mt][nt][half * 2 + 1] + b1;
                int bb = r >> 10, n = r & 1023;
                int which = col >= C_;
                int cc = col - which * C_;
                int hh = cc / HD_, hd = cc % HD_;
                size_t idx = (((size_t)(bb * H_ + hh)) * N_ + n) * HD_ + hd;
                if (!which) {
                    *(float2*)&g_k[idx] = make_float2(v0, v1);
                } else {
                    uint32_t h2, l2;
                    split2h(v0, v1, h2, l2);
                    *(uint32_t*)&g_vh[idx] = h2;
                    *(uint32_t*)&g_vl[idx] = l2;
                }
            }
        }
    }
}

__global__ void __launch_bounds__(256, 2) proj_mma_kernel(const float* __restrict__ bias,
                                                          float* __restrict__ out) {
    extern __shared__ __nv_bfloat16 qsm[];
    const int bx = blockIdx.x * 64;
    const int by = blockIdx.y * 128;
    const int wid = threadIdx.x >> 5, lane = threadIdx.x & 31;
    const int wm = wid & 3, wn = wid >> 2;

    float acc[2][4][4] = {};
    mma_gemm_main<C_, C_>(g_och, g_ocl, g_wph, g_wpl, qsm, by, bx, acc);

    #pragma unroll
    for (int mt = 0; mt < 2; mt++) {
        int r0 = by + wm * 32 + mt * 16 + (lane >> 2);
        #pragma unroll
        for (int nt = 0; nt < 4; nt++) {
            int col = bx + wn * 32 + nt * 8 + (lane & 3) * 2;
            float b0 = bias[col], b1 = bias[col + 1];
            st_cs_f2(&out[(size_t)r0 * C_ + col],
                     acc[mt][nt][0] + b0, acc[mt][nt][1] + b1);
            st_cs_f2(&out[(size_t)(r0 + 8) * C_ + col],
                     acc[mt][nt][2] + b0, acc[mt][nt][3] + b1);
        }
    }
}

// ---------------- launch ----------------
extern "C" void kernel_launch(void* const* d_in, const int* in_sizes, int n_in,
                              void* d_out, int out_size) {
    const float* x     = (const float*)d_in[0];
    const float* Wqkv  = (const float*)d_in[1];
    const float* bqkv  = (const float*)d_in[2];
    const float* Wproj = (const float*)d_in[3];
    const float* bproj = (const float*)d_in[4];
    float* out = (float*)d_out;

    float* attn;
    if ((size_t)out_size >= OUT_ELEMS + ATTN_ELEMS) {
        attn = out + OUT_ELEMS;
    } else {
        void* p = nullptr;
        cudaGetSymbolAddress(&p, g_attn_fallback);
        attn = (float*)p;
    }

    const int FLASH_SMEM_I = (FSTG0 + 2 * FSTGS_I) * 2;   // 92,160 B
    const int FLASH_SMEM_F = (FSTG0 + 2 * FSTGS_F) * 2;   // 110,592 B
    const int GEMM_SMEM    = 2 * QSTG * 2;                // 110,592 B
    cudaFuncSetAttribute(flash_iter_kernel, cudaFuncAttributeMaxDynamicSharedMemorySize, FLASH_SMEM_I);
    cudaFuncSetAttribute(final_flash_kernel, cudaFuncAttributeMaxDynamicSharedMemorySize, FLASH_SMEM_F);
    cudaFuncSetAttribute(qkv_mma_kernel, cudaFuncAttributeMaxDynamicSharedMemorySize, GEMM_SMEM);
    cudaFuncSetAttribute(proj_mma_kernel, cudaFuncAttributeMaxDynamicSharedMemorySize, GEMM_SMEM);

    __nv_bfloat16 *k2h_a, *k2l_a, *k2h_b, *k2l_b;
    { void* p; cudaGetSymbolAddress(&p, g_k2h_a); k2h_a = (__nv_bfloat16*)p; }
    { void* p; cudaGetSymbolAddress(&p, g_k2l_a); k2l_a = (__nv_bfloat16*)p; }
    { void* p; cudaGetSymbolAddress(&p, g_k2h_b); k2h_b = (__nv_bfloat16*)p; }
    { void* p; cudaGetSymbolAddress(&p, g_k2l_b); k2l_b = (__nv_bfloat16*)p; }

    const int TOTAL_PAIRS = XS_PAIRS + WQ_PAIRS + WP_PAIRS;
    split_all_kernel<<<(TOTAL_PAIRS + 255) / 256, 256>>>(x, Wqkv, Wproj);

    qkv_mma_kernel<<<dim3(TWO_C_ / 64, M_ROWS / 128), 256, GEMM_SMEM>>>(bqkv);
    mu_part_kernel<<<BH_ * 8, 256>>>();
    k2_init_kernel<<<(int)((KV_ELEMS / 2 + 255) / 256), 256>>>();   // computes mu inline, writes g_mu + buffer A

    __nv_bfloat16* bufs_h[2] = {k2h_a, k2h_b};
    __nv_bfloat16* bufs_l[2] = {k2l_a, k2l_b};
    for (int it = 0; it < 5; ++it) {
        int s = it & 1, d = (it + 1) & 1;
        flash_iter_kernel<<<dim3(N_ / 128, BH_), 256, FLASH_SMEM_I>>>(
            bufs_h[s], bufs_l[s], bufs_h[d], bufs_l[d]);
    }
    final_flash_kernel<<<dim3(N_ / 128, BH_), 256, FLASH_SMEM_F>>>(attn, bufs_h[1], bufs_l[1]);

    proj_mma_kernel<<<dim3(C_ / 64, M_ROWS / 128), 256, GEMM_SMEM>>>(bproj, out);
}